// round 1
// baseline (speedup 1.0000x reference)
#include <cuda_runtime.h>

// Problem dims
#define Bn 4
#define Sn 512
#define Hn 768
#define NHn 12
#define Dn 64
#define Fn 3072
#define Ln 6
#define MR (Bn*Sn)          // 2048 rows

// -------- scratch (device globals; no allocations allowed) --------
__device__ float g_x  [MR*Hn];
__device__ float g_y  [MR*Hn];   // q / gemm output scratch
__device__ float g_k  [MR*Hn];
__device__ float g_v  [MR*Hn];
__device__ float g_ctx[MR*Hn];
__device__ float g_ffn[MR*Fn];

// ------------------------------------------------------------------
// block reductions (blockDim.x == 256)
// ------------------------------------------------------------------
__device__ __forceinline__ float block_reduce_sum(float v) {
    __shared__ float sh[8];
    __syncthreads();
#pragma unroll
    for (int o = 16; o; o >>= 1) v += __shfl_xor_sync(0xffffffffu, v, o);
    if ((threadIdx.x & 31) == 0) sh[threadIdx.x >> 5] = v;
    __syncthreads();
    float r = sh[threadIdx.x & 7];
#pragma unroll
    for (int o = 4; o; o >>= 1) r += __shfl_xor_sync(0xffffffffu, r, o);
    return r;
}

__device__ __forceinline__ float block_reduce_max(float v) {
    __shared__ float sh[8];
    __syncthreads();
#pragma unroll
    for (int o = 16; o; o >>= 1) v = fmaxf(v, __shfl_xor_sync(0xffffffffu, v, o));
    if ((threadIdx.x & 31) == 0) sh[threadIdx.x >> 5] = v;
    __syncthreads();
    float r = sh[threadIdx.x & 7];
#pragma unroll
    for (int o = 4; o; o >>= 1) r = fmaxf(r, __shfl_xor_sync(0xffffffffu, r, o));
    return r;
}

// ------------------------------------------------------------------
// embedding: x[row,:] = emb[tok[row],:] + pos[row % S,:]
// ------------------------------------------------------------------
__global__ void embed_kernel(const int* __restrict__ tok,
                             const float* __restrict__ emb,
                             const float* __restrict__ pos,
                             float* __restrict__ x) {
    int row = blockIdx.x;
    int t = tok[row];
    const float* e = emb + (size_t)t * Hn;
    const float* p = pos + (size_t)(row % Sn) * Hn;
    float* xo = x + (size_t)row * Hn;
    for (int c = threadIdx.x; c < Hn; c += blockDim.x) xo[c] = e[c] + p[c];
}

// ------------------------------------------------------------------
// generic SGEMM: C[M,N] = A[M,K] @ B[K,N] + bias (+resid) (relu)
// BM=BN=128, BK=8, 256 threads, 8x8 microtile
// ------------------------------------------------------------------
template<int RELU, int RESID>
__global__ __launch_bounds__(256, 2)
void sgemm128(const float* __restrict__ A, const float* __restrict__ Bm,
              const float* __restrict__ bias, const float* __restrict__ Rs,
              float* __restrict__ C, int M, int N, int K) {
    __shared__ float As[8][128];
    __shared__ float Bs[8][128];
    const int bm = blockIdx.y * 128, bn = blockIdx.x * 128;
    const int tid = threadIdx.x;
    const int tr = (tid >> 4) << 3;
    const int tc = (tid & 15) << 3;

    float acc[8][8];
#pragma unroll
    for (int i = 0; i < 8; i++)
#pragma unroll
        for (int j = 0; j < 8; j++) acc[i][j] = 0.f;

    const int am  = tid >> 1;          // 0..127
    const int ak  = (tid & 1) << 2;    // 0 or 4
    const int bk  = tid >> 5;          // 0..7
    const int bn4 = (tid & 31) << 2;   // 0..124

    const float* Aptr = A + (size_t)(bm + am) * K + ak;
    const float* Bptr = Bm + (size_t)bk * N + bn + bn4;

    for (int kt = 0; kt < K; kt += 8) {
        float4 av = *(const float4*)(Aptr + kt);
        As[ak + 0][am] = av.x; As[ak + 1][am] = av.y;
        As[ak + 2][am] = av.z; As[ak + 3][am] = av.w;
        *(float4*)&Bs[bk][bn4] = *(const float4*)(Bptr + (size_t)kt * N);
        __syncthreads();
#pragma unroll
        for (int kk = 0; kk < 8; kk++) {
            float a[8], b[8];
            *(float4*)&a[0] = *(const float4*)&As[kk][tr];
            *(float4*)&a[4] = *(const float4*)&As[kk][tr + 4];
            *(float4*)&b[0] = *(const float4*)&Bs[kk][tc];
            *(float4*)&b[4] = *(const float4*)&Bs[kk][tc + 4];
#pragma unroll
            for (int i = 0; i < 8; i++)
#pragma unroll
                for (int j = 0; j < 8; j++) acc[i][j] += a[i] * b[j];
        }
        __syncthreads();
    }

    float bb[8];
#pragma unroll
    for (int j = 0; j < 8; j++) bb[j] = bias[bn + tc + j];

#pragma unroll
    for (int i = 0; i < 8; i++) {
        size_t off = (size_t)(bm + tr + i) * N + bn + tc;
        float vv[8];
#pragma unroll
        for (int j = 0; j < 8; j++) vv[j] = acc[i][j] + bb[j];
        if (RESID) {
            float4 r0 = *(const float4*)(Rs + off);
            float4 r1 = *(const float4*)(Rs + off + 4);
            vv[0] += r0.x; vv[1] += r0.y; vv[2] += r0.z; vv[3] += r0.w;
            vv[4] += r1.x; vv[5] += r1.y; vv[6] += r1.z; vv[7] += r1.w;
        }
        if (RELU) {
#pragma unroll
            for (int j = 0; j < 8; j++) vv[j] = fmaxf(vv[j], 0.f);
        }
        *(float4*)(C + off)     = make_float4(vv[0], vv[1], vv[2], vv[3]);
        *(float4*)(C + off + 4) = make_float4(vv[4], vv[5], vv[6], vv[7]);
    }
}

// ------------------------------------------------------------------
// attention scores: per (b,h): S = Q @ K^T * scale + mask*(-1e4)
// M=N=512, K=64; lda=ldb=768; writes into attn output region (ldc=512)
// ------------------------------------------------------------------
__global__ __launch_bounds__(256, 2)
void attn_scores(const float* __restrict__ Q, const float* __restrict__ Kk,
                 const int* __restrict__ tok, float* __restrict__ attnL) {
    int bh = blockIdx.z;
    int b = bh / NHn, h = bh - b * NHn;
    const float* A  = Q  + (size_t)b * Sn * Hn + h * Dn;
    const float* Bm = Kk + (size_t)b * Sn * Hn + h * Dn;
    float* C = attnL + (size_t)bh * Sn * Sn;

    __shared__ float As[8][128];
    __shared__ float Bs[8][128];
    const int bm = blockIdx.y * 128, bn = blockIdx.x * 128;
    const int tid = threadIdx.x;
    const int tr = (tid >> 4) << 3;
    const int tc = (tid & 15) << 3;

    float acc[8][8];
#pragma unroll
    for (int i = 0; i < 8; i++)
#pragma unroll
        for (int j = 0; j < 8; j++) acc[i][j] = 0.f;

    const int am = tid >> 1;         // 0..127 (row within tile)
    const int ak = (tid & 1) << 2;   // 0 or 4

    for (int kt = 0; kt < Dn; kt += 8) {
        float4 av = *(const float4*)(A + (size_t)(bm + am) * Hn + kt + ak);
        As[ak + 0][am] = av.x; As[ak + 1][am] = av.y;
        As[ak + 2][am] = av.z; As[ak + 3][am] = av.w;
        float4 bvv = *(const float4*)(Bm + (size_t)(bn + am) * Hn + kt + ak);
        Bs[ak + 0][am] = bvv.x; Bs[ak + 1][am] = bvv.y;
        Bs[ak + 2][am] = bvv.z; Bs[ak + 3][am] = bvv.w;
        __syncthreads();
#pragma unroll
        for (int kk = 0; kk < 8; kk++) {
            float a[8], b[8];
            *(float4*)&a[0] = *(const float4*)&As[kk][tr];
            *(float4*)&a[4] = *(const float4*)&As[kk][tr + 4];
            *(float4*)&b[0] = *(const float4*)&Bs[kk][tc];
            *(float4*)&b[4] = *(const float4*)&Bs[kk][tc + 4];
#pragma unroll
            for (int i = 0; i < 8; i++)
#pragma unroll
                for (int j = 0; j < 8; j++) acc[i][j] += a[i] * b[j];
        }
        __syncthreads();
    }

    float mk[8];
#pragma unroll
    for (int j = 0; j < 8; j++)
        mk[j] = (tok[b * Sn + bn + tc + j] == 0) ? -10000.0f : 0.0f;

#pragma unroll
    for (int i = 0; i < 8; i++) {
        size_t off = (size_t)(bm + tr + i) * Sn + bn + tc;
        float vv[8];
#pragma unroll
        for (int j = 0; j < 8; j++) vv[j] = acc[i][j] * 0.125f + mk[j];
        *(float4*)(C + off)     = make_float4(vv[0], vv[1], vv[2], vv[3]);
        *(float4*)(C + off + 4) = make_float4(vv[4], vv[5], vv[6], vv[7]);
    }
}

// ------------------------------------------------------------------
// in-place row softmax over 512 elems; one block (256 thr) per row
// ------------------------------------------------------------------
__global__ void softmax512(float* __restrict__ attnL) {
    float* p = attnL + (size_t)blockIdx.x * Sn;
    int t = threadIdx.x;
    float x0 = p[t], x1 = p[t + 256];
    float mx = block_reduce_max(fmaxf(x0, x1));
    float e0 = __expf(x0 - mx), e1 = __expf(x1 - mx);
    float s = block_reduce_sum(e0 + e1);
    float inv = 1.0f / s;
    p[t] = e0 * inv;
    p[t + 256] = e1 * inv;
}

// ------------------------------------------------------------------
// ctx = attn @ V : per (b,h) M=512, N=64, K=512; write to [B*S, H]
// BM=128, BN=64, BK=16, 256 threads, 8x4 microtile
// ------------------------------------------------------------------
__global__ __launch_bounds__(256, 2)
void attn_ctx(const float* __restrict__ attnL, const float* __restrict__ V,
              float* __restrict__ ctx) {
    int bh = blockIdx.z;
    int b = bh / NHn, h = bh - b * NHn;
    const float* A  = attnL + (size_t)bh * Sn * Sn;        // lda 512
    const float* Bm = V + (size_t)b * Sn * Hn + h * Dn;    // ldb 768

    __shared__ float As[16][128];
    __shared__ float Bs[16][64];
    const int bm = blockIdx.y * 128;
    const int tid = threadIdx.x;
    const int tr = (tid >> 4) << 3;
    const int tc = (tid & 15) << 2;

    float acc[8][4];
#pragma unroll
    for (int i = 0; i < 8; i++)
#pragma unroll
        for (int j = 0; j < 4; j++) acc[i][j] = 0.f;

    for (int kt = 0; kt < Sn; kt += 16) {
        // A tile: 128x16 (2 float4 per thread), stored transposed
#pragma unroll
        for (int u = 0; u < 2; u++) {
            int f = tid + u * 256;
            int row = f >> 2, k4 = (f & 3) << 2;
            float4 av = *(const float4*)(A + (size_t)(bm + row) * Sn + kt + k4);
            As[k4 + 0][row] = av.x; As[k4 + 1][row] = av.y;
            As[k4 + 2][row] = av.z; As[k4 + 3][row] = av.w;
        }
        // B tile: 16x64, one float4 per thread
        {
            int kk = tid >> 4, n4 = (tid & 15) << 2;
            *(float4*)&Bs[kk][n4] =
                *(const float4*)(Bm + (size_t)(kt + kk) * Hn + n4);
        }
        __syncthreads();
#pragma unroll
        for (int kk = 0; kk < 16; kk++) {
            float a[8], bb[4];
            *(float4*)&a[0] = *(const float4*)&As[kk][tr];
            *(float4*)&a[4] = *(const float4*)&As[kk][tr + 4];
            *(float4*)&bb[0] = *(const float4*)&Bs[kk][tc];
#pragma unroll
            for (int i = 0; i < 8; i++)
#pragma unroll
                for (int j = 0; j < 4; j++) acc[i][j] += a[i] * bb[j];
        }
        __syncthreads();
    }

#pragma unroll
    for (int i = 0; i < 8; i++) {
        size_t off = (size_t)(b * Sn + bm + tr + i) * Hn + h * Dn + tc;
        *(float4*)(ctx + off) = make_float4(acc[i][0], acc[i][1], acc[i][2], acc[i][3]);
    }
}

// ------------------------------------------------------------------
// layernorm over 768 (3 elems/thread, 256 threads)
// ------------------------------------------------------------------
__global__ void layernorm(const float* __restrict__ in,
                          const float* __restrict__ g,
                          const float* __restrict__ be,
                          float* __restrict__ out) {
    const float* p = in + (size_t)blockIdx.x * Hn;
    float* o = out + (size_t)blockIdx.x * Hn;
    int t = threadIdx.x;
    float a = p[t], b = p[t + 256], c = p[t + 512];
    float s = block_reduce_sum(a + b + c);
    float m = s * (1.0f / Hn);
    float d0 = a - m, d1 = b - m, d2 = c - m;
    float vs = block_reduce_sum(d0 * d0 + d1 * d1 + d2 * d2);
    float inv = rsqrtf(vs * (1.0f / Hn) + 1e-12f);
    o[t]       = d0 * inv * g[t]       + be[t];
    o[t + 256] = d1 * inv * g[t + 256] + be[t + 256];
    o[t + 512] = d2 * inv * g[t + 512] + be[t + 512];
}

// ------------------------------------------------------------------
extern "C" void kernel_launch(void* const* d_in, const int* in_sizes, int n_in,
                              void* d_out, int out_size) {
    const int*   tok  = (const int*)d_in[0];
    const float* emb  = (const float*)d_in[1];
    const float* pos  = (const float*)d_in[2];
    const float* wq   = (const float*)d_in[3];
    const float* bq   = (const float*)d_in[4];
    const float* wk   = (const float*)d_in[5];
    const float* bk   = (const float*)d_in[6];
    const float* wv   = (const float*)d_in[7];
    const float* bv   = (const float*)d_in[8];
    const float* wo   = (const float*)d_in[9];
    const float* bo   = (const float*)d_in[10];
    const float* g1   = (const float*)d_in[11];
    const float* be1  = (const float*)d_in[12];
    const float* w1   = (const float*)d_in[13];
    const float* b1   = (const float*)d_in[14];
    const float* w2   = (const float*)d_in[15];
    const float* b2   = (const float*)d_in[16];
    const float* g2   = (const float*)d_in[17];
    const float* be2  = (const float*)d_in[18];

    float* out      = (float*)d_out;
    float* attn_out = out + (size_t)MR * Hn;   // [L,B,NH,S,S] after hidden out

    float *x, *y, *k, *v, *ctx, *ffn;
    cudaGetSymbolAddress((void**)&x,   g_x);
    cudaGetSymbolAddress((void**)&y,   g_y);
    cudaGetSymbolAddress((void**)&k,   g_k);
    cudaGetSymbolAddress((void**)&v,   g_v);
    cudaGetSymbolAddress((void**)&ctx, g_ctx);
    cudaGetSymbolAddress((void**)&ffn, g_ffn);

    embed_kernel<<<MR, 256>>>(tok, emb, pos, x);

    dim3 gp(Hn / 128, MR / 128);          // proj: 6 x 16
    dim3 gf1(Fn / 128, MR / 128);         // ffn1: 24 x 16
    dim3 gs(Sn / 128, Sn / 128, Bn * NHn);// scores: 4 x 4 x 48
    dim3 gc(1, Sn / 128, Bn * NHn);       // ctx: 1 x 4 x 48

    for (int l = 0; l < Ln; l++) {
        const float* Wq = wq + (size_t)l * Hn * Hn;
        const float* Wk = wk + (size_t)l * Hn * Hn;
        const float* Wv = wv + (size_t)l * Hn * Hn;
        const float* Wo = wo + (size_t)l * Hn * Hn;
        const float* W1 = w1 + (size_t)l * Hn * Fn;
        const float* W2 = w2 + (size_t)l * Fn * Hn;
        const float* Bq = bq + (size_t)l * Hn;
        const float* Bk = bk + (size_t)l * Hn;
        const float* Bv = bv + (size_t)l * Hn;
        const float* Bo = bo + (size_t)l * Hn;
        const float* B1 = b1 + (size_t)l * Fn;
        const float* B2 = b2 + (size_t)l * Hn;
        const float* G1 = g1 + (size_t)l * Hn;
        const float* E1 = be1 + (size_t)l * Hn;
        const float* G2 = g2 + (size_t)l * Hn;
        const float* E2 = be2 + (size_t)l * Hn;
        float* attnL = attn_out + (size_t)l * Bn * NHn * Sn * Sn;

        sgemm128<0, 0><<<gp, 256>>>(x, Wq, Bq, nullptr, y, MR, Hn, Hn);
        sgemm128<0, 0><<<gp, 256>>>(x, Wk, Bk, nullptr, k, MR, Hn, Hn);
        sgemm128<0, 0><<<gp, 256>>>(x, Wv, Bv, nullptr, v, MR, Hn, Hn);

        attn_scores<<<gs, 256>>>(y, k, tok, attnL);
        softmax512<<<Bn * NHn * Sn, 256>>>(attnL);
        attn_ctx<<<gc, 256>>>(attnL, v, ctx);

        sgemm128<0, 1><<<gp, 256>>>(ctx, Wo, Bo, x, y, MR, Hn, Hn);
        layernorm<<<MR, 256>>>(y, G1, E1, x);

        sgemm128<1, 0><<<gf1, 256>>>(x, W1, B1, nullptr, ffn, MR, Fn, Hn);
        sgemm128<0, 1><<<gp, 256>>>(ffn, W2, B2, x, y, MR, Hn, Fn);
        layernorm<<<MR, 256>>>(y, G2, E2, x);
    }

    cudaMemcpyAsync(out, x, (size_t)MR * Hn * sizeof(float),
                    cudaMemcpyDeviceToDevice);
}

// round 3
// speedup vs baseline: 3.1988x; 3.1988x over previous
#include <cuda_runtime.h>
#include <cuda_bf16.h>

typedef unsigned int u32;
typedef unsigned long long u64;

#define Bn 4
#define Sn 512
#define Hn 768
#define NHn 12
#define Fn 3072
#define Ln 6
#define MR (Bn*Sn)          // 2048
#define QKVN 2304
#define BH (Bn*NHn)         // 48

#define OFF_WO  (QKVN*Hn)
#define OFF_W1  (OFF_WO + Hn*Hn)
#define OFF_W2  (OFF_W1 + Hn*Fn)
#define PER_L   (OFF_W2 + Fn*Hn)

// ---------------- scratch (device globals) ----------------
__device__ __nv_bfloat16 g_wth[(size_t)Ln*PER_L];
__device__ __nv_bfloat16 g_wtl[(size_t)Ln*PER_L];
__device__ float g_x[MR*Hn];
__device__ float g_y[MR*Hn];
__device__ float g_bqkv[Ln*QKVN];
__device__ __nv_bfloat16 g_xh[MR*Hn],  g_xl[MR*Hn];
__device__ __nv_bfloat16 g_qh[(size_t)MR*QKVN], g_ql[(size_t)MR*QKVN];
__device__ __nv_bfloat16 g_vth[Bn*Hn*Sn], g_vtl[Bn*Hn*Sn];
__device__ __nv_bfloat16 g_prh[(size_t)BH*Sn*Sn], g_prl[(size_t)BH*Sn*Sn];
__device__ __nv_bfloat16 g_cth[MR*Hn], g_ctl[MR*Hn];
__device__ __nv_bfloat16 g_fh[(size_t)MR*Fn], g_fl[(size_t)MR*Fn];

// ---------------- helpers ----------------
__device__ __forceinline__ u32 s2u(const void* p) {
    u32 a;
    asm("{ .reg .u64 t; cvta.to.shared.u64 t, %1; cvt.u32.u64 %0, t; }" : "=r"(a) : "l"(p));
    return a;
}
__device__ __forceinline__ u32 swz(u32 o) { return o ^ ((o >> 3) & 0x70); }

__device__ __forceinline__ void cpasync16(u32 dst, const void* src) {
    asm volatile("cp.async.cg.shared.global [%0], [%1], 16;" :: "r"(dst), "l"(src) : "memory");
}
__device__ __forceinline__ void ldsm4(u32& r0, u32& r1, u32& r2, u32& r3, u32 a) {
    asm volatile("ldmatrix.sync.aligned.m8n8.x4.shared.b16 {%0,%1,%2,%3}, [%4];"
                 : "=r"(r0), "=r"(r1), "=r"(r2), "=r"(r3) : "r"(a));
}
__device__ __forceinline__ void mma16816(float* c, const u32* a, const u32* b) {
    asm volatile("mma.sync.aligned.m16n8k16.row.col.f32.bf16.bf16.f32 "
                 "{%0,%1,%2,%3}, {%4,%5,%6,%7}, {%8,%9}, {%0,%1,%2,%3};"
                 : "+f"(c[0]), "+f"(c[1]), "+f"(c[2]), "+f"(c[3])
                 : "r"(a[0]), "r"(a[1]), "r"(a[2]), "r"(a[3]), "r"(b[0]), "r"(b[1]));
}

__device__ __forceinline__ u32 packsplit(float v0, float v1, u32& lopack) {
    __nv_bfloat16 h0 = __float2bfloat16(v0);
    __nv_bfloat16 h1 = __float2bfloat16(v1);
    __nv_bfloat16 l0 = __float2bfloat16(v0 - __bfloat162float(h0));
    __nv_bfloat16 l1 = __float2bfloat16(v1 - __bfloat162float(h1));
    lopack = (u32)__bfloat16_as_ushort(l0) | ((u32)__bfloat16_as_ushort(l1) << 16);
    return (u32)__bfloat16_as_ushort(h0) | ((u32)__bfloat16_as_ushort(h1) << 16);
}

// ==================================================================
// bf16x3 GEMM on mma.sync. CTA tile 128 x NT, BK=64, 8 warps (2x4).
// Warp tile 64 x (NT/4). A,B smem: 128B rows, SW128 swizzle.
// EPI: 0=bias->split  1=scores(scale+mask,f32)  2=ctx->split
//      3=bias+resid->f32  4=bias+relu->split
// ==================================================================
template<int NT, int EPI>
__global__ void __launch_bounds__(256)
gemm_hmma(const __nv_bfloat16* __restrict__ Ah, const __nv_bfloat16* __restrict__ Al, int lda,
          const __nv_bfloat16* __restrict__ Bh, const __nv_bfloat16* __restrict__ Bl, int ldb,
          float* __restrict__ Cf, __nv_bfloat16* __restrict__ Ch, __nv_bfloat16* __restrict__ Cl, int ldc,
          const float* __restrict__ bias, const float* __restrict__ resid,
          const int* __restrict__ tok, int K)
{
    constexpr int NF = NT / 32;          // n-frags per warp (n8 each)
    constexpr int WN = NT / 4;           // warp n-width
    extern __shared__ char smem[];
    const u32 sb = s2u(smem);
    const int tid = threadIdx.x, wid = tid >> 5, lane = tid & 31;
    const int warp_m = wid >> 2, warp_n = wid & 3;
    const int m0 = blockIdx.y * 128, n0 = blockIdx.x * NT;
    const int z = blockIdx.z;
    int b = 0, h = 0;

    if (EPI == 1) {
        b = z / NHn; h = z - b * NHn;
        size_t ao = (size_t)(b * Sn) * lda + h * 64;
        size_t bo = (size_t)(b * Sn) * ldb + 768 + h * 64;
        Ah += ao; Al += ao; Bh += bo; Bl += bo;
    }
    if (EPI == 2) {
        b = z / NHn; h = z - b * NHn;
        size_t ao = (size_t)z * Sn * lda;
        size_t bo = (size_t)(b * Hn + h * 64) * ldb;
        Ah += ao; Al += ao; Bh += bo; Bl += bo;
    }

    const int nsl = K >> 6;
    const int T = nsl * 3;

    float acc[4][NF][4];
#pragma unroll
    for (int mi = 0; mi < 4; mi++)
#pragma unroll
        for (int ni = 0; ni < NF; ni++)
#pragma unroll
            for (int q = 0; q < 4; q++) acc[mi][ni][q] = 0.f;

    auto prefetch = [&](int it) {
        const int bb = it & 1;
        const int pass = it / nsl, sl = it - pass * nsl;
        const __nv_bfloat16* Ap = (pass == 2 ? Al : Ah) + sl * 64;
        const __nv_bfloat16* Bp = (pass == 1 ? Bl : Bh) + sl * 64;
        const u32 ao = sb + (u32)bb * 16384u;
        const u32 bo = sb + 32768u + (u32)bb * (u32)(NT * 128);
#pragma unroll
        for (int i = 0; i < 4; i++) {                 // A: 128 rows x 128B
            int f = tid + i * 256;
            int r = f >> 3, c = f & 7;
            cpasync16(ao + swz(r * 128 + c * 16), Ap + (size_t)(m0 + r) * lda + c * 8);
        }
#pragma unroll
        for (int i = 0; i < NT / 32; i++) {           // B: NT rows x 128B
            int f = tid + i * 256;
            int r = f >> 3, c = f & 7;
            cpasync16(bo + swz(r * 128 + c * 16), Bp + (size_t)(n0 + r) * ldb + c * 8);
        }
        asm volatile("cp.async.commit_group;" ::: "memory");
    };

    prefetch(0);

    for (int it = 0; it < T; it++) {
        if (it + 1 < T) {
            prefetch(it + 1);
            asm volatile("cp.async.wait_group 1;" ::: "memory");
        } else {
            asm volatile("cp.async.wait_group 0;" ::: "memory");
        }
        __syncthreads();

        const int bb = it & 1;
        const u32 abase = sb + (u32)bb * 16384u;
        const u32 bbase = sb + 32768u + (u32)bb * (u32)(NT * 128);

#pragma unroll
        for (int ks = 0; ks < 4; ks++) {
            u32 arg[4][4];
#pragma unroll
            for (int mi = 0; mi < 4; mi++) {
                int row = warp_m * 64 + mi * 16 + (lane & 15);
                int kc = ks * 16 + (lane >> 4) * 8;
                ldsm4(arg[mi][0], arg[mi][1], arg[mi][2], arg[mi][3],
                      abase + swz((u32)(row * 128 + kc * 2)));
            }
            u32 brg[NF][2];
#pragma unroll
            for (int p = 0; p < NF / 2; p++) {
                int nrow = warp_n * WN + p * 16 + (lane & 7) + ((lane >> 4) << 3);
                int kc = ks * 16 + ((lane >> 3) & 1) * 8;
                u32 r0, r1, r2, r3;
                ldsm4(r0, r1, r2, r3, bbase + swz((u32)(nrow * 128 + kc * 2)));
                brg[2 * p][0] = r0; brg[2 * p][1] = r1;
                brg[2 * p + 1][0] = r2; brg[2 * p + 1][1] = r3;
            }
#pragma unroll
            for (int mi = 0; mi < 4; mi++)
#pragma unroll
                for (int ni = 0; ni < NF; ni++)
                    mma16816(acc[mi][ni], arg[mi], brg[ni]);
        }
        __syncthreads();
    }

    // -------- epilogue --------
    const int tg = lane & 3, g = lane >> 2;
#pragma unroll
    for (int mi = 0; mi < 4; mi++) {
#pragma unroll
        for (int half = 0; half < 2; half++) {
            const int mrow = m0 + warp_m * 64 + mi * 16 + g + half * 8;
#pragma unroll
            for (int ni = 0; ni < NF; ni++) {
                const int col = n0 + warp_n * WN + ni * 8 + tg * 2;
                float v0 = acc[mi][ni][half * 2 + 0];
                float v1 = acc[mi][ni][half * 2 + 1];

                if (EPI == 0 || EPI == 4) {
                    v0 += bias[col]; v1 += bias[col + 1];
                    if (EPI == 4) { v0 = fmaxf(v0, 0.f); v1 = fmaxf(v1, 0.f); }
                    u32 lo, hi = packsplit(v0, v1, lo);
                    size_t off = (size_t)mrow * ldc + col;
                    *(u32*)(Ch + off) = hi;
                    *(u32*)(Cl + off) = lo;
                } else if (EPI == 1) {
                    float m0v = (tok[b * Sn + col]     == 0) ? -10000.f : 0.f;
                    float m1v = (tok[b * Sn + col + 1] == 0) ? -10000.f : 0.f;
                    float2 o = make_float2(v0 * 0.125f + m0v, v1 * 0.125f + m1v);
                    *(float2*)(Cf + (size_t)z * Sn * Sn + (size_t)mrow * Sn + col) = o;
                } else if (EPI == 2) {
                    u32 lo, hi = packsplit(v0, v1, lo);
                    size_t off = (size_t)(b * Sn + mrow) * ldc + h * 64 + col;
                    *(u32*)(Ch + off) = hi;
                    *(u32*)(Cl + off) = lo;
                } else { // EPI==3
                    size_t off = (size_t)mrow * ldc + col;
                    float2 rv = *(const float2*)(resid + off);
                    float2 o = make_float2(v0 + bias[col] + rv.x, v1 + bias[col + 1] + rv.y);
                    *(float2*)(Cf + off) = o;
                }
            }
        }
    }
}

// ==================================================================
// support kernels
// ==================================================================
__device__ __forceinline__ float block_sum(float v) {
    __shared__ float sh[8];
    __syncthreads();
#pragma unroll
    for (int o = 16; o; o >>= 1) v += __shfl_xor_sync(0xffffffffu, v, o);
    if ((threadIdx.x & 31) == 0) sh[threadIdx.x >> 5] = v;
    __syncthreads();
    float r = sh[threadIdx.x & 7];
#pragma unroll
    for (int o = 4; o; o >>= 1) r += __shfl_xor_sync(0xffffffffu, r, o);
    return r;
}
__device__ __forceinline__ float block_max(float v) {
    __shared__ float sh[8];
    __syncthreads();
#pragma unroll
    for (int o = 16; o; o >>= 1) v = fmaxf(v, __shfl_xor_sync(0xffffffffu, v, o));
    if ((threadIdx.x & 31) == 0) sh[threadIdx.x >> 5] = v;
    __syncthreads();
    float r = sh[threadIdx.x & 7];
#pragma unroll
    for (int o = 4; o; o >>= 1) r = fmaxf(r, __shfl_xor_sync(0xffffffffu, r, o));
    return r;
}

// fp32 [K,N] -> transposed bf16 hi/lo [N,K]
__global__ void tsplit(const float* __restrict__ in, __nv_bfloat16* __restrict__ oh,
                       __nv_bfloat16* __restrict__ ol, int K, int N,
                       long in_l, long out_l, long out_off) {
    __shared__ float t[32][33];
    const float* src = in + (size_t)blockIdx.z * in_l;
    __nv_bfloat16* dh = oh + out_off + (size_t)blockIdx.z * out_l;
    __nv_bfloat16* dl = ol + out_off + (size_t)blockIdx.z * out_l;
    int n0 = blockIdx.x * 32, k0 = blockIdx.y * 32;
    int tx = threadIdx.x;
    for (int r = threadIdx.y; r < 32; r += 8)
        t[r][tx] = src[(size_t)(k0 + r) * N + n0 + tx];
    __syncthreads();
    for (int r = threadIdx.y; r < 32; r += 8) {
        float v = t[tx][r];
        __nv_bfloat16 hb = __float2bfloat16(v);
        size_t o = (size_t)(n0 + r) * K + k0 + tx;
        dh[o] = hb;
        dl[o] = __float2bfloat16(v - __bfloat162float(hb));
    }
}

// bf16 transpose of V slice: qkv[:,1536:2304] per batch -> [B*768, 512]
__global__ void vtrans(const __nv_bfloat16* __restrict__ ih, const __nv_bfloat16* __restrict__ il,
                       __nv_bfloat16* __restrict__ oh, __nv_bfloat16* __restrict__ ol) {
    __shared__ __nv_bfloat16 th[32][33], tl[32][33];
    int bb = blockIdx.z;
    int d0 = blockIdx.x * 32, s0 = blockIdx.y * 32;
    int tx = threadIdx.x;
    for (int r = threadIdx.y; r < 32; r += 8) {
        size_t o = (size_t)(bb * Sn + s0 + r) * QKVN + 1536 + d0 + tx;
        th[r][tx] = ih[o];
        tl[r][tx] = il[o];
    }
    __syncthreads();
    for (int r = threadIdx.y; r < 32; r += 8) {
        size_t o = (size_t)(bb * Hn + d0 + r) * Sn + s0 + tx;
        oh[o] = th[tx][r];
        ol[o] = tl[tx][r];
    }
}

__global__ void biaspack(const float* __restrict__ bq, const float* __restrict__ bk,
                         const float* __restrict__ bv, float* __restrict__ o) {
    int i = blockIdx.x * 256 + threadIdx.x;
    if (i >= Ln * QKVN) return;
    int l = i / QKVN, n = i - l * QKVN;
    float v = (n < 768) ? bq[l * Hn + n] : (n < 1536) ? bk[l * Hn + n - 768] : bv[l * Hn + n - 1536];
    o[i] = v;
}

__global__ void embed_kernel(const int* __restrict__ tok, const float* __restrict__ emb,
                             const float* __restrict__ pos, float* __restrict__ x,
                             __nv_bfloat16* __restrict__ xh, __nv_bfloat16* __restrict__ xl) {
    int row = blockIdx.x;
    int t = tok[row];
    const float* e = emb + (size_t)t * Hn;
    const float* p = pos + (size_t)(row % Sn) * Hn;
    size_t base = (size_t)row * Hn;
    for (int c = threadIdx.x; c < Hn; c += blockDim.x) {
        float v = e[c] + p[c];
        x[base + c] = v;
        __nv_bfloat16 hb = __float2bfloat16(v);
        xh[base + c] = hb;
        xl[base + c] = __float2bfloat16(v - __bfloat162float(hb));
    }
}

__global__ void layernorm(const float* __restrict__ in, const float* __restrict__ g,
                          const float* __restrict__ be, float* __restrict__ out,
                          __nv_bfloat16* __restrict__ oh, __nv_bfloat16* __restrict__ ol) {
    size_t base = (size_t)blockIdx.x * Hn;
    int t = threadIdx.x;
    float a = in[base + t], b = in[base + t + 256], c = in[base + t + 512];
    float s = block_sum(a + b + c);
    float m = s * (1.0f / Hn);
    float d0 = a - m, d1 = b - m, d2 = c - m;
    float vs = block_sum(d0 * d0 + d1 * d1 + d2 * d2);
    float inv = rsqrtf(vs * (1.0f / Hn) + 1e-12f);
#pragma unroll
    for (int u = 0; u < 3; u++) {
        int idx = t + u * 256;
        float dv = (u == 0 ? d0 : u == 1 ? d1 : d2);
        float v = dv * inv * g[idx] + be[idx];
        out[base + idx] = v;
        __nv_bfloat16 hb = __float2bfloat16(v);
        oh[base + idx] = hb;
        ol[base + idx] = __float2bfloat16(v - __bfloat162float(hb));
    }
}

__global__ void softmax512(float* __restrict__ attnL, __nv_bfloat16* __restrict__ ph,
                           __nv_bfloat16* __restrict__ pl) {
    size_t base = (size_t)blockIdx.x * Sn;
    float* p = attnL + base;
    int t = threadIdx.x;
    float x0 = p[t], x1 = p[t + 256];
    float mx = block_max(fmaxf(x0, x1));
    float e0 = __expf(x0 - mx), e1 = __expf(x1 - mx);
    float s = block_sum(e0 + e1);
    float inv = 1.0f / s;
    float v0 = e0 * inv, v1 = e1 * inv;
    p[t] = v0; p[t + 256] = v1;
    __nv_bfloat16 h0 = __float2bfloat16(v0), h1 = __float2bfloat16(v1);
    ph[base + t] = h0;       ph[base + t + 256] = h1;
    pl[base + t] = __float2bfloat16(v0 - __bfloat162float(h0));
    pl[base + t + 256] = __float2bfloat16(v1 - __bfloat162float(h1));
}

// ==================================================================
#define SM128 (32768 + 2*128*128)   // 65536
#define SM64  (32768 + 2*64*128)    // 49152

extern "C" void kernel_launch(void* const* d_in, const int* in_sizes, int n_in,
                              void* d_out, int out_size) {
    const int*   tok = (const int*)d_in[0];
    const float* emb = (const float*)d_in[1];
    const float* pos = (const float*)d_in[2];
    const float* wq  = (const float*)d_in[3];
    const float* bq  = (const float*)d_in[4];
    const float* wk  = (const float*)d_in[5];
    const float* bk  = (const float*)d_in[6];
    const float* wv  = (const float*)d_in[7];
    const float* bv  = (const float*)d_in[8];
    const float* wo  = (const float*)d_in[9];
    const float* bo  = (const float*)d_in[10];
    const float* g1  = (const float*)d_in[11];
    const float* be1 = (const float*)d_in[12];
    const float* w1  = (const float*)d_in[13];
    const float* b1  = (const float*)d_in[14];
    const float* w2  = (const float*)d_in[15];
    const float* b2  = (const float*)d_in[16];
    const float* g2  = (const float*)d_in[17];
    const float* be2 = (const float*)d_in[18];

    float* out      = (float*)d_out;
    float* attn_out = out + (size_t)MR * Hn;

    float *x, *y, *bqkv;
    __nv_bfloat16 *wth, *wtl, *xh, *xl, *qh, *ql, *vth, *vtl, *prh, *prl, *cth, *ctl, *fh, *fl;
    cudaGetSymbolAddress((void**)&x, g_x);      cudaGetSymbolAddress((void**)&y, g_y);
    cudaGetSymbolAddress((void**)&bqkv, g_bqkv);
    cudaGetSymbolAddress((void**)&wth, g_wth);  cudaGetSymbolAddress((void**)&wtl, g_wtl);
    cudaGetSymbolAddress((void**)&xh, g_xh);    cudaGetSymbolAddress((void**)&xl, g_xl);
    cudaGetSymbolAddress((void**)&qh, g_qh);    cudaGetSymbolAddress((void**)&ql, g_ql);
    cudaGetSymbolAddress((void**)&vth, g_vth);  cudaGetSymbolAddress((void**)&vtl, g_vtl);
    cudaGetSymbolAddress((void**)&prh, g_prh);  cudaGetSymbolAddress((void**)&prl, g_prl);
    cudaGetSymbolAddress((void**)&cth, g_cth);  cudaGetSymbolAddress((void**)&ctl, g_ctl);
    cudaGetSymbolAddress((void**)&fh, g_fh);    cudaGetSymbolAddress((void**)&fl, g_fl);

    cudaFuncSetAttribute(gemm_hmma<128,0>, cudaFuncAttributeMaxDynamicSharedMemorySize, SM128);
    cudaFuncSetAttribute(gemm_hmma<128,1>, cudaFuncAttributeMaxDynamicSharedMemorySize, SM128);
    cudaFuncSetAttribute(gemm_hmma<128,3>, cudaFuncAttributeMaxDynamicSharedMemorySize, SM128);
    cudaFuncSetAttribute(gemm_hmma<128,4>, cudaFuncAttributeMaxDynamicSharedMemorySize, SM128);
    cudaFuncSetAttribute(gemm_hmma<64,2>,  cudaFuncAttributeMaxDynamicSharedMemorySize, SM64);

    dim3 tb(32, 8);
    tsplit<<<dim3(Hn/32, Hn/32, Ln), tb>>>(wq, wth, wtl, Hn, Hn, (long)Hn*Hn, (long)PER_L, 0);
    tsplit<<<dim3(Hn/32, Hn/32, Ln), tb>>>(wk, wth, wtl, Hn, Hn, (long)Hn*Hn, (long)PER_L, (long)768*Hn);
    tsplit<<<dim3(Hn/32, Hn/32, Ln), tb>>>(wv, wth, wtl, Hn, Hn, (long)Hn*Hn, (long)PER_L, (long)1536*Hn);
    tsplit<<<dim3(Hn/32, Hn/32, Ln), tb>>>(wo, wth, wtl, Hn, Hn, (long)Hn*Hn, (long)PER_L, (long)OFF_WO);
    tsplit<<<dim3(Fn/32, Hn/32, Ln), tb>>>(w1, wth, wtl, Hn, Fn, (long)Hn*Fn, (long)PER_L, (long)OFF_W1);
    tsplit<<<dim3(Hn/32, Fn/32, Ln), tb>>>(w2, wth, wtl, Fn, Hn, (long)Fn*Hn, (long)PER_L, (long)OFF_W2);
    biaspack<<<(Ln*QKVN + 255)/256, 256>>>(bq, bk, bv, bqkv);
    embed_kernel<<<MR, 256>>>(tok, emb, pos, x, xh, xl);

    for (int l = 0; l < Ln; l++) {
        const __nv_bfloat16* Wh = wth + (size_t)l * PER_L;
        const __nv_bfloat16* Wl = wtl + (size_t)l * PER_L;
        float* attnL = attn_out + (size_t)l * BH * Sn * Sn;

        // fused QKV projection: [2048,768] x [2304,768]^T
        gemm_hmma<128,0><<<dim3(QKVN/128, MR/128), 256, SM128>>>(
            xh, xl, Hn, Wh, Wl, Hn, nullptr, qh, ql, QKVN,
            bqkv + (size_t)l * QKVN, nullptr, nullptr, Hn);

        vtrans<<<dim3(Hn/32, Sn/32, Bn), tb>>>(qh, ql, vth, vtl);

        // scores: per (b,h) Q@K^T *0.125 + mask
        gemm_hmma<128,1><<<dim3(Sn/128, Sn/128, BH), 256, SM128>>>(
            qh, ql, QKVN, qh, ql, QKVN, attnL, nullptr, nullptr, Sn,
            nullptr, nullptr, tok, 64);

        softmax512<<<BH * Sn, 256>>>(attnL, prh, prl);

        // ctx: per (b,h) attn @ V -> [B*S, H] (split)
        gemm_hmma<64,2><<<dim3(1, Sn/128, BH), 256, SM64>>>(
            prh, prl, Sn, vth, vtl, Sn, nullptr, cth, ctl, Hn,
            nullptr, nullptr, nullptr, Sn);

        // Wo + residual(x)
        gemm_hmma<128,3><<<dim3(Hn/128, MR/128), 256, SM128>>>(
            cth, ctl, Hn, Wh + OFF_WO, Wl + OFF_WO, Hn, y, nullptr, nullptr, Hn,
            bo + (size_t)l * Hn, x, nullptr, Hn);
        layernorm<<<MR, 256>>>(y, g1 + (size_t)l * Hn, be1 + (size_t)l * Hn, x, xh, xl);

        // FFN1 (relu, split out)
        gemm_hmma<128,4><<<dim3(Fn/128, MR/128), 256, SM128>>>(
            xh, xl, Hn, Wh + OFF_W1, Wl + OFF_W1, Hn, nullptr, fh, fl, Fn,
            b1 + (size_t)l * Fn, nullptr, nullptr, Hn);

        // FFN2 + residual(x)
        gemm_hmma<128,3><<<dim3(Hn/128, MR/128), 256, SM128>>>(
            fh, fl, Fn, Wh + OFF_W2, Wl + OFF_W2, Fn, y, nullptr, nullptr, Hn,
            b2 + (size_t)l * Hn, x, nullptr, Fn);
        layernorm<<<MR, 256>>>(y, g2 + (size_t)l * Hn, be2 + (size_t)l * Hn, x, xh, xl);
    }

    cudaMemcpyAsync(out, x, (size_t)MR * Hn * sizeof(float), cudaMemcpyDeviceToDevice);
}

// round 4
// speedup vs baseline: 3.5969x; 1.1244x over previous
#include <cuda_runtime.h>
#include <cuda_bf16.h>

typedef unsigned int u32;
typedef unsigned long long u64;

#define Bn 4
#define Sn 512
#define Hn 768
#define NHn 12
#define Fn 3072
#define Ln 6
#define MR (Bn*Sn)          // 2048
#define QKVN 2304
#define BH (Bn*NHn)         // 48

#define OFF_WO  (QKVN*Hn)
#define OFF_W1  (OFF_WO + Hn*Hn)
#define OFF_W2  (OFF_W1 + Hn*Fn)
#define PER_L   (OFF_W2 + Fn*Hn)

// ---------------- scratch (device globals) ----------------
__device__ __nv_bfloat16 g_wth[(size_t)Ln*PER_L];
__device__ __nv_bfloat16 g_wtl[(size_t)Ln*PER_L];
__device__ float g_x[MR*Hn];
__device__ float g_y[MR*Hn];
__device__ float g_bqkv[Ln*QKVN];
__device__ __nv_bfloat16 g_xh[MR*Hn],  g_xl[MR*Hn];
__device__ __nv_bfloat16 g_qh[(size_t)MR*QKVN], g_ql[(size_t)MR*QKVN];
__device__ __nv_bfloat16 g_vth[Bn*Hn*Sn], g_vtl[Bn*Hn*Sn];
__device__ __nv_bfloat16 g_prh[(size_t)BH*Sn*Sn], g_prl[(size_t)BH*Sn*Sn];
__device__ __nv_bfloat16 g_cth[MR*Hn], g_ctl[MR*Hn];
__device__ __nv_bfloat16 g_fh[(size_t)MR*Fn], g_fl[(size_t)MR*Fn];

// ---------------- helpers ----------------
__device__ __forceinline__ u32 s2u(const void* p) {
    u32 a;
    asm("{ .reg .u64 t; cvta.to.shared.u64 t, %1; cvt.u32.u64 %0, t; }" : "=r"(a) : "l"(p));
    return a;
}
__device__ __forceinline__ u32 swz(u32 o) { return o ^ ((o >> 3) & 0x70); }

__device__ __forceinline__ void cpasync16(u32 dst, const void* src) {
    asm volatile("cp.async.cg.shared.global [%0], [%1], 16;" :: "r"(dst), "l"(src) : "memory");
}
__device__ __forceinline__ void ldsm4(u32& r0, u32& r1, u32& r2, u32& r3, u32 a) {
    asm volatile("ldmatrix.sync.aligned.m8n8.x4.shared.b16 {%0,%1,%2,%3}, [%4];"
                 : "=r"(r0), "=r"(r1), "=r"(r2), "=r"(r3) : "r"(a));
}
__device__ __forceinline__ void mma16816(float* c, const u32* a, const u32* b) {
    asm volatile("mma.sync.aligned.m16n8k16.row.col.f32.bf16.bf16.f32 "
                 "{%0,%1,%2,%3}, {%4,%5,%6,%7}, {%8,%9}, {%0,%1,%2,%3};"
                 : "+f"(c[0]), "+f"(c[1]), "+f"(c[2]), "+f"(c[3])
                 : "r"(a[0]), "r"(a[1]), "r"(a[2]), "r"(a[3]), "r"(b[0]), "r"(b[1]));
}

__device__ __forceinline__ u32 packsplit(float v0, float v1, u32& lopack) {
    __nv_bfloat16 h0 = __float2bfloat16(v0);
    __nv_bfloat16 h1 = __float2bfloat16(v1);
    __nv_bfloat16 l0 = __float2bfloat16(v0 - __bfloat162float(h0));
    __nv_bfloat16 l1 = __float2bfloat16(v1 - __bfloat162float(h1));
    lopack = (u32)__bfloat16_as_ushort(l0) | ((u32)__bfloat16_as_ushort(l1) << 16);
    return (u32)__bfloat16_as_ushort(h0) | ((u32)__bfloat16_as_ushort(h1) << 16);
}

// ==================================================================
// bf16x3 GEMM v2: slab-major (load Ah,Al,Bh,Bl once per slab, 3 MMA
// passes from resident smem). CTA tile MT x NT, BK=64, 512 threads,
// 16 warps (4x4). 3-stage cp.async pipeline, 1 sync per slab.
// EPI: 0=bias->split  2=ctx->split  3=bias+resid->f32  4=bias+relu->split
// ==================================================================
template<int MT, int NT, int EPI>
__global__ void __launch_bounds__(512)
gemm2(const __nv_bfloat16* __restrict__ Ah, const __nv_bfloat16* __restrict__ Al, int lda,
      const __nv_bfloat16* __restrict__ Bh, const __nv_bfloat16* __restrict__ Bl, int ldb,
      float* __restrict__ Cf, __nv_bfloat16* __restrict__ Ch, __nv_bfloat16* __restrict__ Cl, int ldc,
      const float* __restrict__ bias, const float* __restrict__ resid, int K)
{
    constexpr int WM = MT / 4, WN = NT / 4;
    constexpr int MI = WM / 16, NI = WN / 8;
    constexpr u32 ASZ = (u32)MT * 128u, BSZ = (u32)NT * 128u;
    constexpr u32 STG = 2 * ASZ + 2 * BSZ;

    extern __shared__ char smem[];
    const u32 sb = s2u(smem);
    const int tid = threadIdx.x, wid = tid >> 5, lane = tid & 31;
    const int warp_m = wid >> 2, warp_n = wid & 3;
    const int m0 = blockIdx.y * MT, n0 = blockIdx.x * NT;
    const int z = blockIdx.z;
    int b = 0, h = 0;

    if (EPI == 2) {
        b = z / NHn; h = z - b * NHn;
        size_t ao = (size_t)z * Sn * lda;
        size_t bo = (size_t)(b * Hn + h * 64) * ldb;
        Ah += ao; Al += ao; Bh += bo; Bl += bo;
    }

    const int nsl = K >> 6;

    float acc[MI][NI][4];
#pragma unroll
    for (int mi = 0; mi < MI; mi++)
#pragma unroll
        for (int ni = 0; ni < NI; ni++)
#pragma unroll
            for (int q = 0; q < 4; q++) acc[mi][ni][q] = 0.f;

    auto prefetch = [&](int sl) {
        const u32 base = sb + (u32)(sl % 3) * STG;
        const __nv_bfloat16* Aph = Ah + sl * 64;
        const __nv_bfloat16* Apl = Al + sl * 64;
        const __nv_bfloat16* Bph = Bh + sl * 64;
        const __nv_bfloat16* Bpl = Bl + sl * 64;
#pragma unroll
        for (int i = 0; i < MT * 8 / 512; i++) {
            int u = tid + i * 512;
            int r = u >> 3, c = u & 7;
            u32 d = swz((u32)(r * 128 + c * 16));
            size_t go = (size_t)(m0 + r) * lda + c * 8;
            cpasync16(base + d, Aph + go);
            cpasync16(base + ASZ + d, Apl + go);
        }
#pragma unroll
        for (int i = 0; i < NT * 8 / 512; i++) {
            int u = tid + i * 512;
            int r = u >> 3, c = u & 7;
            u32 d = swz((u32)(r * 128 + c * 16));
            size_t go = (size_t)(n0 + r) * ldb + c * 8;
            cpasync16(base + 2 * ASZ + d, Bph + go);
            cpasync16(base + 2 * ASZ + BSZ + d, Bpl + go);
        }
        asm volatile("cp.async.commit_group;" ::: "memory");
    };

    prefetch(0);
    prefetch(1);

    for (int it = 0; it < nsl; it++) {
        if (it < nsl - 1) asm volatile("cp.async.wait_group 1;" ::: "memory");
        else              asm volatile("cp.async.wait_group 0;" ::: "memory");
        __syncthreads();
        if (it + 2 < nsl) prefetch(it + 2);

        const u32 ab = sb + (u32)(it % 3) * STG;
        const u32 bb = ab + 2 * ASZ;

#pragma unroll
        for (int ks = 0; ks < 4; ks++) {
            u32 ahr[MI][4], alr[MI][4];
#pragma unroll
            for (int mi = 0; mi < MI; mi++) {
                int row = warp_m * WM + mi * 16 + (lane & 15);
                u32 off = swz((u32)(row * 128 + (ks * 16 + (lane >> 4) * 8) * 2));
                ldsm4(ahr[mi][0], ahr[mi][1], ahr[mi][2], ahr[mi][3], ab + off);
                ldsm4(alr[mi][0], alr[mi][1], alr[mi][2], alr[mi][3], ab + ASZ + off);
            }
            u32 bhr[NI][2], blr[NI][2];
#pragma unroll
            for (int nj = 0; nj < NI / 2; nj++) {
                int nrow = warp_n * WN + nj * 16 + (lane & 7) + ((lane >> 4) << 3);
                u32 off = swz((u32)(nrow * 128 + (ks * 16 + ((lane >> 3) & 1) * 8) * 2));
                u32 r0, r1, r2, r3;
                ldsm4(r0, r1, r2, r3, bb + off);
                bhr[2 * nj][0] = r0; bhr[2 * nj][1] = r1;
                bhr[2 * nj + 1][0] = r2; bhr[2 * nj + 1][1] = r3;
                ldsm4(r0, r1, r2, r3, bb + BSZ + off);
                blr[2 * nj][0] = r0; blr[2 * nj][1] = r1;
                blr[2 * nj + 1][0] = r2; blr[2 * nj + 1][1] = r3;
            }
#pragma unroll
            for (int mi = 0; mi < MI; mi++)
#pragma unroll
                for (int ni = 0; ni < NI; ni++) {
                    mma16816(acc[mi][ni], ahr[mi], bhr[ni]);
                    mma16816(acc[mi][ni], ahr[mi], blr[ni]);
                    mma16816(acc[mi][ni], alr[mi], bhr[ni]);
                }
        }
    }

    // -------- epilogue --------
    const int tg = lane & 3, g = lane >> 2;
#pragma unroll
    for (int mi = 0; mi < MI; mi++) {
#pragma unroll
        for (int half = 0; half < 2; half++) {
            const int mrow = m0 + warp_m * WM + mi * 16 + half * 8 + g;
#pragma unroll
            for (int ni = 0; ni < NI; ni++) {
                const int col = n0 + warp_n * WN + ni * 8 + tg * 2;
                float v0 = acc[mi][ni][half * 2 + 0];
                float v1 = acc[mi][ni][half * 2 + 1];

                if (EPI == 0 || EPI == 4) {
                    v0 += bias[col]; v1 += bias[col + 1];
                    if (EPI == 4) { v0 = fmaxf(v0, 0.f); v1 = fmaxf(v1, 0.f); }
                    u32 lo, hi = packsplit(v0, v1, lo);
                    size_t off = (size_t)mrow * ldc + col;
                    *(u32*)(Ch + off) = hi;
                    *(u32*)(Cl + off) = lo;
                } else if (EPI == 2) {
                    u32 lo, hi = packsplit(v0, v1, lo);
                    size_t off = (size_t)(b * Sn + mrow) * ldc + h * 64 + col;
                    *(u32*)(Ch + off) = hi;
                    *(u32*)(Cl + off) = lo;
                } else { // EPI==3
                    size_t off = (size_t)mrow * ldc + col;
                    float2 rv = *(const float2*)(resid + off);
                    float2 o = make_float2(v0 + bias[col] + rv.x, v1 + bias[col + 1] + rv.y);
                    *(float2*)(Cf + off) = o;
                }
            }
        }
    }
}

// ==================================================================
// Fused attention scores + softmax. CTA = 64 q-rows x all 512 k-cols
// for one (b,h). Writes fp32 attn (required output) + bf16 hi/lo probs.
// 256 threads, 8 warps (1x8 over n). All operands resident in smem.
// smem: Qh[0,8K) Ql[8K,16K) Kh[16K,80K) Kl[80K,144K) red[144K,146K)
// ==================================================================
#define SMEM_SS (147456 + 2048)
__global__ void __launch_bounds__(256)
attn_scores_softmax(const __nv_bfloat16* __restrict__ qh, const __nv_bfloat16* __restrict__ ql,
                    const int* __restrict__ tok, float* __restrict__ attn,
                    __nv_bfloat16* __restrict__ ph, __nv_bfloat16* __restrict__ pl)
{
    extern __shared__ char smem[];
    const u32 sb = s2u(smem);
    const int tid = threadIdx.x, wid = tid >> 5, lane = tid & 31;
    const int g = lane >> 2, tg = lane & 3;
    const int m0 = blockIdx.x * 64;
    const int zbh = blockIdx.y;
    const int b = zbh / NHn, h = zbh - b * NHn;

    const __nv_bfloat16* Qh_src = qh + (size_t)(b * Sn + m0) * QKVN + h * 64;
    const __nv_bfloat16* Ql_src = ql + (size_t)(b * Sn + m0) * QKVN + h * 64;
    const __nv_bfloat16* Kh_src = qh + (size_t)(b * Sn) * QKVN + 768 + h * 64;
    const __nv_bfloat16* Kl_src = ql + (size_t)(b * Sn) * QKVN + 768 + h * 64;

    for (int u = tid; u < 512; u += 256) {
        int r = u >> 3, c = u & 7;
        u32 d = swz((u32)(r * 128 + c * 16));
        size_t go = (size_t)r * QKVN + c * 8;
        cpasync16(sb + d, Qh_src + go);
        cpasync16(sb + 8192 + d, Ql_src + go);
    }
    for (int u = tid; u < 4096; u += 256) {
        int r = u >> 3, c = u & 7;
        u32 d = swz((u32)(r * 128 + c * 16));
        size_t go = (size_t)r * QKVN + c * 8;
        cpasync16(sb + 16384 + d, Kh_src + go);
        cpasync16(sb + 81920 + d, Kl_src + go);
    }
    asm volatile("cp.async.commit_group;" ::: "memory");
    asm volatile("cp.async.wait_group 0;" ::: "memory");
    __syncthreads();

    float acc[4][8][4];
#pragma unroll
    for (int mi = 0; mi < 4; mi++)
#pragma unroll
        for (int ni = 0; ni < 8; ni++)
#pragma unroll
            for (int q = 0; q < 4; q++) acc[mi][ni][q] = 0.f;

#pragma unroll
    for (int pass = 0; pass < 3; pass++) {
        const u32 ab = sb + (pass == 2 ? 8192u : 0u);
        const u32 bb = sb + (pass == 1 ? 81920u : 16384u);
#pragma unroll
        for (int ks = 0; ks < 4; ks++) {
            u32 arg[4][4];
#pragma unroll
            for (int mi = 0; mi < 4; mi++) {
                int row = mi * 16 + (lane & 15);
                u32 off = swz((u32)(row * 128 + (ks * 16 + (lane >> 4) * 8) * 2));
                ldsm4(arg[mi][0], arg[mi][1], arg[mi][2], arg[mi][3], ab + off);
            }
            u32 brg[8][2];
#pragma unroll
            for (int nj = 0; nj < 4; nj++) {
                int nrow = wid * 64 + nj * 16 + (lane & 7) + ((lane >> 4) << 3);
                u32 off = swz((u32)(nrow * 128 + (ks * 16 + ((lane >> 3) & 1) * 8) * 2));
                u32 r0, r1, r2, r3;
                ldsm4(r0, r1, r2, r3, bb + off);
                brg[2 * nj][0] = r0; brg[2 * nj][1] = r1;
                brg[2 * nj + 1][0] = r2; brg[2 * nj + 1][1] = r3;
            }
#pragma unroll
            for (int mi = 0; mi < 4; mi++)
#pragma unroll
                for (int ni = 0; ni < 8; ni++)
                    mma16816(acc[mi][ni], arg[mi], brg[ni]);
        }
    }

    // ---- scale + mask ----
    float mk[8][2];
#pragma unroll
    for (int ni = 0; ni < 8; ni++) {
        int c = wid * 64 + ni * 8 + tg * 2;
        mk[ni][0] = (tok[b * Sn + c]     == 0) ? -10000.f : 0.f;
        mk[ni][1] = (tok[b * Sn + c + 1] == 0) ? -10000.f : 0.f;
    }
#pragma unroll
    for (int mi = 0; mi < 4; mi++)
#pragma unroll
        for (int ni = 0; ni < 8; ni++)
#pragma unroll
            for (int q = 0; q < 4; q++)
                acc[mi][ni][q] = acc[mi][ni][q] * 0.125f + mk[ni][q & 1];

    float* red = (float*)(smem + 147456);
    float rmax[8], rsum[8];

    // ---- row max ----
#pragma unroll
    for (int mi = 0; mi < 4; mi++)
#pragma unroll
        for (int half = 0; half < 2; half++) {
            float mx = -1e30f;
#pragma unroll
            for (int ni = 0; ni < 8; ni++)
                mx = fmaxf(mx, fmaxf(acc[mi][ni][half * 2], acc[mi][ni][half * 2 + 1]));
            mx = fmaxf(mx, __shfl_xor_sync(0xffffffffu, mx, 1));
            mx = fmaxf(mx, __shfl_xor_sync(0xffffffffu, mx, 2));
            int row = mi * 16 + half * 8 + g;
            if (tg == 0) red[row * 8 + wid] = mx;
        }
    __syncthreads();
#pragma unroll
    for (int mi = 0; mi < 4; mi++)
#pragma unroll
        for (int half = 0; half < 2; half++) {
            int row = mi * 16 + half * 8 + g;
            float m = -1e30f;
#pragma unroll
            for (int w = 0; w < 8; w++) m = fmaxf(m, red[row * 8 + w]);
            rmax[mi * 2 + half] = m;
        }
    __syncthreads();

    // ---- exp + row sum ----
#pragma unroll
    for (int mi = 0; mi < 4; mi++)
#pragma unroll
        for (int half = 0; half < 2; half++) {
            float s = 0.f;
#pragma unroll
            for (int ni = 0; ni < 8; ni++) {
                float e0 = __expf(acc[mi][ni][half * 2]     - rmax[mi * 2 + half]);
                float e1 = __expf(acc[mi][ni][half * 2 + 1] - rmax[mi * 2 + half]);
                acc[mi][ni][half * 2] = e0; acc[mi][ni][half * 2 + 1] = e1;
                s += e0 + e1;
            }
            s += __shfl_xor_sync(0xffffffffu, s, 1);
            s += __shfl_xor_sync(0xffffffffu, s, 2);
            int row = mi * 16 + half * 8 + g;
            if (tg == 0) red[row * 8 + wid] = s;
        }
    __syncthreads();
#pragma unroll
    for (int mi = 0; mi < 4; mi++)
#pragma unroll
        for (int half = 0; half < 2; half++) {
            int row = mi * 16 + half * 8 + g;
            float s = 0.f;
#pragma unroll
            for (int w = 0; w < 8; w++) s += red[row * 8 + w];
            rsum[mi * 2 + half] = 1.f / s;
        }

    // ---- write attn fp32 + probs hi/lo ----
#pragma unroll
    for (int mi = 0; mi < 4; mi++)
#pragma unroll
        for (int half = 0; half < 2; half++) {
            int rloc = m0 + mi * 16 + half * 8 + g;
            size_t rbase = (size_t)zbh * Sn * Sn + (size_t)rloc * Sn;
            float inv = rsum[mi * 2 + half];
#pragma unroll
            for (int ni = 0; ni < 8; ni++) {
                int col = wid * 64 + ni * 8 + tg * 2;
                float p0 = acc[mi][ni][half * 2]     * inv;
                float p1 = acc[mi][ni][half * 2 + 1] * inv;
                *(float2*)(attn + rbase + col) = make_float2(p0, p1);
                u32 lo, hi = packsplit(p0, p1, lo);
                *(u32*)(ph + rbase + col) = hi;
                *(u32*)(pl + rbase + col) = lo;
            }
        }
}

// ==================================================================
// support kernels
// ==================================================================
__device__ __forceinline__ float block_sum(float v) {
    __shared__ float sh[8];
    __syncthreads();
#pragma unroll
    for (int o = 16; o; o >>= 1) v += __shfl_xor_sync(0xffffffffu, v, o);
    if ((threadIdx.x & 31) == 0) sh[threadIdx.x >> 5] = v;
    __syncthreads();
    float r = sh[threadIdx.x & 7];
#pragma unroll
    for (int o = 4; o; o >>= 1) r += __shfl_xor_sync(0xffffffffu, r, o);
    return r;
}

// fp32 [K,N] -> transposed bf16 hi/lo [N,K]
__global__ void tsplit(const float* __restrict__ in, __nv_bfloat16* __restrict__ oh,
                       __nv_bfloat16* __restrict__ ol, int K, int N,
                       long in_l, long out_l, long out_off) {
    __shared__ float t[32][33];
    const float* src = in + (size_t)blockIdx.z * in_l;
    __nv_bfloat16* dh = oh + out_off + (size_t)blockIdx.z * out_l;
    __nv_bfloat16* dl = ol + out_off + (size_t)blockIdx.z * out_l;
    int n0 = blockIdx.x * 32, k0 = blockIdx.y * 32;
    int tx = threadIdx.x;
    for (int r = threadIdx.y; r < 32; r += 8)
        t[r][tx] = src[(size_t)(k0 + r) * N + n0 + tx];
    __syncthreads();
    for (int r = threadIdx.y; r < 32; r += 8) {
        float v = t[tx][r];
        __nv_bfloat16 hb = __float2bfloat16(v);
        size_t o = (size_t)(n0 + r) * K + k0 + tx;
        dh[o] = hb;
        dl[o] = __float2bfloat16(v - __bfloat162float(hb));
    }
}

// bf16 transpose of V slice: qkv[:,1536:2304] per batch -> [B*768, 512]
__global__ void vtrans(const __nv_bfloat16* __restrict__ ih, const __nv_bfloat16* __restrict__ il,
                       __nv_bfloat16* __restrict__ oh, __nv_bfloat16* __restrict__ ol) {
    __shared__ __nv_bfloat16 th[32][33], tl[32][33];
    int bb = blockIdx.z;
    int d0 = blockIdx.x * 32, s0 = blockIdx.y * 32;
    int tx = threadIdx.x;
    for (int r = threadIdx.y; r < 32; r += 8) {
        size_t o = (size_t)(bb * Sn + s0 + r) * QKVN + 1536 + d0 + tx;
        th[r][tx] = ih[o];
        tl[r][tx] = il[o];
    }
    __syncthreads();
    for (int r = threadIdx.y; r < 32; r += 8) {
        size_t o = (size_t)(bb * Hn + d0 + r) * Sn + s0 + tx;
        oh[o] = th[tx][r];
        ol[o] = tl[tx][r];
    }
}

__global__ void biaspack(const float* __restrict__ bq, const float* __restrict__ bk,
                         const float* __restrict__ bv, float* __restrict__ o) {
    int i = blockIdx.x * 256 + threadIdx.x;
    if (i >= Ln * QKVN) return;
    int l = i / QKVN, n = i - l * QKVN;
    float v = (n < 768) ? bq[l * Hn + n] : (n < 1536) ? bk[l * Hn + n - 768] : bv[l * Hn + n - 1536];
    o[i] = v;
}

__global__ void embed_kernel(const int* __restrict__ tok, const float* __restrict__ emb,
                             const float* __restrict__ pos, float* __restrict__ x,
                             __nv_bfloat16* __restrict__ xh, __nv_bfloat16* __restrict__ xl) {
    int row = blockIdx.x;
    int t = tok[row];
    const float* e = emb + (size_t)t * Hn;
    const float* p = pos + (size_t)(row % Sn) * Hn;
    size_t base = (size_t)row * Hn;
    for (int c = threadIdx.x; c < Hn; c += blockDim.x) {
        float v = e[c] + p[c];
        x[base + c] = v;
        __nv_bfloat16 hb = __float2bfloat16(v);
        xh[base + c] = hb;
        xl[base + c] = __float2bfloat16(v - __bfloat162float(hb));
    }
}

__global__ void layernorm(const float* __restrict__ in, const float* __restrict__ g,
                          const float* __restrict__ be, float* __restrict__ out,
                          __nv_bfloat16* __restrict__ oh, __nv_bfloat16* __restrict__ ol) {
    size_t base = (size_t)blockIdx.x * Hn;
    int t = threadIdx.x;
    float a = in[base + t], b = in[base + t + 256], c = in[base + t + 512];
    float s = block_sum(a + b + c);
    float m = s * (1.0f / Hn);
    float d0 = a - m, d1 = b - m, d2 = c - m;
    float vs = block_sum(d0 * d0 + d1 * d1 + d2 * d2);
    float inv = rsqrtf(vs * (1.0f / Hn) + 1e-12f);
#pragma unroll
    for (int u = 0; u < 3; u++) {
        int idx = t + u * 256;
        float dv = (u == 0 ? d0 : u == 1 ? d1 : d2);
        float v = dv * inv * g[idx] + be[idx];
        out[base + idx] = v;
        __nv_bfloat16 hb = __float2bfloat16(v);
        oh[base + idx] = hb;
        ol[base + idx] = __float2bfloat16(v - __bfloat162float(hb));
    }
}

// ==================================================================
#define SMEM_G128 (3 * (2*128*128 + 2*128*128))   // 196608
#define SMEM_G64N (3 * (2*64*128  + 2*128*128))   // 147456
#define SMEM_GCTX (3 * (2*128*128 + 2*64*128))    // 147456

extern "C" void kernel_launch(void* const* d_in, const int* in_sizes, int n_in,
                              void* d_out, int out_size) {
    const int*   tok = (const int*)d_in[0];
    const float* emb = (const float*)d_in[1];
    const float* pos = (const float*)d_in[2];
    const float* wq  = (const float*)d_in[3];
    const float* bq  = (const float*)d_in[4];
    const float* wk  = (const float*)d_in[5];
    const float* bk  = (const float*)d_in[6];
    const float* wv  = (const float*)d_in[7];
    const float* bv  = (const float*)d_in[8];
    const float* wo  = (const float*)d_in[9];
    const float* bo  = (const float*)d_in[10];
    const float* g1  = (const float*)d_in[11];
    const float* be1 = (const float*)d_in[12];
    const float* w1  = (const float*)d_in[13];
    const float* b1  = (const float*)d_in[14];
    const float* w2  = (const float*)d_in[15];
    const float* b2  = (const float*)d_in[16];
    const float* g2  = (const float*)d_in[17];
    const float* be2 = (const float*)d_in[18];

    float* out      = (float*)d_out;
    float* attn_out = out + (size_t)MR * Hn;

    float *x, *y, *bqkv;
    __nv_bfloat16 *wth, *wtl, *xh, *xl, *qh, *ql, *vth, *vtl, *prh, *prl, *cth, *ctl, *fh, *fl;
    cudaGetSymbolAddress((void**)&x, g_x);      cudaGetSymbolAddress((void**)&y, g_y);
    cudaGetSymbolAddress((void**)&bqkv, g_bqkv);
    cudaGetSymbolAddress((void**)&wth, g_wth);  cudaGetSymbolAddress((void**)&wtl, g_wtl);
    cudaGetSymbolAddress((void**)&xh, g_xh);    cudaGetSymbolAddress((void**)&xl, g_xl);
    cudaGetSymbolAddress((void**)&qh, g_qh);    cudaGetSymbolAddress((void**)&ql, g_ql);
    cudaGetSymbolAddress((void**)&vth, g_vth);  cudaGetSymbolAddress((void**)&vtl, g_vtl);
    cudaGetSymbolAddress((void**)&prh, g_prh);  cudaGetSymbolAddress((void**)&prl, g_prl);
    cudaGetSymbolAddress((void**)&cth, g_cth);  cudaGetSymbolAddress((void**)&ctl, g_ctl);
    cudaGetSymbolAddress((void**)&fh, g_fh);    cudaGetSymbolAddress((void**)&fl, g_fl);

    cudaFuncSetAttribute(gemm2<128,128,0>, cudaFuncAttributeMaxDynamicSharedMemorySize, SMEM_G128);
    cudaFuncSetAttribute(gemm2<128,128,4>, cudaFuncAttributeMaxDynamicSharedMemorySize, SMEM_G128);
    cudaFuncSetAttribute(gemm2<64,128,3>,  cudaFuncAttributeMaxDynamicSharedMemorySize, SMEM_G64N);
    cudaFuncSetAttribute(gemm2<128,64,2>,  cudaFuncAttributeMaxDynamicSharedMemorySize, SMEM_GCTX);
    cudaFuncSetAttribute(attn_scores_softmax, cudaFuncAttributeMaxDynamicSharedMemorySize, SMEM_SS);

    dim3 tb(32, 8);
    tsplit<<<dim3(Hn/32, Hn/32, Ln), tb>>>(wq, wth, wtl, Hn, Hn, (long)Hn*Hn, (long)PER_L, 0);
    tsplit<<<dim3(Hn/32, Hn/32, Ln), tb>>>(wk, wth, wtl, Hn, Hn, (long)Hn*Hn, (long)PER_L, (long)768*Hn);
    tsplit<<<dim3(Hn/32, Hn/32, Ln), tb>>>(wv, wth, wtl, Hn, Hn, (long)Hn*Hn, (long)PER_L, (long)1536*Hn);
    tsplit<<<dim3(Hn/32, Hn/32, Ln), tb>>>(wo, wth, wtl, Hn, Hn, (long)Hn*Hn, (long)PER_L, (long)OFF_WO);
    tsplit<<<dim3(Fn/32, Hn/32, Ln), tb>>>(w1, wth, wtl, Hn, Fn, (long)Hn*Fn, (long)PER_L, (long)OFF_W1);
    tsplit<<<dim3(Hn/32, Fn/32, Ln), tb>>>(w2, wth, wtl, Fn, Hn, (long)Fn*Hn, (long)PER_L, (long)OFF_W2);
    biaspack<<<(Ln*QKVN + 255)/256, 256>>>(bq, bk, bv, bqkv);
    embed_kernel<<<MR, 256>>>(tok, emb, pos, x, xh, xl);

    for (int l = 0; l < Ln; l++) {
        const __nv_bfloat16* Wh = wth + (size_t)l * PER_L;
        const __nv_bfloat16* Wl = wtl + (size_t)l * PER_L;
        float* attnL = attn_out + (size_t)l * BH * Sn * Sn;

        // fused QKV projection: [2048,768] x [2304,768]^T -> split
        gemm2<128,128,0><<<dim3(QKVN/128, MR/128), 512, SMEM_G128>>>(
            xh, xl, Hn, Wh, Wl, Hn, nullptr, qh, ql, QKVN,
            bqkv + (size_t)l * QKVN, nullptr, Hn);

        vtrans<<<dim3(Hn/32, Sn/32, Bn), tb>>>(qh, ql, vth, vtl);

        // fused scores + softmax -> attn fp32 + probs hi/lo
        attn_scores_softmax<<<dim3(Sn/64, BH), 256, SMEM_SS>>>(
            qh, ql, tok, attnL, prh, prl);

        // ctx: per (b,h) P @ V -> [B*S, H] split
        gemm2<128,64,2><<<dim3(1, Sn/128, BH), 512, SMEM_GCTX>>>(
            prh, prl, Sn, vth, vtl, Sn, nullptr, cth, ctl, Hn,
            nullptr, nullptr, Sn);

        // Wo + residual(x)
        gemm2<64,128,3><<<dim3(Hn/128, MR/64), 512, SMEM_G64N>>>(
            cth, ctl, Hn, Wh + OFF_WO, Wl + OFF_WO, Hn, y, nullptr, nullptr, Hn,
            bo + (size_t)l * Hn, x, Hn);
        layernorm<<<MR, 256>>>(y, g1 + (size_t)l * Hn, be1 + (size_t)l * Hn, x, xh, xl);

        // FFN1 (relu, split out)
        gemm2<128,128,4><<<dim3(Fn/128, MR/128), 512, SMEM_G128>>>(
            xh, xl, Hn, Wh + OFF_W1, Wl + OFF_W1, Hn, nullptr, fh, fl, Fn,
            b1 + (size_t)l * Fn, nullptr, Hn);

        // FFN2 + residual(x)
        gemm2<64,128,3><<<dim3(Hn/128, MR/64), 512, SMEM_G64N>>>(
            fh, fl, Fn, Wh + OFF_W2, Wl + OFF_W2, Fn, y, nullptr, nullptr, Hn,
            b2 + (size_t)l * Hn, x, Fn);
        layernorm<<<MR, 256>>>(y, g2 + (size_t)l * Hn, be2 + (size_t)l * Hn, x, xh, xl);
    }

    cudaMemcpyAsync(out, x, (size_t)MR * Hn * sizeof(float), cudaMemcpyDeviceToDevice);
}

// round 5
// speedup vs baseline: 3.8405x; 1.0677x over previous
#include <cuda_runtime.h>
#include <cuda_bf16.h>

typedef unsigned int u32;
typedef unsigned long long u64;

#define Bn 4
#define Sn 512
#define Hn 768
#define NHn 12
#define Fn 3072
#define Ln 6
#define MR (Bn*Sn)          // 2048
#define QKVN 2304
#define BH (Bn*NHn)         // 48

#define OFF_WO  (QKVN*Hn)
#define OFF_W1  (OFF_WO + Hn*Hn)
#define OFF_W2  (OFF_W1 + Hn*Fn)
#define PER_L   (OFF_W2 + Fn*Hn)

// ---------------- scratch (device globals) ----------------
__device__ __nv_bfloat16 g_wth[(size_t)Ln*PER_L];
__device__ __nv_bfloat16 g_wtl[(size_t)Ln*PER_L];
__device__ float g_x[MR*Hn];
__device__ float g_y[MR*Hn];
__device__ float g_bqkv[Ln*QKVN];
__device__ __nv_bfloat16 g_xh[MR*Hn],  g_xl[MR*Hn];
__device__ __nv_bfloat16 g_qh[(size_t)MR*QKVN], g_ql[(size_t)MR*QKVN];
__device__ __nv_bfloat16 g_vth[Bn*Hn*Sn], g_vtl[Bn*Hn*Sn];
__device__ __nv_bfloat16 g_cth[MR*Hn], g_ctl[MR*Hn];
__device__ __nv_bfloat16 g_fh[(size_t)MR*Fn], g_fl[(size_t)MR*Fn];

// ---------------- helpers ----------------
__device__ __forceinline__ u32 s2u(const void* p) {
    u32 a;
    asm("{ .reg .u64 t; cvta.to.shared.u64 t, %1; cvt.u32.u64 %0, t; }" : "=r"(a) : "l"(p));
    return a;
}
__device__ __forceinline__ u32 swz(u32 o) { return o ^ ((o >> 3) & 0x70); }

__device__ __forceinline__ void cpasync16(u32 dst, const void* src) {
    asm volatile("cp.async.cg.shared.global [%0], [%1], 16;" :: "r"(dst), "l"(src) : "memory");
}
__device__ __forceinline__ void ldsm4(u32& r0, u32& r1, u32& r2, u32& r3, u32 a) {
    asm volatile("ldmatrix.sync.aligned.m8n8.x4.shared.b16 {%0,%1,%2,%3}, [%4];"
                 : "=r"(r0), "=r"(r1), "=r"(r2), "=r"(r3) : "r"(a));
}
__device__ __forceinline__ void mma16816(float* c, const u32* a, const u32* b) {
    asm volatile("mma.sync.aligned.m16n8k16.row.col.f32.bf16.bf16.f32 "
                 "{%0,%1,%2,%3}, {%4,%5,%6,%7}, {%8,%9}, {%0,%1,%2,%3};"
                 : "+f"(c[0]), "+f"(c[1]), "+f"(c[2]), "+f"(c[3])
                 : "r"(a[0]), "r"(a[1]), "r"(a[2]), "r"(a[3]), "r"(b[0]), "r"(b[1]));
}

__device__ __forceinline__ u32 packsplit(float v0, float v1, u32& lopack) {
    __nv_bfloat16 h0 = __float2bfloat16(v0);
    __nv_bfloat16 h1 = __float2bfloat16(v1);
    __nv_bfloat16 l0 = __float2bfloat16(v0 - __bfloat162float(h0));
    __nv_bfloat16 l1 = __float2bfloat16(v1 - __bfloat162float(h1));
    lopack = (u32)__bfloat16_as_ushort(l0) | ((u32)__bfloat16_as_ushort(l1) << 16);
    return (u32)__bfloat16_as_ushort(h0) | ((u32)__bfloat16_as_ushort(h1) << 16);
}

// ==================================================================
// bf16x3 GEMM: slab-major, CTA tile MT x NT, BK=64, 512 threads,
// 16 warps (4x4). 3-stage cp.async pipeline.
// EPI: 0=bias->split  3=bias+resid->f32  4=bias+relu->split
// ==================================================================
template<int MT, int NT, int EPI>
__global__ void __launch_bounds__(512)
gemm2(const __nv_bfloat16* __restrict__ Ah, const __nv_bfloat16* __restrict__ Al, int lda,
      const __nv_bfloat16* __restrict__ Bh, const __nv_bfloat16* __restrict__ Bl, int ldb,
      float* __restrict__ Cf, __nv_bfloat16* __restrict__ Ch, __nv_bfloat16* __restrict__ Cl, int ldc,
      const float* __restrict__ bias, const float* __restrict__ resid, int K)
{
    constexpr int WM = MT / 4, WN = NT / 4;
    constexpr int MI = WM / 16, NI = WN / 8;
    constexpr u32 ASZ = (u32)MT * 128u, BSZ = (u32)NT * 128u;
    constexpr u32 STG = 2 * ASZ + 2 * BSZ;

    extern __shared__ char smem[];
    const u32 sb = s2u(smem);
    const int tid = threadIdx.x, wid = tid >> 5, lane = tid & 31;
    const int warp_m = wid >> 2, warp_n = wid & 3;
    const int m0 = blockIdx.y * MT, n0 = blockIdx.x * NT;

    const int nsl = K >> 6;

    float acc[MI][NI][4];
#pragma unroll
    for (int mi = 0; mi < MI; mi++)
#pragma unroll
        for (int ni = 0; ni < NI; ni++)
#pragma unroll
            for (int q = 0; q < 4; q++) acc[mi][ni][q] = 0.f;

    auto prefetch = [&](int sl) {
        const u32 base = sb + (u32)(sl % 3) * STG;
        const __nv_bfloat16* Aph = Ah + sl * 64;
        const __nv_bfloat16* Apl = Al + sl * 64;
        const __nv_bfloat16* Bph = Bh + sl * 64;
        const __nv_bfloat16* Bpl = Bl + sl * 64;
#pragma unroll
        for (int i = 0; i < MT * 8 / 512; i++) {
            int u = tid + i * 512;
            int r = u >> 3, c = u & 7;
            u32 d = swz((u32)(r * 128 + c * 16));
            size_t go = (size_t)(m0 + r) * lda + c * 8;
            cpasync16(base + d, Aph + go);
            cpasync16(base + ASZ + d, Apl + go);
        }
#pragma unroll
        for (int i = 0; i < NT * 8 / 512; i++) {
            int u = tid + i * 512;
            int r = u >> 3, c = u & 7;
            u32 d = swz((u32)(r * 128 + c * 16));
            size_t go = (size_t)(n0 + r) * ldb + c * 8;
            cpasync16(base + 2 * ASZ + d, Bph + go);
            cpasync16(base + 2 * ASZ + BSZ + d, Bpl + go);
        }
        asm volatile("cp.async.commit_group;" ::: "memory");
    };

    prefetch(0);
    prefetch(1);

    for (int it = 0; it < nsl; it++) {
        if (it < nsl - 1) asm volatile("cp.async.wait_group 1;" ::: "memory");
        else              asm volatile("cp.async.wait_group 0;" ::: "memory");
        __syncthreads();
        if (it + 2 < nsl) prefetch(it + 2);

        const u32 ab = sb + (u32)(it % 3) * STG;
        const u32 bb = ab + 2 * ASZ;

#pragma unroll
        for (int ks = 0; ks < 4; ks++) {
            u32 ahr[MI][4], alr[MI][4];
#pragma unroll
            for (int mi = 0; mi < MI; mi++) {
                int row = warp_m * WM + mi * 16 + (lane & 15);
                u32 off = swz((u32)(row * 128 + (ks * 16 + (lane >> 4) * 8) * 2));
                ldsm4(ahr[mi][0], ahr[mi][1], ahr[mi][2], ahr[mi][3], ab + off);
                ldsm4(alr[mi][0], alr[mi][1], alr[mi][2], alr[mi][3], ab + ASZ + off);
            }
            u32 bhr[NI][2], blr[NI][2];
#pragma unroll
            for (int nj = 0; nj < NI / 2; nj++) {
                int nrow = warp_n * WN + nj * 16 + (lane & 7) + ((lane >> 4) << 3);
                u32 off = swz((u32)(nrow * 128 + (ks * 16 + ((lane >> 3) & 1) * 8) * 2));
                u32 r0, r1, r2, r3;
                ldsm4(r0, r1, r2, r3, bb + off);
                bhr[2 * nj][0] = r0; bhr[2 * nj][1] = r1;
                bhr[2 * nj + 1][0] = r2; bhr[2 * nj + 1][1] = r3;
                ldsm4(r0, r1, r2, r3, bb + BSZ + off);
                blr[2 * nj][0] = r0; blr[2 * nj][1] = r1;
                blr[2 * nj + 1][0] = r2; blr[2 * nj + 1][1] = r3;
            }
#pragma unroll
            for (int mi = 0; mi < MI; mi++)
#pragma unroll
                for (int ni = 0; ni < NI; ni++) {
                    mma16816(acc[mi][ni], ahr[mi], bhr[ni]);
                    mma16816(acc[mi][ni], ahr[mi], blr[ni]);
                    mma16816(acc[mi][ni], alr[mi], bhr[ni]);
                }
        }
    }

    const int tg = lane & 3, g = lane >> 2;
#pragma unroll
    for (int mi = 0; mi < MI; mi++) {
#pragma unroll
        for (int half = 0; half < 2; half++) {
            const int mrow = m0 + warp_m * WM + mi * 16 + half * 8 + g;
#pragma unroll
            for (int ni = 0; ni < NI; ni++) {
                const int col = n0 + warp_n * WN + ni * 8 + tg * 2;
                float v0 = acc[mi][ni][half * 2 + 0];
                float v1 = acc[mi][ni][half * 2 + 1];

                if (EPI == 0 || EPI == 4) {
                    v0 += bias[col]; v1 += bias[col + 1];
                    if (EPI == 4) { v0 = fmaxf(v0, 0.f); v1 = fmaxf(v1, 0.f); }
                    u32 lo, hi = packsplit(v0, v1, lo);
                    size_t off = (size_t)mrow * ldc + col;
                    *(u32*)(Ch + off) = hi;
                    *(u32*)(Cl + off) = lo;
                } else { // EPI==3
                    size_t off = (size_t)mrow * ldc + col;
                    float2 rv = *(const float2*)(resid + off);
                    float2 o = make_float2(v0 + bias[col] + rv.x, v1 + bias[col + 1] + rv.y);
                    *(float2*)(Cf + off) = o;
                }
            }
        }
    }
}

// ==================================================================
// Fully fused attention: scores + softmax + P@V for one (b,h), 64 q-rows.
// 256 threads, 8 warps. smem map (bytes):
//   [0,8K)        Qh      [8K,16K)     Ql
//   [16K,80K)     Kh -> later Ph       [80K,144K)  Kl -> later Pl
//   [144K,176K)   Vh half             [176K,208K)  Vl half
//   [208K,210K)   reduction buffer
// ==================================================================
#define ATT_PH   16384u
#define ATT_PL   81920u
#define ATT_VH   147456u
#define ATT_VL   180224u
#define ATT_RED  212992
#define SMEM_ATT (ATT_RED + 2048)

__global__ void __launch_bounds__(256)
attn_fused(const __nv_bfloat16* __restrict__ qh, const __nv_bfloat16* __restrict__ ql,
           const __nv_bfloat16* __restrict__ vth, const __nv_bfloat16* __restrict__ vtl,
           const int* __restrict__ tok, float* __restrict__ attn,
           __nv_bfloat16* __restrict__ cth, __nv_bfloat16* __restrict__ ctl)
{
    extern __shared__ char smem[];
    const u32 sb = s2u(smem);
    const int tid = threadIdx.x, wid = tid >> 5, lane = tid & 31;
    const int g = lane >> 2, tg = lane & 3;
    const int m0 = blockIdx.x * 64;
    const int zbh = blockIdx.y;
    const int b = zbh / NHn, h = zbh - b * NHn;

    const __nv_bfloat16* Qh_src = qh + (size_t)(b * Sn + m0) * QKVN + h * 64;
    const __nv_bfloat16* Ql_src = ql + (size_t)(b * Sn + m0) * QKVN + h * 64;
    const __nv_bfloat16* Kh_src = qh + (size_t)(b * Sn) * QKVN + 768 + h * 64;
    const __nv_bfloat16* Kl_src = ql + (size_t)(b * Sn) * QKVN + 768 + h * 64;

    // ---- load Q (group) ----
    for (int u = tid; u < 512; u += 256) {
        int r = u >> 3, c = u & 7;
        u32 d = swz((u32)(r * 128 + c * 16));
        size_t go = (size_t)r * QKVN + c * 8;
        cpasync16(sb + d, Qh_src + go);
        cpasync16(sb + 8192 + d, Ql_src + go);
    }
    for (int u = tid; u < 4096; u += 256) {
        int r = u >> 3, c = u & 7;
        u32 d = swz((u32)(r * 128 + c * 16));
        size_t go = (size_t)r * QKVN + c * 8;
        cpasync16(sb + ATT_PH + d, Kh_src + go);
        cpasync16(sb + ATT_PL + d, Kl_src + go);
    }
    asm volatile("cp.async.commit_group;" ::: "memory");

    // ---- prefetch V half 0 (independent smem region) ----
    auto loadV = [&](int dh) {
        const __nv_bfloat16* Vh_src = vth + (size_t)(b * Hn + h * 64 + dh * 32) * Sn;
        const __nv_bfloat16* Vl_src = vtl + (size_t)(b * Hn + h * 64 + dh * 32) * Sn;
        for (int u = tid; u < 2048; u += 256) {
            int sl = u >> 8, r = (u >> 3) & 31, c = u & 7;
            u32 d = (u32)(sl * 4096) + swz((u32)(r * 128 + c * 16));
            size_t go = (size_t)r * Sn + sl * 64 + c * 8;
            cpasync16(sb + ATT_VH + d, Vh_src + go);
            cpasync16(sb + ATT_VL + d, Vl_src + go);
        }
        asm volatile("cp.async.commit_group;" ::: "memory");
    };
    loadV(0);

    asm volatile("cp.async.wait_group 1;" ::: "memory");   // Q,K ready; V0 in flight
    __syncthreads();

    // ---- scores: P = Q K^T (bf16x3) ----
    float acc[4][8][4];
#pragma unroll
    for (int mi = 0; mi < 4; mi++)
#pragma unroll
        for (int ni = 0; ni < 8; ni++)
#pragma unroll
            for (int q = 0; q < 4; q++) acc[mi][ni][q] = 0.f;

#pragma unroll
    for (int pass = 0; pass < 3; pass++) {
        const u32 ab = sb + (pass == 2 ? 8192u : 0u);
        const u32 bb = sb + (pass == 1 ? ATT_PL : ATT_PH);
#pragma unroll
        for (int ks = 0; ks < 4; ks++) {
            u32 arg[4][4];
#pragma unroll
            for (int mi = 0; mi < 4; mi++) {
                int row = mi * 16 + (lane & 15);
                u32 off = swz((u32)(row * 128 + (ks * 16 + (lane >> 4) * 8) * 2));
                ldsm4(arg[mi][0], arg[mi][1], arg[mi][2], arg[mi][3], ab + off);
            }
            u32 brg[8][2];
#pragma unroll
            for (int nj = 0; nj < 4; nj++) {
                int nrow = wid * 64 + nj * 16 + (lane & 7) + ((lane >> 4) << 3);
                u32 off = swz((u32)(nrow * 128 + (ks * 16 + ((lane >> 3) & 1) * 8) * 2));
                u32 r0, r1, r2, r3;
                ldsm4(r0, r1, r2, r3, bb + off);
                brg[2 * nj][0] = r0; brg[2 * nj][1] = r1;
                brg[2 * nj + 1][0] = r2; brg[2 * nj + 1][1] = r3;
            }
#pragma unroll
            for (int mi = 0; mi < 4; mi++)
#pragma unroll
                for (int ni = 0; ni < 8; ni++)
                    mma16816(acc[mi][ni], arg[mi], brg[ni]);
        }
    }
    __syncthreads();   // all warps done reading K smem (P will overwrite it)

    // ---- scale + mask ----
    float mk[8][2];
#pragma unroll
    for (int ni = 0; ni < 8; ni++) {
        int c = wid * 64 + ni * 8 + tg * 2;
        mk[ni][0] = (tok[b * Sn + c]     == 0) ? -10000.f : 0.f;
        mk[ni][1] = (tok[b * Sn + c + 1] == 0) ? -10000.f : 0.f;
    }
#pragma unroll
    for (int mi = 0; mi < 4; mi++)
#pragma unroll
        for (int ni = 0; ni < 8; ni++)
#pragma unroll
            for (int q = 0; q < 4; q++)
                acc[mi][ni][q] = acc[mi][ni][q] * 0.125f + mk[ni][q & 1];

    float* red = (float*)(smem + ATT_RED);
    float rmax[8], rsum[8];

    // ---- row max ----
#pragma unroll
    for (int mi = 0; mi < 4; mi++)
#pragma unroll
        for (int half = 0; half < 2; half++) {
            float mx = -1e30f;
#pragma unroll
            for (int ni = 0; ni < 8; ni++)
                mx = fmaxf(mx, fmaxf(acc[mi][ni][half * 2], acc[mi][ni][half * 2 + 1]));
            mx = fmaxf(mx, __shfl_xor_sync(0xffffffffu, mx, 1));
            mx = fmaxf(mx, __shfl_xor_sync(0xffffffffu, mx, 2));
            int row = mi * 16 + half * 8 + g;
            if (tg == 0) red[row * 8 + wid] = mx;
        }
    __syncthreads();
#pragma unroll
    for (int mi = 0; mi < 4; mi++)
#pragma unroll
        for (int half = 0; half < 2; half++) {
            int row = mi * 16 + half * 8 + g;
            float m = -1e30f;
#pragma unroll
            for (int w = 0; w < 8; w++) m = fmaxf(m, red[row * 8 + w]);
            rmax[mi * 2 + half] = m;
        }
    __syncthreads();

    // ---- exp + row sum ----
#pragma unroll
    for (int mi = 0; mi < 4; mi++)
#pragma unroll
        for (int half = 0; half < 2; half++) {
            float s = 0.f;
#pragma unroll
            for (int ni = 0; ni < 8; ni++) {
                float e0 = __expf(acc[mi][ni][half * 2]     - rmax[mi * 2 + half]);
                float e1 = __expf(acc[mi][ni][half * 2 + 1] - rmax[mi * 2 + half]);
                acc[mi][ni][half * 2] = e0; acc[mi][ni][half * 2 + 1] = e1;
                s += e0 + e1;
            }
            s += __shfl_xor_sync(0xffffffffu, s, 1);
            s += __shfl_xor_sync(0xffffffffu, s, 2);
            int row = mi * 16 + half * 8 + g;
            if (tg == 0) red[row * 8 + wid] = s;
        }
    __syncthreads();
#pragma unroll
    for (int mi = 0; mi < 4; mi++)
#pragma unroll
        for (int half = 0; half < 2; half++) {
            int row = mi * 16 + half * 8 + g;
            float s = 0.f;
#pragma unroll
            for (int w = 0; w < 8; w++) s += red[row * 8 + w];
            rsum[mi * 2 + half] = 1.f / s;
        }

    // ---- write attn fp32 out + store P (bf16 hi/lo) to smem (over K) ----
#pragma unroll
    for (int mi = 0; mi < 4; mi++)
#pragma unroll
        for (int half = 0; half < 2; half++) {
            int row = mi * 16 + half * 8 + g;
            size_t rbase = (size_t)zbh * Sn * Sn + (size_t)(m0 + row) * Sn;
            float inv = rsum[mi * 2 + half];
#pragma unroll
            for (int ni = 0; ni < 8; ni++) {
                int col = ni * 8 + tg * 2;           // within warp's 64-col slab
                float p0 = acc[mi][ni][half * 2]     * inv;
                float p1 = acc[mi][ni][half * 2 + 1] * inv;
                *(float2*)(attn + rbase + wid * 64 + col) = make_float2(p0, p1);
                u32 lo, hi = packsplit(p0, p1, lo);
                u32 off = (u32)(wid * 8192) + swz((u32)(row * 128 + col * 2));
                *(u32*)(smem + ATT_PH + off) = hi;
                *(u32*)(smem + ATT_PL + off) = lo;
            }
        }

    // ---- ctx = P @ V, two d-halves of 32 ----
    const int wm = wid >> 1, wn = wid & 1;
#pragma unroll
    for (int dh = 0; dh < 2; dh++) {
        asm volatile("cp.async.wait_group 0;" ::: "memory");
        __syncthreads();   // V half ready + P writes visible (dh=0) / V reload safe (dh=1)

        float acc2[2][4];
#pragma unroll
        for (int ni = 0; ni < 2; ni++)
#pragma unroll
            for (int q = 0; q < 4; q++) acc2[ni][q] = 0.f;

#pragma unroll 2
        for (int sl = 0; sl < 8; sl++) {
#pragma unroll
            for (int ks = 0; ks < 4; ks++) {
                int row = wm * 16 + (lane & 15);
                u32 aoff = (u32)(sl * 8192) + swz((u32)(row * 128 + (ks * 16 + (lane >> 4) * 8) * 2));
                u32 ah[4], al[4];
                ldsm4(ah[0], ah[1], ah[2], ah[3], sb + ATT_PH + aoff);
                ldsm4(al[0], al[1], al[2], al[3], sb + ATT_PL + aoff);
                int nrow = wn * 16 + (lane & 7) + ((lane >> 4) << 3);
                u32 boff = (u32)(sl * 4096) + swz((u32)(nrow * 128 + (ks * 16 + ((lane >> 3) & 1) * 8) * 2));
                u32 bh[2][2], bl[2][2], r0, r1, r2, r3;
                ldsm4(r0, r1, r2, r3, sb + ATT_VH + boff);
                bh[0][0] = r0; bh[0][1] = r1; bh[1][0] = r2; bh[1][1] = r3;
                ldsm4(r0, r1, r2, r3, sb + ATT_VL + boff);
                bl[0][0] = r0; bl[0][1] = r1; bl[1][0] = r2; bl[1][1] = r3;
#pragma unroll
                for (int ni = 0; ni < 2; ni++) {
                    mma16816(acc2[ni], ah, bh[ni]);
                    mma16816(acc2[ni], ah, bl[ni]);
                    mma16816(acc2[ni], al, bh[ni]);
                }
            }
        }

        if (dh == 0) {     // start V half 1 load after everyone finished half 0
            __syncthreads();
            loadV(1);
        }

        // write ctx split
#pragma unroll
        for (int half = 0; half < 2; half++) {
            int row = m0 + wm * 16 + half * 8 + g;
#pragma unroll
            for (int ni = 0; ni < 2; ni++) {
                int col = dh * 32 + wn * 16 + ni * 8 + tg * 2;
                float v0 = acc2[ni][half * 2], v1 = acc2[ni][half * 2 + 1];
                u32 lo, hi = packsplit(v0, v1, lo);
                size_t off = (size_t)(b * Sn + row) * Hn + h * 64 + col;
                *(u32*)(cth + off) = hi;
                *(u32*)(ctl + off) = lo;
            }
        }
    }
}

// ==================================================================
// support kernels
// ==================================================================
__device__ __forceinline__ float block_sum(float v) {
    __shared__ float sh[8];
    __syncthreads();
#pragma unroll
    for (int o = 16; o; o >>= 1) v += __shfl_xor_sync(0xffffffffu, v, o);
    if ((threadIdx.x & 31) == 0) sh[threadIdx.x >> 5] = v;
    __syncthreads();
    float r = sh[threadIdx.x & 7];
#pragma unroll
    for (int o = 4; o; o >>= 1) r += __shfl_xor_sync(0xffffffffu, r, o);
    return r;
}

// merged transpose+split for the 4 HxH weights (wq,wk,wv,wo)
__global__ void tsplit4(const float* __restrict__ wq, const float* __restrict__ wk,
                        const float* __restrict__ wv, const float* __restrict__ wo,
                        __nv_bfloat16* __restrict__ oh, __nv_bfloat16* __restrict__ ol) {
    __shared__ float t[32][33];
    int z = blockIdx.z, l = z >> 2, which = z & 3;
    const float* src = (which == 0 ? wq : which == 1 ? wk : which == 2 ? wv : wo)
                       + (size_t)l * Hn * Hn;
    size_t obase = (size_t)l * PER_L + (size_t)which * 768 * Hn;
    __nv_bfloat16* dh = oh + obase;
    __nv_bfloat16* dl = ol + obase;
    int n0 = blockIdx.x * 32, k0 = blockIdx.y * 32;
    int tx = threadIdx.x;
    for (int r = threadIdx.y; r < 32; r += 8)
        t[r][tx] = src[(size_t)(k0 + r) * Hn + n0 + tx];
    __syncthreads();
    for (int r = threadIdx.y; r < 32; r += 8) {
        float v = t[tx][r];
        __nv_bfloat16 hb = __float2bfloat16(v);
        size_t o = (size_t)(n0 + r) * Hn + k0 + tx;
        dh[o] = hb;
        dl[o] = __float2bfloat16(v - __bfloat162float(hb));
    }
}

// fp32 [K,N] -> transposed bf16 hi/lo [N,K]
__global__ void tsplit(const float* __restrict__ in, __nv_bfloat16* __restrict__ oh,
                       __nv_bfloat16* __restrict__ ol, int K, int N,
                       long in_l, long out_l, long out_off) {
    __shared__ float t[32][33];
    const float* src = in + (size_t)blockIdx.z * in_l;
    __nv_bfloat16* dh = oh + out_off + (size_t)blockIdx.z * out_l;
    __nv_bfloat16* dl = ol + out_off + (size_t)blockIdx.z * out_l;
    int n0 = blockIdx.x * 32, k0 = blockIdx.y * 32;
    int tx = threadIdx.x;
    for (int r = threadIdx.y; r < 32; r += 8)
        t[r][tx] = src[(size_t)(k0 + r) * N + n0 + tx];
    __syncthreads();
    for (int r = threadIdx.y; r < 32; r += 8) {
        float v = t[tx][r];
        __nv_bfloat16 hb = __float2bfloat16(v);
        size_t o = (size_t)(n0 + r) * K + k0 + tx;
        dh[o] = hb;
        dl[o] = __float2bfloat16(v - __bfloat162float(hb));
    }
}

// bf16 transpose of V slice: qkv[:,1536:2304] per batch -> [B*768, 512]
__global__ void vtrans(const __nv_bfloat16* __restrict__ ih, const __nv_bfloat16* __restrict__ il,
                       __nv_bfloat16* __restrict__ oh, __nv_bfloat16* __restrict__ ol) {
    __shared__ __nv_bfloat16 th[32][33], tl[32][33];
    int bb = blockIdx.z;
    int d0 = blockIdx.x * 32, s0 = blockIdx.y * 32;
    int tx = threadIdx.x;
    for (int r = threadIdx.y; r < 32; r += 8) {
        size_t o = (size_t)(bb * Sn + s0 + r) * QKVN + 1536 + d0 + tx;
        th[r][tx] = ih[o];
        tl[r][tx] = il[o];
    }
    __syncthreads();
    for (int r = threadIdx.y; r < 32; r += 8) {
        size_t o = (size_t)(bb * Hn + d0 + r) * Sn + s0 + tx;
        oh[o] = th[tx][r];
        ol[o] = tl[tx][r];
    }
}

__global__ void biaspack(const float* __restrict__ bq, const float* __restrict__ bk,
                         const float* __restrict__ bv, float* __restrict__ o) {
    int i = blockIdx.x * 256 + threadIdx.x;
    if (i >= Ln * QKVN) return;
    int l = i / QKVN, n = i - l * QKVN;
    float v = (n < 768) ? bq[l * Hn + n] : (n < 1536) ? bk[l * Hn + n - 768] : bv[l * Hn + n - 1536];
    o[i] = v;
}

__global__ void embed_kernel(const int* __restrict__ tok, const float* __restrict__ emb,
                             const float* __restrict__ pos, float* __restrict__ x,
                             __nv_bfloat16* __restrict__ xh, __nv_bfloat16* __restrict__ xl) {
    int row = blockIdx.x;
    int t = tok[row];
    const float* e = emb + (size_t)t * Hn;
    const float* p = pos + (size_t)(row % Sn) * Hn;
    size_t base = (size_t)row * Hn;
    for (int c = threadIdx.x; c < Hn; c += blockDim.x) {
        float v = e[c] + p[c];
        x[base + c] = v;
        __nv_bfloat16 hb = __float2bfloat16(v);
        xh[base + c] = hb;
        xl[base + c] = __float2bfloat16(v - __bfloat162float(hb));
    }
}

__global__ void layernorm(const float* __restrict__ in, const float* __restrict__ g,
                          const float* __restrict__ be, float* __restrict__ out,
                          __nv_bfloat16* __restrict__ oh, __nv_bfloat16* __restrict__ ol) {
    size_t base = (size_t)blockIdx.x * Hn;
    int t = threadIdx.x;
    float a = in[base + t], b = in[base + t + 256], c = in[base + t + 512];
    float s = block_sum(a + b + c);
    float m = s * (1.0f / Hn);
    float d0 = a - m, d1 = b - m, d2 = c - m;
    float vs = block_sum(d0 * d0 + d1 * d1 + d2 * d2);
    float inv = rsqrtf(vs * (1.0f / Hn) + 1e-12f);
#pragma unroll
    for (int u = 0; u < 3; u++) {
        int idx = t + u * 256;
        float dv = (u == 0 ? d0 : u == 1 ? d1 : d2);
        float v = dv * inv * g[idx] + be[idx];
        out[base + idx] = v;
        __nv_bfloat16 hb = __float2bfloat16(v);
        oh[base + idx] = hb;
        ol[base + idx] = __float2bfloat16(v - __bfloat162float(hb));
    }
}

// ==================================================================
#define SMEM_G128 (3 * (2*128*128 + 2*128*128))   // 196608
#define SMEM_G64N (3 * (2*64*128  + 2*128*128))   // 147456

extern "C" void kernel_launch(void* const* d_in, const int* in_sizes, int n_in,
                              void* d_out, int out_size) {
    const int*   tok = (const int*)d_in[0];
    const float* emb = (const float*)d_in[1];
    const float* pos = (const float*)d_in[2];
    const float* wq  = (const float*)d_in[3];
    const float* bq  = (const float*)d_in[4];
    const float* wk  = (const float*)d_in[5];
    const float* bk  = (const float*)d_in[6];
    const float* wv  = (const float*)d_in[7];
    const float* bv  = (const float*)d_in[8];
    const float* wo  = (const float*)d_in[9];
    const float* bo  = (const float*)d_in[10];
    const float* g1  = (const float*)d_in[11];
    const float* be1 = (const float*)d_in[12];
    const float* w1  = (const float*)d_in[13];
    const float* b1  = (const float*)d_in[14];
    const float* w2  = (const float*)d_in[15];
    const float* b2  = (const float*)d_in[16];
    const float* g2  = (const float*)d_in[17];
    const float* be2 = (const float*)d_in[18];

    float* out      = (float*)d_out;
    float* attn_out = out + (size_t)MR * Hn;

    float *x, *y, *bqkv;
    __nv_bfloat16 *wth, *wtl, *xh, *xl, *qh, *ql, *vth, *vtl, *cth, *ctl, *fh, *fl;
    cudaGetSymbolAddress((void**)&x, g_x);      cudaGetSymbolAddress((void**)&y, g_y);
    cudaGetSymbolAddress((void**)&bqkv, g_bqkv);
    cudaGetSymbolAddress((void**)&wth, g_wth);  cudaGetSymbolAddress((void**)&wtl, g_wtl);
    cudaGetSymbolAddress((void**)&xh, g_xh);    cudaGetSymbolAddress((void**)&xl, g_xl);
    cudaGetSymbolAddress((void**)&qh, g_qh);    cudaGetSymbolAddress((void**)&ql, g_ql);
    cudaGetSymbolAddress((void**)&vth, g_vth);  cudaGetSymbolAddress((void**)&vtl, g_vtl);
    cudaGetSymbolAddress((void**)&cth, g_cth);  cudaGetSymbolAddress((void**)&ctl, g_ctl);
    cudaGetSymbolAddress((void**)&fh, g_fh);    cudaGetSymbolAddress((void**)&fl, g_fl);

    cudaFuncSetAttribute(gemm2<128,128,0>, cudaFuncAttributeMaxDynamicSharedMemorySize, SMEM_G128);
    cudaFuncSetAttribute(gemm2<128,128,4>, cudaFuncAttributeMaxDynamicSharedMemorySize, SMEM_G128);
    cudaFuncSetAttribute(gemm2<64,128,3>,  cudaFuncAttributeMaxDynamicSharedMemorySize, SMEM_G64N);
    cudaFuncSetAttribute(attn_fused, cudaFuncAttributeMaxDynamicSharedMemorySize, SMEM_ATT);

    dim3 tb(32, 8);
    // launches 0..4 (so ncu -s 5 captures the QKV GEMM next):
    tsplit4<<<dim3(Hn/32, Hn/32, 4*Ln), tb>>>(wq, wk, wv, wo, wth, wtl);
    tsplit<<<dim3(Fn/32, Hn/32, Ln), tb>>>(w1, wth, wtl, Hn, Fn, (long)Hn*Fn, (long)PER_L, (long)OFF_W1);
    tsplit<<<dim3(Hn/32, Fn/32, Ln), tb>>>(w2, wth, wtl, Fn, Hn, (long)Fn*Hn, (long)PER_L, (long)OFF_W2);
    biaspack<<<(Ln*QKVN + 255)/256, 256>>>(bq, bk, bv, bqkv);
    embed_kernel<<<MR, 256>>>(tok, emb, pos, x, xh, xl);

    for (int l = 0; l < Ln; l++) {
        const __nv_bfloat16* Wh = wth + (size_t)l * PER_L;
        const __nv_bfloat16* Wl = wtl + (size_t)l * PER_L;
        float* attnL = attn_out + (size_t)l * BH * Sn * Sn;

        // fused QKV projection: [2048,768] x [2304,768]^T -> split
        gemm2<128,128,0><<<dim3(QKVN/128, MR/128), 512, SMEM_G128>>>(
            xh, xl, Hn, Wh, Wl, Hn, nullptr, qh, ql, QKVN,
            bqkv + (size_t)l * QKVN, nullptr, Hn);

        vtrans<<<dim3(Hn/32, Sn/32, Bn), tb>>>(qh, ql, vth, vtl);

        // fused scores + softmax + P@V
        attn_fused<<<dim3(Sn/64, BH), 256, SMEM_ATT>>>(
            qh, ql, vth, vtl, tok, attnL, cth, ctl);

        // Wo + residual(x)
        gemm2<64,128,3><<<dim3(Hn/128, MR/64), 512, SMEM_G64N>>>(
            cth, ctl, Hn, Wh + OFF_WO, Wl + OFF_WO, Hn, y, nullptr, nullptr, Hn,
            bo + (size_t)l * Hn, x, Hn);
        layernorm<<<MR, 256>>>(y, g1 + (size_t)l * Hn, be1 + (size_t)l * Hn, x, xh, xl);

        // FFN1 (relu, split out)
        gemm2<128,128,4><<<dim3(Fn/128, MR/128), 512, SMEM_G128>>>(
            xh, xl, Hn, Wh + OFF_W1, Wl + OFF_W1, Hn, nullptr, fh, fl, Fn,
            b1 + (size_t)l * Fn, nullptr, Hn);

        // FFN2 + residual(x)
        gemm2<64,128,3><<<dim3(Hn/128, MR/64), 512, SMEM_G64N>>>(
            fh, fl, Fn, Wh + OFF_W2, Wl + OFF_W2, Fn, y, nullptr, nullptr, Hn,
            b2 + (size_t)l * Hn, x, Fn);
        layernorm<<<MR, 256>>>(y, g2 + (size_t)l * Hn, be2 + (size_t)l * Hn, x, xh, xl);
    }

    cudaMemcpyAsync(out, x, (size_t)MR * Hn * sizeof(float), cudaMemcpyDeviceToDevice);
}

// round 6
// speedup vs baseline: 6.1017x; 1.5888x over previous
#include <cuda_runtime.h>
#include <cuda_bf16.h>
#include <cuda_fp16.h>

typedef unsigned int u32;
typedef unsigned long long u64;

#define Bn 4
#define Sn 512
#define Hn 768
#define NHn 12
#define Fn 3072
#define Ln 6
#define MR (Bn*Sn)          // 2048
#define QKVN 2304
#define BH (Bn*NHn)         // 48
#define PER_LQ (QKVN*Hn)

// ---------------- scratch (device globals) ----------------
__device__ __nv_bfloat16 g_wth[(size_t)Ln*PER_LQ];   // QKV weights hi (transposed)
__device__ __nv_bfloat16 g_wtl[(size_t)Ln*PER_LQ];   // QKV weights lo
__device__ __half g_wo16[(size_t)Ln*Hn*Hn];
__device__ __half g_w116[(size_t)Ln*Hn*Fn];
__device__ __half g_w216[(size_t)Ln*Fn*Hn];
__device__ float g_x[MR*Hn];
__device__ float g_y[MR*Hn];
__device__ float g_bqkv[Ln*QKVN];
__device__ __nv_bfloat16 g_xh[MR*Hn],  g_xl[MR*Hn];
__device__ __half g_xf[MR*Hn];
__device__ __nv_bfloat16 g_qh[(size_t)MR*QKVN], g_ql[(size_t)MR*QKVN];
__device__ __half g_vt16[Bn*Hn*Sn];
__device__ __half g_ct16[MR*Hn];
__device__ __half g_f16[(size_t)MR*Fn];

// ---------------- helpers ----------------
__device__ __forceinline__ u32 s2u(const void* p) {
    u32 a;
    asm("{ .reg .u64 t; cvta.to.shared.u64 t, %1; cvt.u32.u64 %0, t; }" : "=r"(a) : "l"(p));
    return a;
}
__device__ __forceinline__ u32 swz(u32 o) { return o ^ ((o >> 3) & 0x70); }

__device__ __forceinline__ void cpasync16(u32 dst, const void* src) {
    asm volatile("cp.async.cg.shared.global [%0], [%1], 16;" :: "r"(dst), "l"(src) : "memory");
}
__device__ __forceinline__ void ldsm4(u32& r0, u32& r1, u32& r2, u32& r3, u32 a) {
    asm volatile("ldmatrix.sync.aligned.m8n8.x4.shared.b16 {%0,%1,%2,%3}, [%4];"
                 : "=r"(r0), "=r"(r1), "=r"(r2), "=r"(r3) : "r"(a));
}
__device__ __forceinline__ void mma16816(float* c, const u32* a, const u32* b) {
    asm volatile("mma.sync.aligned.m16n8k16.row.col.f32.bf16.bf16.f32 "
                 "{%0,%1,%2,%3}, {%4,%5,%6,%7}, {%8,%9}, {%0,%1,%2,%3};"
                 : "+f"(c[0]), "+f"(c[1]), "+f"(c[2]), "+f"(c[3])
                 : "r"(a[0]), "r"(a[1]), "r"(a[2]), "r"(a[3]), "r"(b[0]), "r"(b[1]));
}
__device__ __forceinline__ void mma16816h(float* c, const u32* a, const u32* b) {
    asm volatile("mma.sync.aligned.m16n8k16.row.col.f32.f16.f16.f32 "
                 "{%0,%1,%2,%3}, {%4,%5,%6,%7}, {%8,%9}, {%0,%1,%2,%3};"
                 : "+f"(c[0]), "+f"(c[1]), "+f"(c[2]), "+f"(c[3])
                 : "r"(a[0]), "r"(a[1]), "r"(a[2]), "r"(a[3]), "r"(b[0]), "r"(b[1]));
}
__device__ __forceinline__ u32 packsplit(float v0, float v1, u32& lopack) {
    __nv_bfloat16 h0 = __float2bfloat16(v0);
    __nv_bfloat16 h1 = __float2bfloat16(v1);
    __nv_bfloat16 l0 = __float2bfloat16(v0 - __bfloat162float(h0));
    __nv_bfloat16 l1 = __float2bfloat16(v1 - __bfloat162float(h1));
    lopack = (u32)__bfloat16_as_ushort(l0) | ((u32)__bfloat16_as_ushort(l1) << 16);
    return (u32)__bfloat16_as_ushort(h0) | ((u32)__bfloat16_as_ushort(h1) << 16);
}
__device__ __forceinline__ u32 packh2(float v0, float v1) {
    __half2 h = __floats2half2_rn(v0, v1);
    return *reinterpret_cast<u32*>(&h);
}

// ==================================================================
// bf16x3 GEMM (QKV only): slab-major, 128x128, BK=64, 512 threads.
// ==================================================================
__global__ void __launch_bounds__(512)
gemm_qkv(const __nv_bfloat16* __restrict__ Ah, const __nv_bfloat16* __restrict__ Al,
         const __nv_bfloat16* __restrict__ Bh, const __nv_bfloat16* __restrict__ Bl,
         __nv_bfloat16* __restrict__ Ch, __nv_bfloat16* __restrict__ Cl,
         const float* __restrict__ bias)
{
    constexpr int MT = 128, NT = 128, lda = Hn, ldb = Hn, ldc = QKVN, K = Hn;
    constexpr u32 ASZ = MT * 128u, BSZ = NT * 128u;
    constexpr u32 STG = 2 * ASZ + 2 * BSZ;

    extern __shared__ char smem[];
    const u32 sb = s2u(smem);
    const int tid = threadIdx.x, wid = tid >> 5, lane = tid & 31;
    const int warp_m = wid >> 2, warp_n = wid & 3;
    const int m0 = blockIdx.y * MT, n0 = blockIdx.x * NT;
    const int nsl = K >> 6;

    float acc[2][4][4];
#pragma unroll
    for (int mi = 0; mi < 2; mi++)
#pragma unroll
        for (int ni = 0; ni < 4; ni++)
#pragma unroll
            for (int q = 0; q < 4; q++) acc[mi][ni][q] = 0.f;

    auto prefetch = [&](int sl) {
        const u32 base = sb + (u32)(sl % 3) * STG;
#pragma unroll
        for (int i = 0; i < 2; i++) {
            int u = tid + i * 512;
            int r = u >> 3, c = u & 7;
            u32 d = swz((u32)(r * 128 + c * 16));
            size_t go = (size_t)(m0 + r) * lda + sl * 64 + c * 8;
            cpasync16(base + d, Ah + go);
            cpasync16(base + ASZ + d, Al + go);
        }
#pragma unroll
        for (int i = 0; i < 2; i++) {
            int u = tid + i * 512;
            int r = u >> 3, c = u & 7;
            u32 d = swz((u32)(r * 128 + c * 16));
            size_t go = (size_t)(n0 + r) * ldb + sl * 64 + c * 8;
            cpasync16(base + 2 * ASZ + d, Bh + go);
            cpasync16(base + 2 * ASZ + BSZ + d, Bl + go);
        }
        asm volatile("cp.async.commit_group;" ::: "memory");
    };

    prefetch(0); prefetch(1);

    for (int it = 0; it < nsl; it++) {
        if (it < nsl - 1) asm volatile("cp.async.wait_group 1;" ::: "memory");
        else              asm volatile("cp.async.wait_group 0;" ::: "memory");
        __syncthreads();
        if (it + 2 < nsl) prefetch(it + 2);

        const u32 ab = sb + (u32)(it % 3) * STG;
        const u32 bb = ab + 2 * ASZ;

#pragma unroll
        for (int ks = 0; ks < 4; ks++) {
            u32 ahr[2][4], alr[2][4];
#pragma unroll
            for (int mi = 0; mi < 2; mi++) {
                int row = warp_m * 32 + mi * 16 + (lane & 15);
                u32 off = swz((u32)(row * 128 + (ks * 16 + (lane >> 4) * 8) * 2));
                ldsm4(ahr[mi][0], ahr[mi][1], ahr[mi][2], ahr[mi][3], ab + off);
                ldsm4(alr[mi][0], alr[mi][1], alr[mi][2], alr[mi][3], ab + ASZ + off);
            }
            u32 bhr[4][2], blr[4][2];
#pragma unroll
            for (int nj = 0; nj < 2; nj++) {
                int nrow = warp_n * 32 + nj * 16 + (lane & 7) + ((lane >> 4) << 3);
                u32 off = swz((u32)(nrow * 128 + (ks * 16 + ((lane >> 3) & 1) * 8) * 2));
                u32 r0, r1, r2, r3;
                ldsm4(r0, r1, r2, r3, bb + off);
                bhr[2 * nj][0] = r0; bhr[2 * nj][1] = r1;
                bhr[2 * nj + 1][0] = r2; bhr[2 * nj + 1][1] = r3;
                ldsm4(r0, r1, r2, r3, bb + BSZ + off);
                blr[2 * nj][0] = r0; blr[2 * nj][1] = r1;
                blr[2 * nj + 1][0] = r2; blr[2 * nj + 1][1] = r3;
            }
#pragma unroll
            for (int mi = 0; mi < 2; mi++)
#pragma unroll
                for (int ni = 0; ni < 4; ni++) {
                    mma16816(acc[mi][ni], ahr[mi], bhr[ni]);
                    mma16816(acc[mi][ni], ahr[mi], blr[ni]);
                    mma16816(acc[mi][ni], alr[mi], bhr[ni]);
                }
        }
    }

    const int tg = lane & 3, g = lane >> 2;
#pragma unroll
    for (int mi = 0; mi < 2; mi++)
#pragma unroll
        for (int half = 0; half < 2; half++) {
            const int mrow = m0 + warp_m * 32 + mi * 16 + half * 8 + g;
#pragma unroll
            for (int ni = 0; ni < 4; ni++) {
                const int col = n0 + warp_n * 32 + ni * 8 + tg * 2;
                float v0 = acc[mi][ni][half * 2] + bias[col];
                float v1 = acc[mi][ni][half * 2 + 1] + bias[col + 1];
                u32 lo, hi = packsplit(v0, v1, lo);
                size_t off = (size_t)mrow * ldc + col;
                *(u32*)(Ch + off) = hi;
                *(u32*)(Cl + off) = lo;
            }
        }
}

// ==================================================================
// fp16 single-pass GEMM. EPI: 3=bias+resid->f32, 4=bias+relu->fp16
// ==================================================================
template<int MT, int NT, int EPI>
__global__ void __launch_bounds__(512)
gemm1(const __half* __restrict__ A, int lda, const __half* __restrict__ B, int ldb,
      float* __restrict__ Cf, __half* __restrict__ Ch, int ldc,
      const float* __restrict__ bias, const float* __restrict__ resid, int K)
{
    constexpr int WM = MT / 4, WN = NT / 4;
    constexpr int MI = WM / 16, NI = WN / 8;
    constexpr u32 ASZ = (u32)MT * 128u, BSZ = (u32)NT * 128u;
    constexpr u32 STG = ASZ + BSZ;

    extern __shared__ char smem[];
    const u32 sb = s2u(smem);
    const int tid = threadIdx.x, wid = tid >> 5, lane = tid & 31;
    const int warp_m = wid >> 2, warp_n = wid & 3;
    const int m0 = blockIdx.y * MT, n0 = blockIdx.x * NT;
    const int nsl = K >> 6;

    float acc[MI][NI][4];
#pragma unroll
    for (int mi = 0; mi < MI; mi++)
#pragma unroll
        for (int ni = 0; ni < NI; ni++)
#pragma unroll
            for (int q = 0; q < 4; q++) acc[mi][ni][q] = 0.f;

    auto prefetch = [&](int sl) {
        const u32 base = sb + (u32)(sl % 3) * STG;
#pragma unroll
        for (int i = 0; i < MT * 8 / 512; i++) {
            int u = tid + i * 512;
            int r = u >> 3, c = u & 7;
            cpasync16(base + swz((u32)(r * 128 + c * 16)),
                      A + (size_t)(m0 + r) * lda + sl * 64 + c * 8);
        }
#pragma unroll
        for (int i = 0; i < NT * 8 / 512; i++) {
            int u = tid + i * 512;
            int r = u >> 3, c = u & 7;
            cpasync16(base + ASZ + swz((u32)(r * 128 + c * 16)),
                      B + (size_t)(n0 + r) * ldb + sl * 64 + c * 8);
        }
        asm volatile("cp.async.commit_group;" ::: "memory");
    };

    prefetch(0); prefetch(1);

    for (int it = 0; it < nsl; it++) {
        if (it < nsl - 1) asm volatile("cp.async.wait_group 1;" ::: "memory");
        else              asm volatile("cp.async.wait_group 0;" ::: "memory");
        __syncthreads();
        if (it + 2 < nsl) prefetch(it + 2);

        const u32 ab = sb + (u32)(it % 3) * STG;
        const u32 bb = ab + ASZ;

#pragma unroll
        for (int ks = 0; ks < 4; ks++) {
            u32 ar[MI][4];
#pragma unroll
            for (int mi = 0; mi < MI; mi++) {
                int row = warp_m * WM + mi * 16 + (lane & 15);
                u32 off = swz((u32)(row * 128 + (ks * 16 + (lane >> 4) * 8) * 2));
                ldsm4(ar[mi][0], ar[mi][1], ar[mi][2], ar[mi][3], ab + off);
            }
            u32 br[NI][2];
#pragma unroll
            for (int nj = 0; nj < NI / 2; nj++) {
                int nrow = warp_n * WN + nj * 16 + (lane & 7) + ((lane >> 4) << 3);
                u32 off = swz((u32)(nrow * 128 + (ks * 16 + ((lane >> 3) & 1) * 8) * 2));
                u32 r0, r1, r2, r3;
                ldsm4(r0, r1, r2, r3, bb + off);
                br[2 * nj][0] = r0; br[2 * nj][1] = r1;
                br[2 * nj + 1][0] = r2; br[2 * nj + 1][1] = r3;
            }
#pragma unroll
            for (int mi = 0; mi < MI; mi++)
#pragma unroll
                for (int ni = 0; ni < NI; ni++)
                    mma16816h(acc[mi][ni], ar[mi], br[ni]);
        }
    }

    const int tg = lane & 3, g = lane >> 2;
#pragma unroll
    for (int mi = 0; mi < MI; mi++)
#pragma unroll
        for (int half = 0; half < 2; half++) {
            const int mrow = m0 + warp_m * WM + mi * 16 + half * 8 + g;
#pragma unroll
            for (int ni = 0; ni < NI; ni++) {
                const int col = n0 + warp_n * WN + ni * 8 + tg * 2;
                float v0 = acc[mi][ni][half * 2]     + bias[col];
                float v1 = acc[mi][ni][half * 2 + 1] + bias[col + 1];
                size_t off = (size_t)mrow * ldc + col;
                if (EPI == 3) {
                    float2 rv = *(const float2*)(resid + off);
                    *(float2*)(Cf + off) = make_float2(v0 + rv.x, v1 + rv.y);
                } else {
                    v0 = fmaxf(v0, 0.f); v1 = fmaxf(v1, 0.f);
                    *(u32*)(Ch + off) = packh2(v0, v1);
                }
            }
        }
}

// ==================================================================
// Fused attention: scores(bf16x3) + softmax + P@V(fp16). 64 q-rows/(b,h).
// smem: Qh[0,8K) Ql[8K,16K) Kh[16K,80K)->P Kl[80K,144K) V[144K,208K) red[208K..]
// ==================================================================
#define ATT_K    16384u
#define ATT_KL   81920u
#define ATT_V    147456u
#define ATT_RED  212992
#define SMEM_ATT (ATT_RED + 2048)

__global__ void __launch_bounds__(256)
attn_fused(const __nv_bfloat16* __restrict__ qh, const __nv_bfloat16* __restrict__ ql,
           const __half* __restrict__ vt, const int* __restrict__ tok,
           float* __restrict__ attn, __half* __restrict__ ct)
{
    extern __shared__ char smem[];
    const u32 sb = s2u(smem);
    const int tid = threadIdx.x, wid = tid >> 5, lane = tid & 31;
    const int g = lane >> 2, tg = lane & 3;
    const int m0 = blockIdx.x * 64;
    const int zbh = blockIdx.y;
    const int b = zbh / NHn, h = zbh - b * NHn;

    const __nv_bfloat16* Qh_src = qh + (size_t)(b * Sn + m0) * QKVN + h * 64;
    const __nv_bfloat16* Ql_src = ql + (size_t)(b * Sn + m0) * QKVN + h * 64;
    const __nv_bfloat16* Kh_src = qh + (size_t)(b * Sn) * QKVN + 768 + h * 64;
    const __nv_bfloat16* Kl_src = ql + (size_t)(b * Sn) * QKVN + 768 + h * 64;

    for (int u = tid; u < 512; u += 256) {
        int r = u >> 3, c = u & 7;
        u32 d = swz((u32)(r * 128 + c * 16));
        size_t go = (size_t)r * QKVN + c * 8;
        cpasync16(sb + d, Qh_src + go);
        cpasync16(sb + 8192 + d, Ql_src + go);
    }
    for (int u = tid; u < 4096; u += 256) {
        int r = u >> 3, c = u & 7;
        u32 d = swz((u32)(r * 128 + c * 16));
        size_t go = (size_t)r * QKVN + c * 8;
        cpasync16(sb + ATT_K + d, Kh_src + go);
        cpasync16(sb + ATT_KL + d, Kl_src + go);
    }
    asm volatile("cp.async.commit_group;" ::: "memory");

    // V full tile (64 d-rows x 512 s) fp16, 8 slabs of 64x64
    {
        const __half* V_src = vt + (size_t)(b * Hn + h * 64) * Sn;
        for (int u = tid; u < 4096; u += 256) {
            int sl = u >> 9, r = (u >> 3) & 63, c = u & 7;
            u32 d = (u32)(sl * 8192) + swz((u32)(r * 128 + c * 16));
            cpasync16(sb + ATT_V + d, V_src + (size_t)r * Sn + sl * 64 + c * 8);
        }
        asm volatile("cp.async.commit_group;" ::: "memory");
    }

    asm volatile("cp.async.wait_group 1;" ::: "memory");   // Q,K ready
    __syncthreads();

    // ---- scores bf16x3 ----
    float acc[4][8][4];
#pragma unroll
    for (int mi = 0; mi < 4; mi++)
#pragma unroll
        for (int ni = 0; ni < 8; ni++)
#pragma unroll
            for (int q = 0; q < 4; q++) acc[mi][ni][q] = 0.f;

#pragma unroll
    for (int pass = 0; pass < 3; pass++) {
        const u32 ab = sb + (pass == 2 ? 8192u : 0u);
        const u32 bb = sb + (pass == 1 ? ATT_KL : ATT_K);
#pragma unroll
        for (int ks = 0; ks < 4; ks++) {
            u32 arg[4][4];
#pragma unroll
            for (int mi = 0; mi < 4; mi++) {
                int row = mi * 16 + (lane & 15);
                u32 off = swz((u32)(row * 128 + (ks * 16 + (lane >> 4) * 8) * 2));
                ldsm4(arg[mi][0], arg[mi][1], arg[mi][2], arg[mi][3], ab + off);
            }
            u32 brg[8][2];
#pragma unroll
            for (int nj = 0; nj < 4; nj++) {
                int nrow = wid * 64 + nj * 16 + (lane & 7) + ((lane >> 4) << 3);
                u32 off = swz((u32)(nrow * 128 + (ks * 16 + ((lane >> 3) & 1) * 8) * 2));
                u32 r0, r1, r2, r3;
                ldsm4(r0, r1, r2, r3, bb + off);
                brg[2 * nj][0] = r0; brg[2 * nj][1] = r1;
                brg[2 * nj + 1][0] = r2; brg[2 * nj + 1][1] = r3;
            }
#pragma unroll
            for (int mi = 0; mi < 4; mi++)
#pragma unroll
                for (int ni = 0; ni < 8; ni++)
                    mma16816(acc[mi][ni], arg[mi], brg[ni]);
        }
    }
    __syncthreads();   // done reading Kh (P will overwrite)

    // ---- scale + mask ----
    float mk[8][2];
#pragma unroll
    for (int ni = 0; ni < 8; ni++) {
        int c = wid * 64 + ni * 8 + tg * 2;
        mk[ni][0] = (tok[b * Sn + c]     == 0) ? -10000.f : 0.f;
        mk[ni][1] = (tok[b * Sn + c + 1] == 0) ? -10000.f : 0.f;
    }
#pragma unroll
    for (int mi = 0; mi < 4; mi++)
#pragma unroll
        for (int ni = 0; ni < 8; ni++)
#pragma unroll
            for (int q = 0; q < 4; q++)
                acc[mi][ni][q] = acc[mi][ni][q] * 0.125f + mk[ni][q & 1];

    float* red = (float*)(smem + ATT_RED);
    float rmax[8], rsum[8];

#pragma unroll
    for (int mi = 0; mi < 4; mi++)
#pragma unroll
        for (int half = 0; half < 2; half++) {
            float mx = -1e30f;
#pragma unroll
            for (int ni = 0; ni < 8; ni++)
                mx = fmaxf(mx, fmaxf(acc[mi][ni][half * 2], acc[mi][ni][half * 2 + 1]));
            mx = fmaxf(mx, __shfl_xor_sync(0xffffffffu, mx, 1));
            mx = fmaxf(mx, __shfl_xor_sync(0xffffffffu, mx, 2));
            int row = mi * 16 + half * 8 + g;
            if (tg == 0) red[row * 8 + wid] = mx;
        }
    __syncthreads();
#pragma unroll
    for (int mi = 0; mi < 4; mi++)
#pragma unroll
        for (int half = 0; half < 2; half++) {
            int row = mi * 16 + half * 8 + g;
            float m = -1e30f;
#pragma unroll
            for (int w = 0; w < 8; w++) m = fmaxf(m, red[row * 8 + w]);
            rmax[mi * 2 + half] = m;
        }
    __syncthreads();

#pragma unroll
    for (int mi = 0; mi < 4; mi++)
#pragma unroll
        for (int half = 0; half < 2; half++) {
            float s = 0.f;
#pragma unroll
            for (int ni = 0; ni < 8; ni++) {
                float e0 = __expf(acc[mi][ni][half * 2]     - rmax[mi * 2 + half]);
                float e1 = __expf(acc[mi][ni][half * 2 + 1] - rmax[mi * 2 + half]);
                acc[mi][ni][half * 2] = e0; acc[mi][ni][half * 2 + 1] = e1;
                s += e0 + e1;
            }
            s += __shfl_xor_sync(0xffffffffu, s, 1);
            s += __shfl_xor_sync(0xffffffffu, s, 2);
            int row = mi * 16 + half * 8 + g;
            if (tg == 0) red[row * 8 + wid] = s;
        }
    __syncthreads();
#pragma unroll
    for (int mi = 0; mi < 4; mi++)
#pragma unroll
        for (int half = 0; half < 2; half++) {
            int row = mi * 16 + half * 8 + g;
            float s = 0.f;
#pragma unroll
            for (int w = 0; w < 8; w++) s += red[row * 8 + w];
            rsum[mi * 2 + half] = 1.f / s;
        }

    // ---- write attn fp32 + P fp16 to smem ----
#pragma unroll
    for (int mi = 0; mi < 4; mi++)
#pragma unroll
        for (int half = 0; half < 2; half++) {
            int row = mi * 16 + half * 8 + g;
            size_t rbase = (size_t)zbh * Sn * Sn + (size_t)(m0 + row) * Sn;
            float inv = rsum[mi * 2 + half];
#pragma unroll
            for (int ni = 0; ni < 8; ni++) {
                int col = ni * 8 + tg * 2;
                float p0 = acc[mi][ni][half * 2]     * inv;
                float p1 = acc[mi][ni][half * 2 + 1] * inv;
                *(float2*)(attn + rbase + wid * 64 + col) = make_float2(p0, p1);
                u32 off = (u32)(wid * 8192) + swz((u32)(row * 128 + col * 2));
                *(u32*)(smem + ATT_K + off) = packh2(p0, p1);
            }
        }

    asm volatile("cp.async.wait_group 0;" ::: "memory");   // V ready
    __syncthreads();                                        // P visible

    // ---- ctx = P @ V (fp16 single pass), 8 warps: 2m x 4n, out 64x64 ----
    const int wm = wid >> 2, wn = wid & 3;
    float acc2[2][2][4];
#pragma unroll
    for (int mi = 0; mi < 2; mi++)
#pragma unroll
        for (int ni = 0; ni < 2; ni++)
#pragma unroll
            for (int q = 0; q < 4; q++) acc2[mi][ni][q] = 0.f;

#pragma unroll 2
    for (int sl = 0; sl < 8; sl++) {
#pragma unroll
        for (int ks = 0; ks < 4; ks++) {
            u32 ar[2][4];
#pragma unroll
            for (int mi = 0; mi < 2; mi++) {
                int row = wm * 32 + mi * 16 + (lane & 15);
                u32 aoff = (u32)(sl * 8192) + swz((u32)(row * 128 + (ks * 16 + (lane >> 4) * 8) * 2));
                ldsm4(ar[mi][0], ar[mi][1], ar[mi][2], ar[mi][3], sb + ATT_K + aoff);
            }
            int nrow = wn * 16 + (lane & 7) + ((lane >> 4) << 3);
            u32 boff = (u32)(sl * 8192) + swz((u32)(nrow * 128 + (ks * 16 + ((lane >> 3) & 1) * 8) * 2));
            u32 br[2][2], r0, r1, r2, r3;
            ldsm4(r0, r1, r2, r3, sb + ATT_V + boff);
            br[0][0] = r0; br[0][1] = r1; br[1][0] = r2; br[1][1] = r3;
#pragma unroll
            for (int mi = 0; mi < 2; mi++)
#pragma unroll
                for (int ni = 0; ni < 2; ni++)
                    mma16816h(acc2[mi][ni], ar[mi], br[ni]);
        }
    }

#pragma unroll
    for (int mi = 0; mi < 2; mi++)
#pragma unroll
        for (int half = 0; half < 2; half++) {
            int row = m0 + wm * 32 + mi * 16 + half * 8 + g;
#pragma unroll
            for (int ni = 0; ni < 2; ni++) {
                int col = wn * 16 + ni * 8 + tg * 2;
                size_t off = (size_t)(b * Sn + row) * Hn + h * 64 + col;
                *(u32*)(ct + off) = packh2(acc2[mi][ni][half * 2], acc2[mi][ni][half * 2 + 1]);
            }
        }
}

// ==================================================================
// support kernels
// ==================================================================
__device__ __forceinline__ float block_sum(float v) {
    __shared__ float sh[8];
    __syncthreads();
#pragma unroll
    for (int o = 16; o; o >>= 1) v += __shfl_xor_sync(0xffffffffu, v, o);
    if ((threadIdx.x & 31) == 0) sh[threadIdx.x >> 5] = v;
    __syncthreads();
    float r = sh[threadIdx.x & 7];
#pragma unroll
    for (int o = 4; o; o >>= 1) r += __shfl_xor_sync(0xffffffffu, r, o);
    return r;
}

// QKV weights: fp32 [K,N] -> transposed bf16 hi/lo [N,K]
__global__ void tsplit3(const float* __restrict__ wq, const float* __restrict__ wk,
                        const float* __restrict__ wv,
                        __nv_bfloat16* __restrict__ oh, __nv_bfloat16* __restrict__ ol) {
    __shared__ float t[32][33];
    int z = blockIdx.z, l = z / 3, which = z - l * 3;
    const float* src = (which == 0 ? wq : which == 1 ? wk : wv) + (size_t)l * Hn * Hn;
    size_t obase = (size_t)l * PER_LQ + (size_t)which * 768 * Hn;
    int n0 = blockIdx.x * 32, k0 = blockIdx.y * 32;
    int tx = threadIdx.x;
    for (int r = threadIdx.y; r < 32; r += 8)
        t[r][tx] = src[(size_t)(k0 + r) * Hn + n0 + tx];
    __syncthreads();
    for (int r = threadIdx.y; r < 32; r += 8) {
        float v = t[tx][r];
        __nv_bfloat16 hb = __float2bfloat16(v);
        size_t o = obase + (size_t)(n0 + r) * Hn + k0 + tx;
        oh[o] = hb;
        ol[o] = __float2bfloat16(v - __bfloat162float(hb));
    }
}

// fp32 [K,N] -> transposed fp16 [N,K]
__global__ void tsplit_h(const float* __restrict__ in, __half* __restrict__ o,
                         int K, int N, long in_l, long out_l) {
    __shared__ float t[32][33];
    const float* src = in + (size_t)blockIdx.z * in_l;
    __half* dst = o + (size_t)blockIdx.z * out_l;
    int n0 = blockIdx.x * 32, k0 = blockIdx.y * 32;
    int tx = threadIdx.x;
    for (int r = threadIdx.y; r < 32; r += 8)
        t[r][tx] = src[(size_t)(k0 + r) * N + n0 + tx];
    __syncthreads();
    for (int r = threadIdx.y; r < 32; r += 8)
        dst[(size_t)(n0 + r) * K + k0 + tx] = __float2half(t[tx][r]);
}

// V transpose: qkv cols 1536:2304 (bf16 hi+lo) -> fp16 [B*768, 512]
__global__ void vtrans(const __nv_bfloat16* __restrict__ ih, const __nv_bfloat16* __restrict__ il,
                       __half* __restrict__ o) {
    __shared__ float t[32][33];
    int bb = blockIdx.z;
    int d0 = blockIdx.x * 32, s0 = blockIdx.y * 32;
    int tx = threadIdx.x;
    for (int r = threadIdx.y; r < 32; r += 8) {
        size_t off = (size_t)(bb * Sn + s0 + r) * QKVN + 1536 + d0 + tx;
        t[r][tx] = __bfloat162float(ih[off]) + __bfloat162float(il[off]);
    }
    __syncthreads();
    for (int r = threadIdx.y; r < 32; r += 8)
        o[(size_t)(bb * Hn + d0 + r) * Sn + s0 + tx] = __float2half(t[tx][r]);
}

__global__ void biaspack(const float* __restrict__ bq, const float* __restrict__ bk,
                         const float* __restrict__ bv, float* __restrict__ o) {
    int i = blockIdx.x * 256 + threadIdx.x;
    if (i >= Ln * QKVN) return;
    int l = i / QKVN, n = i - l * QKVN;
    float v = (n < 768) ? bq[l * Hn + n] : (n < 1536) ? bk[l * Hn + n - 768] : bv[l * Hn + n - 1536];
    o[i] = v;
}

__global__ void embed_kernel(const int* __restrict__ tok, const float* __restrict__ emb,
                             const float* __restrict__ pos, float* __restrict__ x,
                             __nv_bfloat16* __restrict__ xh, __nv_bfloat16* __restrict__ xl) {
    int row = blockIdx.x;
    int t = tok[row];
    const float* e = emb + (size_t)t * Hn;
    const float* p = pos + (size_t)(row % Sn) * Hn;
    size_t base = (size_t)row * Hn;
    for (int c = threadIdx.x; c < Hn; c += blockDim.x) {
        float v = e[c] + p[c];
        x[base + c] = v;
        __nv_bfloat16 hb = __float2bfloat16(v);
        xh[base + c] = hb;
        xl[base + c] = __float2bfloat16(v - __bfloat162float(hb));
    }
}

// layernorm; optional bf16 hi/lo outputs and optional fp16 output
__global__ void layernorm(const float* __restrict__ in, const float* __restrict__ g,
                          const float* __restrict__ be, float* __restrict__ out,
                          __nv_bfloat16* __restrict__ oh, __nv_bfloat16* __restrict__ ol,
                          __half* __restrict__ of) {
    size_t base = (size_t)blockIdx.x * Hn;
    int t = threadIdx.x;
    float a = in[base + t], b = in[base + t + 256], c = in[base + t + 512];
    float s = block_sum(a + b + c);
    float m = s * (1.0f / Hn);
    float d0 = a - m, d1 = b - m, d2 = c - m;
    float vs = block_sum(d0 * d0 + d1 * d1 + d2 * d2);
    float inv = rsqrtf(vs * (1.0f / Hn) + 1e-12f);
#pragma unroll
    for (int u = 0; u < 3; u++) {
        int idx = t + u * 256;
        float dv = (u == 0 ? d0 : u == 1 ? d1 : d2);
        float v = dv * inv * g[idx] + be[idx];
        out[base + idx] = v;
        if (oh) {
            __nv_bfloat16 hb = __float2bfloat16(v);
            oh[base + idx] = hb;
            ol[base + idx] = __float2bfloat16(v - __bfloat162float(hb));
        }
        if (of) of[base + idx] = __float2half(v);
    }
}

// ==================================================================
#define SMEM_QKV (3 * (2*128*128 + 2*128*128))   // 196608
#define SMEM_G1A (3 * (64*128 + 128*128))        // 73728  (MT=64,NT=128)
#define SMEM_G1B (3 * (128*128 + 128*128))       // 98304  (MT=128,NT=128)

extern "C" void kernel_launch(void* const* d_in, const int* in_sizes, int n_in,
                              void* d_out, int out_size) {
    const int*   tok = (const int*)d_in[0];
    const float* emb = (const float*)d_in[1];
    const float* pos = (const float*)d_in[2];
    const float* wq  = (const float*)d_in[3];
    const float* bq  = (const float*)d_in[4];
    const float* wk  = (const float*)d_in[5];
    const float* bk  = (const float*)d_in[6];
    const float* wv  = (const float*)d_in[7];
    const float* bv  = (const float*)d_in[8];
    const float* wo  = (const float*)d_in[9];
    const float* bo  = (const float*)d_in[10];
    const float* g1  = (const float*)d_in[11];
    const float* be1 = (const float*)d_in[12];
    const float* w1  = (const float*)d_in[13];
    const float* b1  = (const float*)d_in[14];
    const float* w2  = (const float*)d_in[15];
    const float* b2  = (const float*)d_in[16];
    const float* g2  = (const float*)d_in[17];
    const float* be2 = (const float*)d_in[18];

    float* out      = (float*)d_out;
    float* attn_out = out + (size_t)MR * Hn;

    float *x, *y, *bqkv;
    __nv_bfloat16 *wth, *wtl, *xh, *xl, *qh, *ql;
    __half *wo16, *w116, *w216, *xf, *vt, *ct, *f16;
    cudaGetSymbolAddress((void**)&x, g_x);      cudaGetSymbolAddress((void**)&y, g_y);
    cudaGetSymbolAddress((void**)&bqkv, g_bqkv);
    cudaGetSymbolAddress((void**)&wth, g_wth);  cudaGetSymbolAddress((void**)&wtl, g_wtl);
    cudaGetSymbolAddress((void**)&wo16, g_wo16);
    cudaGetSymbolAddress((void**)&w116, g_w116);
    cudaGetSymbolAddress((void**)&w216, g_w216);
    cudaGetSymbolAddress((void**)&xh, g_xh);    cudaGetSymbolAddress((void**)&xl, g_xl);
    cudaGetSymbolAddress((void**)&xf, g_xf);
    cudaGetSymbolAddress((void**)&qh, g_qh);    cudaGetSymbolAddress((void**)&ql, g_ql);
    cudaGetSymbolAddress((void**)&vt, g_vt16);
    cudaGetSymbolAddress((void**)&ct, g_ct16);
    cudaGetSymbolAddress((void**)&f16, g_f16);

    cudaFuncSetAttribute(gemm_qkv, cudaFuncAttributeMaxDynamicSharedMemorySize, SMEM_QKV);
    cudaFuncSetAttribute(gemm1<64,128,3>,  cudaFuncAttributeMaxDynamicSharedMemorySize, SMEM_G1A);
    cudaFuncSetAttribute(gemm1<128,128,4>, cudaFuncAttributeMaxDynamicSharedMemorySize, SMEM_G1B);
    cudaFuncSetAttribute(attn_fused, cudaFuncAttributeMaxDynamicSharedMemorySize, SMEM_ATT);

    dim3 tb(32, 8);
    tsplit3<<<dim3(Hn/32, Hn/32, 3*Ln), tb>>>(wq, wk, wv, wth, wtl);
    tsplit_h<<<dim3(Hn/32, Hn/32, Ln), tb>>>(wo, wo16, Hn, Hn, (long)Hn*Hn, (long)Hn*Hn);
    tsplit_h<<<dim3(Fn/32, Hn/32, Ln), tb>>>(w1, w116, Hn, Fn, (long)Hn*Fn, (long)Hn*Fn);
    tsplit_h<<<dim3(Hn/32, Fn/32, Ln), tb>>>(w2, w216, Fn, Hn, (long)Fn*Hn, (long)Fn*Hn);
    biaspack<<<(Ln*QKVN + 255)/256, 256>>>(bq, bk, bv, bqkv);
    embed_kernel<<<MR, 256>>>(tok, emb, pos, x, xh, xl);

    for (int l = 0; l < Ln; l++) {
        float* attnL = attn_out + (size_t)l * BH * Sn * Sn;

        // fused QKV (bf16x3)
        gemm_qkv<<<dim3(QKVN/128, MR/128), 512, SMEM_QKV>>>(
            xh, xl, wth + (size_t)l * PER_LQ, wtl + (size_t)l * PER_LQ,
            qh, ql, bqkv + (size_t)l * QKVN);

        vtrans<<<dim3(Hn/32, Sn/32, Bn), tb>>>(qh, ql, vt);

        // scores(bf16x3) + softmax + P@V(fp16)
        attn_fused<<<dim3(Sn/64, BH), 256, SMEM_ATT>>>(qh, ql, vt, tok, attnL, ct);

        // Wo (fp16) + resid
        gemm1<64,128,3><<<dim3(Hn/128, MR/64), 512, SMEM_G1A>>>(
            ct, Hn, wo16 + (size_t)l * Hn * Hn, Hn, y, nullptr, Hn,
            bo + (size_t)l * Hn, x, Hn);
        layernorm<<<MR, 256>>>(y, g1 + (size_t)l * Hn, be1 + (size_t)l * Hn,
                               x, nullptr, nullptr, xf);

        // FFN1 (fp16, relu)
        gemm1<128,128,4><<<dim3(Fn/128, MR/128), 512, SMEM_G1B>>>(
            xf, Hn, w116 + (size_t)l * Hn * Fn, Hn, nullptr, f16, Fn,
            b1 + (size_t)l * Fn, nullptr, Hn);

        // FFN2 (fp16) + resid
        gemm1<64,128,3><<<dim3(Hn/128, MR/64), 512, SMEM_G1A>>>(
            f16, Fn, w216 + (size_t)l * Fn * Hn, Fn, y, nullptr, Hn,
            b2 + (size_t)l * Hn, x, Fn);
        bool last = (l == Ln - 1);
        layernorm<<<MR, 256>>>(y, g2 + (size_t)l * Hn, be2 + (size_t)l * Hn,
                               x, last ? nullptr : xh, last ? nullptr : xl, nullptr);
    }

    cudaMemcpyAsync(out, x, (size_t)MR * Hn * sizeof(float), cudaMemcpyDeviceToDevice);
}

// round 7
// speedup vs baseline: 7.5812x; 1.2425x over previous
#include <cuda_runtime.h>
#include <cuda_bf16.h>
#include <cuda_fp16.h>

typedef unsigned int u32;
typedef unsigned long long u64;

#define Bn 4
#define Sn 512
#define Hn 768
#define NHn 12
#define Fn 3072
#define Ln 6
#define MR (Bn*Sn)          // 2048
#define QKVN 2304
#define BH (Bn*NHn)         // 48

// ---------------- scratch (device globals) ----------------
__device__ __half g_wqkv16[(size_t)Ln*QKVN*Hn];  // [l][n=2304][k=768]
__device__ __half g_wo16[(size_t)Ln*Hn*Hn];
__device__ __half g_w116[(size_t)Ln*Hn*Fn];
__device__ __half g_w216[(size_t)Ln*Fn*Hn];
__device__ float g_x[MR*Hn];
__device__ float g_y[MR*Hn];
__device__ float g_bqkv[Ln*QKVN];
__device__ __half g_xf[MR*Hn];
__device__ __half g_qkv16[(size_t)MR*QKVN];
__device__ __half g_ct16[MR*Hn];
__device__ __half g_f16[(size_t)MR*Fn];

// ---------------- helpers ----------------
__device__ __forceinline__ u32 s2u(const void* p) {
    u32 a;
    asm("{ .reg .u64 t; cvta.to.shared.u64 t, %1; cvt.u32.u64 %0, t; }" : "=r"(a) : "l"(p));
    return a;
}
__device__ __forceinline__ u32 swz(u32 o) { return o ^ ((o >> 3) & 0x70); }

__device__ __forceinline__ void cpasync16(u32 dst, const void* src) {
    asm volatile("cp.async.cg.shared.global [%0], [%1], 16;" :: "r"(dst), "l"(src) : "memory");
}
__device__ __forceinline__ void ldsm4(u32& r0, u32& r1, u32& r2, u32& r3, u32 a) {
    asm volatile("ldmatrix.sync.aligned.m8n8.x4.shared.b16 {%0,%1,%2,%3}, [%4];"
                 : "=r"(r0), "=r"(r1), "=r"(r2), "=r"(r3) : "r"(a));
}
__device__ __forceinline__ void ldsm4t(u32& r0, u32& r1, u32& r2, u32& r3, u32 a) {
    asm volatile("ldmatrix.sync.aligned.m8n8.x4.trans.shared.b16 {%0,%1,%2,%3}, [%4];"
                 : "=r"(r0), "=r"(r1), "=r"(r2), "=r"(r3) : "r"(a));
}
__device__ __forceinline__ void mma16816h(float* c, const u32* a, const u32* b) {
    asm volatile("mma.sync.aligned.m16n8k16.row.col.f32.f16.f16.f32 "
                 "{%0,%1,%2,%3}, {%4,%5,%6,%7}, {%8,%9}, {%0,%1,%2,%3};"
                 : "+f"(c[0]), "+f"(c[1]), "+f"(c[2]), "+f"(c[3])
                 : "r"(a[0]), "r"(a[1]), "r"(a[2]), "r"(a[3]), "r"(b[0]), "r"(b[1]));
}
__device__ __forceinline__ u32 packh2(float v0, float v1) {
    __half2 h = __floats2half2_rn(v0, v1);
    return *reinterpret_cast<u32*>(&h);
}

// ==================================================================
// fp16 single-pass GEMM. MT x NT, BK=64, 512 threads (16 warps 4x4).
// EPI: 0=bias->fp16  3=bias+resid->f32  4=bias+relu->fp16
// ==================================================================
template<int MT, int NT, int EPI>
__global__ void __launch_bounds__(512)
gemm1(const __half* __restrict__ A, int lda, const __half* __restrict__ B, int ldb,
      float* __restrict__ Cf, __half* __restrict__ Ch, int ldc,
      const float* __restrict__ bias, const float* __restrict__ resid, int K)
{
    constexpr int WM = MT / 4, WN = NT / 4;
    constexpr int MI = WM / 16, NI = WN / 8;
    constexpr u32 ASZ = (u32)MT * 128u, BSZ = (u32)NT * 128u;
    constexpr u32 STG = ASZ + BSZ;

    extern __shared__ char smem[];
    const u32 sb = s2u(smem);
    const int tid = threadIdx.x, wid = tid >> 5, lane = tid & 31;
    const int warp_m = wid >> 2, warp_n = wid & 3;
    const int m0 = blockIdx.y * MT, n0 = blockIdx.x * NT;
    const int nsl = K >> 6;

    float acc[MI][NI][4];
#pragma unroll
    for (int mi = 0; mi < MI; mi++)
#pragma unroll
        for (int ni = 0; ni < NI; ni++)
#pragma unroll
            for (int q = 0; q < 4; q++) acc[mi][ni][q] = 0.f;

    auto prefetch = [&](int sl) {
        const u32 base = sb + (u32)(sl % 3) * STG;
#pragma unroll
        for (int i = 0; i < MT * 8 / 512; i++) {
            int u = tid + i * 512;
            int r = u >> 3, c = u & 7;
            cpasync16(base + swz((u32)(r * 128 + c * 16)),
                      A + (size_t)(m0 + r) * lda + sl * 64 + c * 8);
        }
#pragma unroll
        for (int i = 0; i < NT * 8 / 512; i++) {
            int u = tid + i * 512;
            int r = u >> 3, c = u & 7;
            cpasync16(base + ASZ + swz((u32)(r * 128 + c * 16)),
                      B + (size_t)(n0 + r) * ldb + sl * 64 + c * 8);
        }
        asm volatile("cp.async.commit_group;" ::: "memory");
    };

    prefetch(0); prefetch(1);

    for (int it = 0; it < nsl; it++) {
        if (it < nsl - 1) asm volatile("cp.async.wait_group 1;" ::: "memory");
        else              asm volatile("cp.async.wait_group 0;" ::: "memory");
        __syncthreads();
        if (it + 2 < nsl) prefetch(it + 2);

        const u32 ab = sb + (u32)(it % 3) * STG;
        const u32 bb = ab + ASZ;

#pragma unroll
        for (int ks = 0; ks < 4; ks++) {
            u32 ar[MI][4];
#pragma unroll
            for (int mi = 0; mi < MI; mi++) {
                int row = warp_m * WM + mi * 16 + (lane & 15);
                u32 off = swz((u32)(row * 128 + (ks * 16 + (lane >> 4) * 8) * 2));
                ldsm4(ar[mi][0], ar[mi][1], ar[mi][2], ar[mi][3], ab + off);
            }
            u32 br[NI][2];
#pragma unroll
            for (int nj = 0; nj < NI / 2; nj++) {
                int nrow = warp_n * WN + nj * 16 + (lane & 7) + ((lane >> 4) << 3);
                u32 off = swz((u32)(nrow * 128 + (ks * 16 + ((lane >> 3) & 1) * 8) * 2));
                u32 r0, r1, r2, r3;
                ldsm4(r0, r1, r2, r3, bb + off);
                br[2 * nj][0] = r0; br[2 * nj][1] = r1;
                br[2 * nj + 1][0] = r2; br[2 * nj + 1][1] = r3;
            }
#pragma unroll
            for (int mi = 0; mi < MI; mi++)
#pragma unroll
                for (int ni = 0; ni < NI; ni++)
                    mma16816h(acc[mi][ni], ar[mi], br[ni]);
        }
    }

    const int tg = lane & 3, g = lane >> 2;
#pragma unroll
    for (int mi = 0; mi < MI; mi++)
#pragma unroll
        for (int half = 0; half < 2; half++) {
            const int mrow = m0 + warp_m * WM + mi * 16 + half * 8 + g;
#pragma unroll
            for (int ni = 0; ni < NI; ni++) {
                const int col = n0 + warp_n * WN + ni * 8 + tg * 2;
                float v0 = acc[mi][ni][half * 2]     + bias[col];
                float v1 = acc[mi][ni][half * 2 + 1] + bias[col + 1];
                size_t off = (size_t)mrow * ldc + col;
                if (EPI == 3) {
                    float2 rv = *(const float2*)(resid + off);
                    *(float2*)(Cf + off) = make_float2(v0 + rv.x, v1 + rv.y);
                } else if (EPI == 4) {
                    v0 = fmaxf(v0, 0.f); v1 = fmaxf(v1, 0.f);
                    *(u32*)(Ch + off) = packh2(v0, v1);
                } else {
                    *(u32*)(Ch + off) = packh2(v0, v1);
                }
            }
        }
}

// ==================================================================
// Fused attention (all fp16): scores + softmax + P@V. 64 q-rows/(b,h).
// Q,K,V all read directly from the qkv buffer; V used via trans-ldmatrix.
// smem: Q[0,8K)  K[8K,72K)->P  V[72K,136K)  red[136K..]
// ==================================================================
#define ATT_KP   8192u
#define ATT_V    73728u
#define ATT_RED  139264
#define SMEM_ATT (ATT_RED + 2048)

__global__ void __launch_bounds__(256)
attn_fused(const __half* __restrict__ qkv, const int* __restrict__ tok,
           float* __restrict__ attn, __half* __restrict__ ct)
{
    extern __shared__ char smem[];
    const u32 sb = s2u(smem);
    const int tid = threadIdx.x, wid = tid >> 5, lane = tid & 31;
    const int g = lane >> 2, tg = lane & 3;
    const int m0 = blockIdx.x * 64;
    const int zbh = blockIdx.y;
    const int b = zbh / NHn, h = zbh - b * NHn;

    const __half* Q_src = qkv + (size_t)(b * Sn + m0) * QKVN + h * 64;
    const __half* K_src = qkv + (size_t)(b * Sn) * QKVN + 768 + h * 64;
    const __half* V_src = qkv + (size_t)(b * Sn) * QKVN + 1536 + h * 64;

    for (int u = tid; u < 512; u += 256) {
        int r = u >> 3, c = u & 7;
        cpasync16(sb + swz((u32)(r * 128 + c * 16)), Q_src + (size_t)r * QKVN + c * 8);
    }
    for (int u = tid; u < 4096; u += 256) {
        int r = u >> 3, c = u & 7;
        cpasync16(sb + ATT_KP + swz((u32)(r * 128 + c * 16)), K_src + (size_t)r * QKVN + c * 8);
    }
    asm volatile("cp.async.commit_group;" ::: "memory");
    for (int u = tid; u < 4096; u += 256) {
        int r = u >> 3, c = u & 7;
        cpasync16(sb + ATT_V + swz((u32)(r * 128 + c * 16)), V_src + (size_t)r * QKVN + c * 8);
    }
    asm volatile("cp.async.commit_group;" ::: "memory");

    asm volatile("cp.async.wait_group 1;" ::: "memory");   // Q,K ready
    __syncthreads();

    // ---- scores = Q K^T (fp16 single pass) ----
    float acc[4][8][4];
#pragma unroll
    for (int mi = 0; mi < 4; mi++)
#pragma unroll
        for (int ni = 0; ni < 8; ni++)
#pragma unroll
            for (int q = 0; q < 4; q++) acc[mi][ni][q] = 0.f;

#pragma unroll
    for (int ks = 0; ks < 4; ks++) {
        u32 arg[4][4];
#pragma unroll
        for (int mi = 0; mi < 4; mi++) {
            int row = mi * 16 + (lane & 15);
            u32 off = swz((u32)(row * 128 + (ks * 16 + (lane >> 4) * 8) * 2));
            ldsm4(arg[mi][0], arg[mi][1], arg[mi][2], arg[mi][3], sb + off);
        }
        u32 brg[8][2];
#pragma unroll
        for (int nj = 0; nj < 4; nj++) {
            int nrow = wid * 64 + nj * 16 + (lane & 7) + ((lane >> 4) << 3);
            u32 off = swz((u32)(nrow * 128 + (ks * 16 + ((lane >> 3) & 1) * 8) * 2));
            u32 r0, r1, r2, r3;
            ldsm4(r0, r1, r2, r3, sb + ATT_KP + off);
            brg[2 * nj][0] = r0; brg[2 * nj][1] = r1;
            brg[2 * nj + 1][0] = r2; brg[2 * nj + 1][1] = r3;
        }
#pragma unroll
        for (int mi = 0; mi < 4; mi++)
#pragma unroll
            for (int ni = 0; ni < 8; ni++)
                mma16816h(acc[mi][ni], arg[mi], brg[ni]);
    }
    __syncthreads();   // all warps done reading K (P will overwrite)

    // ---- scale + mask ----
    float mk[8][2];
#pragma unroll
    for (int ni = 0; ni < 8; ni++) {
        int c = wid * 64 + ni * 8 + tg * 2;
        mk[ni][0] = (tok[b * Sn + c]     == 0) ? -10000.f : 0.f;
        mk[ni][1] = (tok[b * Sn + c + 1] == 0) ? -10000.f : 0.f;
    }
#pragma unroll
    for (int mi = 0; mi < 4; mi++)
#pragma unroll
        for (int ni = 0; ni < 8; ni++)
#pragma unroll
            for (int q = 0; q < 4; q++)
                acc[mi][ni][q] = acc[mi][ni][q] * 0.125f + mk[ni][q & 1];

    float* red = (float*)(smem + ATT_RED);
    float rmax[8], rsum[8];

#pragma unroll
    for (int mi = 0; mi < 4; mi++)
#pragma unroll
        for (int half = 0; half < 2; half++) {
            float mx = -1e30f;
#pragma unroll
            for (int ni = 0; ni < 8; ni++)
                mx = fmaxf(mx, fmaxf(acc[mi][ni][half * 2], acc[mi][ni][half * 2 + 1]));
            mx = fmaxf(mx, __shfl_xor_sync(0xffffffffu, mx, 1));
            mx = fmaxf(mx, __shfl_xor_sync(0xffffffffu, mx, 2));
            int row = mi * 16 + half * 8 + g;
            if (tg == 0) red[row * 8 + wid] = mx;
        }
    __syncthreads();
#pragma unroll
    for (int mi = 0; mi < 4; mi++)
#pragma unroll
        for (int half = 0; half < 2; half++) {
            int row = mi * 16 + half * 8 + g;
            float m = -1e30f;
#pragma unroll
            for (int w = 0; w < 8; w++) m = fmaxf(m, red[row * 8 + w]);
            rmax[mi * 2 + half] = m;
        }
    __syncthreads();

#pragma unroll
    for (int mi = 0; mi < 4; mi++)
#pragma unroll
        for (int half = 0; half < 2; half++) {
            float s = 0.f;
#pragma unroll
            for (int ni = 0; ni < 8; ni++) {
                float e0 = __expf(acc[mi][ni][half * 2]     - rmax[mi * 2 + half]);
                float e1 = __expf(acc[mi][ni][half * 2 + 1] - rmax[mi * 2 + half]);
                acc[mi][ni][half * 2] = e0; acc[mi][ni][half * 2 + 1] = e1;
                s += e0 + e1;
            }
            s += __shfl_xor_sync(0xffffffffu, s, 1);
            s += __shfl_xor_sync(0xffffffffu, s, 2);
            int row = mi * 16 + half * 8 + g;
            if (tg == 0) red[row * 8 + wid] = s;
        }
    __syncthreads();
#pragma unroll
    for (int mi = 0; mi < 4; mi++)
#pragma unroll
        for (int half = 0; half < 2; half++) {
            int row = mi * 16 + half * 8 + g;
            float s = 0.f;
#pragma unroll
            for (int w = 0; w < 8; w++) s += red[row * 8 + w];
            rsum[mi * 2 + half] = 1.f / s;
        }

    // ---- write attn fp32 + P fp16 into smem (over K region, 8 slabs 64x64) ----
#pragma unroll
    for (int mi = 0; mi < 4; mi++)
#pragma unroll
        for (int half = 0; half < 2; half++) {
            int row = mi * 16 + half * 8 + g;
            size_t rbase = (size_t)zbh * Sn * Sn + (size_t)(m0 + row) * Sn;
            float inv = rsum[mi * 2 + half];
#pragma unroll
            for (int ni = 0; ni < 8; ni++) {
                int col = ni * 8 + tg * 2;
                float p0 = acc[mi][ni][half * 2]     * inv;
                float p1 = acc[mi][ni][half * 2 + 1] * inv;
                *(float2*)(attn + rbase + wid * 64 + col) = make_float2(p0, p1);
                u32 off = (u32)(wid * 8192) + swz((u32)(row * 128 + col * 2));
                *(u32*)(smem + ATT_KP + off) = packh2(p0, p1);
            }
        }

    asm volatile("cp.async.wait_group 0;" ::: "memory");   // V ready
    __syncthreads();                                        // P visible

    // ---- ctx = P @ V : A = P slabs, B = V via trans-ldmatrix ----
    const int wm = wid >> 2, wn = wid & 3;
    float acc2[2][2][4];
#pragma unroll
    for (int mi = 0; mi < 2; mi++)
#pragma unroll
        for (int ni = 0; ni < 2; ni++)
#pragma unroll
            for (int q = 0; q < 4; q++) acc2[mi][ni][q] = 0.f;

#pragma unroll 2
    for (int sl = 0; sl < 8; sl++) {
#pragma unroll
        for (int ks = 0; ks < 4; ks++) {
            u32 ar[2][4];
#pragma unroll
            for (int mi = 0; mi < 2; mi++) {
                int row = wm * 32 + mi * 16 + (lane & 15);
                u32 aoff = (u32)(sl * 8192) + swz((u32)(row * 128 + (ks * 16 + (lane >> 4) * 8) * 2));
                ldsm4(ar[mi][0], ar[mi][1], ar[mi][2], ar[mi][3], sb + ATT_KP + aoff);
            }
            // B: V[s][d] with trans-ldsm -> B[k=s][n=d] fragments
            int srow = sl * 64 + ks * 16 + (lane & 7) + ((lane >> 3) & 1) * 8;
            int dcol = wn * 16 + ((lane >> 4) << 3);
            u32 boff = swz((u32)(srow * 128 + dcol * 2));
            u32 br[2][2], r0, r1, r2, r3;
            ldsm4t(r0, r1, r2, r3, sb + ATT_V + boff);
            br[0][0] = r0; br[0][1] = r1; br[1][0] = r2; br[1][1] = r3;
#pragma unroll
            for (int mi = 0; mi < 2; mi++)
#pragma unroll
                for (int ni = 0; ni < 2; ni++)
                    mma16816h(acc2[mi][ni], ar[mi], br[ni]);
        }
    }

#pragma unroll
    for (int mi = 0; mi < 2; mi++)
#pragma unroll
        for (int half = 0; half < 2; half++) {
            int row = m0 + wm * 32 + mi * 16 + half * 8 + g;
#pragma unroll
            for (int ni = 0; ni < 2; ni++) {
                int col = wn * 16 + ni * 8 + tg * 2;
                size_t off = (size_t)(b * Sn + row) * Hn + h * 64 + col;
                *(u32*)(ct + off) = packh2(acc2[mi][ni][half * 2], acc2[mi][ni][half * 2 + 1]);
            }
        }
}

// ==================================================================
// support kernels
// ==================================================================
__device__ __forceinline__ float block_sum(float v) {
    __shared__ float sh[8];
    __syncthreads();
#pragma unroll
    for (int o = 16; o; o >>= 1) v += __shfl_xor_sync(0xffffffffu, v, o);
    if ((threadIdx.x & 31) == 0) sh[threadIdx.x >> 5] = v;
    __syncthreads();
    float r = sh[threadIdx.x & 7];
#pragma unroll
    for (int o = 4; o; o >>= 1) r += __shfl_xor_sync(0xffffffffu, r, o);
    return r;
}

// wq,wk,wv -> packed qkv fp16 [N=2304,K]; wo -> own buffer. fp32 [K,N] -> [N,K]
__global__ void tsplit4h(const float* __restrict__ wq, const float* __restrict__ wk,
                         const float* __restrict__ wv, const float* __restrict__ wo,
                         __half* __restrict__ oqkv, __half* __restrict__ owo) {
    __shared__ float t[32][33];
    int z = blockIdx.z, l = z >> 2, which = z & 3;
    const float* src = (which == 0 ? wq : which == 1 ? wk : which == 2 ? wv : wo)
                       + (size_t)l * Hn * Hn;
    __half* dst;
    size_t obase;
    if (which < 3) { dst = oqkv; obase = (size_t)l * QKVN * Hn + (size_t)which * 768 * Hn; }
    else           { dst = owo;  obase = (size_t)l * Hn * Hn; }
    int n0 = blockIdx.x * 32, k0 = blockIdx.y * 32;
    int tx = threadIdx.x;
    for (int r = threadIdx.y; r < 32; r += 8)
        t[r][tx] = src[(size_t)(k0 + r) * Hn + n0 + tx];
    __syncthreads();
    for (int r = threadIdx.y; r < 32; r += 8)
        dst[obase + (size_t)(n0 + r) * Hn + k0 + tx] = __float2half(t[tx][r]);
}

// fp32 [K,N] -> transposed fp16 [N,K]
__global__ void tsplit_h(const float* __restrict__ in, __half* __restrict__ o,
                         int K, int N, long in_l, long out_l) {
    __shared__ float t[32][33];
    const float* src = in + (size_t)blockIdx.z * in_l;
    __half* dst = o + (size_t)blockIdx.z * out_l;
    int n0 = blockIdx.x * 32, k0 = blockIdx.y * 32;
    int tx = threadIdx.x;
    for (int r = threadIdx.y; r < 32; r += 8)
        t[r][tx] = src[(size_t)(k0 + r) * N + n0 + tx];
    __syncthreads();
    for (int r = threadIdx.y; r < 32; r += 8)
        dst[(size_t)(n0 + r) * K + k0 + tx] = __float2half(t[tx][r]);
}

__global__ void biaspack(const float* __restrict__ bq, const float* __restrict__ bk,
                         const float* __restrict__ bv, float* __restrict__ o) {
    int i = blockIdx.x * 256 + threadIdx.x;
    if (i >= Ln * QKVN) return;
    int l = i / QKVN, n = i - l * QKVN;
    float v = (n < 768) ? bq[l * Hn + n] : (n < 1536) ? bk[l * Hn + n - 768] : bv[l * Hn + n - 1536];
    o[i] = v;
}

__global__ void embed_kernel(const int* __restrict__ tok, const float* __restrict__ emb,
                             const float* __restrict__ pos, float* __restrict__ x,
                             __half* __restrict__ xf) {
    int row = blockIdx.x;
    int t = tok[row];
    const float* e = emb + (size_t)t * Hn;
    const float* p = pos + (size_t)(row % Sn) * Hn;
    size_t base = (size_t)row * Hn;
    for (int c = threadIdx.x; c < Hn; c += blockDim.x) {
        float v = e[c] + p[c];
        x[base + c] = v;
        xf[base + c] = __float2half(v);
    }
}

__global__ void layernorm(const float* __restrict__ in, const float* __restrict__ g,
                          const float* __restrict__ be, float* __restrict__ out,
                          __half* __restrict__ of) {
    size_t base = (size_t)blockIdx.x * Hn;
    int t = threadIdx.x;
    float a = in[base + t], b = in[base + t + 256], c = in[base + t + 512];
    float s = block_sum(a + b + c);
    float m = s * (1.0f / Hn);
    float d0 = a - m, d1 = b - m, d2 = c - m;
    float vs = block_sum(d0 * d0 + d1 * d1 + d2 * d2);
    float inv = rsqrtf(vs * (1.0f / Hn) + 1e-12f);
#pragma unroll
    for (int u = 0; u < 3; u++) {
        int idx = t + u * 256;
        float dv = (u == 0 ? d0 : u == 1 ? d1 : d2);
        float v = dv * inv * g[idx] + be[idx];
        out[base + idx] = v;
        of[base + idx] = __float2half(v);
    }
}

// ==================================================================
#define SMEM_G1A (3 * (64*128 + 128*128))        // 73728  (MT=64,NT=128)
#define SMEM_G1B (3 * (128*128 + 128*128))       // 98304  (MT=128,NT=128)

extern "C" void kernel_launch(void* const* d_in, const int* in_sizes, int n_in,
                              void* d_out, int out_size) {
    const int*   tok = (const int*)d_in[0];
    const float* emb = (const float*)d_in[1];
    const float* pos = (const float*)d_in[2];
    const float* wq  = (const float*)d_in[3];
    const float* bq  = (const float*)d_in[4];
    const float* wk  = (const float*)d_in[5];
    const float* bk  = (const float*)d_in[6];
    const float* wv  = (const float*)d_in[7];
    const float* bv  = (const float*)d_in[8];
    const float* wo  = (const float*)d_in[9];
    const float* bo  = (const float*)d_in[10];
    const float* g1  = (const float*)d_in[11];
    const float* be1 = (const float*)d_in[12];
    const float* w1  = (const float*)d_in[13];
    const float* b1  = (const float*)d_in[14];
    const float* w2  = (const float*)d_in[15];
    const float* b2  = (const float*)d_in[16];
    const float* g2  = (const float*)d_in[17];
    const float* be2 = (const float*)d_in[18];

    float* out      = (float*)d_out;
    float* attn_out = out + (size_t)MR * Hn;

    float *x, *y, *bqkv;
    __half *wqkv16, *wo16, *w116, *w216, *xf, *qkv16, *ct, *f16;
    cudaGetSymbolAddress((void**)&x, g_x);      cudaGetSymbolAddress((void**)&y, g_y);
    cudaGetSymbolAddress((void**)&bqkv, g_bqkv);
    cudaGetSymbolAddress((void**)&wqkv16, g_wqkv16);
    cudaGetSymbolAddress((void**)&wo16, g_wo16);
    cudaGetSymbolAddress((void**)&w116, g_w116);
    cudaGetSymbolAddress((void**)&w216, g_w216);
    cudaGetSymbolAddress((void**)&xf, g_xf);
    cudaGetSymbolAddress((void**)&qkv16, g_qkv16);
    cudaGetSymbolAddress((void**)&ct, g_ct16);
    cudaGetSymbolAddress((void**)&f16, g_f16);

    cudaFuncSetAttribute(gemm1<128,128,0>, cudaFuncAttributeMaxDynamicSharedMemorySize, SMEM_G1B);
    cudaFuncSetAttribute(gemm1<64,128,3>,  cudaFuncAttributeMaxDynamicSharedMemorySize, SMEM_G1A);
    cudaFuncSetAttribute(gemm1<128,128,4>, cudaFuncAttributeMaxDynamicSharedMemorySize, SMEM_G1B);
    cudaFuncSetAttribute(attn_fused, cudaFuncAttributeMaxDynamicSharedMemorySize, SMEM_ATT);

    dim3 tb(32, 8);
    // 5 prologue launches so ncu -s 5 lands on the QKV GEMM
    tsplit4h<<<dim3(Hn/32, Hn/32, 4*Ln), tb>>>(wq, wk, wv, wo, wqkv16, wo16);
    tsplit_h<<<dim3(Fn/32, Hn/32, Ln), tb>>>(w1, w116, Hn, Fn, (long)Hn*Fn, (long)Hn*Fn);
    tsplit_h<<<dim3(Hn/32, Fn/32, Ln), tb>>>(w2, w216, Fn, Hn, (long)Fn*Hn, (long)Fn*Hn);
    biaspack<<<(Ln*QKVN + 255)/256, 256>>>(bq, bk, bv, bqkv);
    embed_kernel<<<MR, 256>>>(tok, emb, pos, x, xf);

    for (int l = 0; l < Ln; l++) {
        float* attnL = attn_out + (size_t)l * BH * Sn * Sn;

        // fused QKV projection (fp16)
        gemm1<128,128,0><<<dim3(QKVN/128, MR/128), 512, SMEM_G1B>>>(
            xf, Hn, wqkv16 + (size_t)l * QKVN * Hn, Hn, nullptr, qkv16, QKVN,
            bqkv + (size_t)l * QKVN, nullptr, Hn);

        // scores + softmax + P@V (all fp16)
        attn_fused<<<dim3(Sn/64, BH), 256, SMEM_ATT>>>(qkv16, tok, attnL, ct);

        // Wo + resid
        gemm1<64,128,3><<<dim3(Hn/128, MR/64), 512, SMEM_G1A>>>(
            ct, Hn, wo16 + (size_t)l * Hn * Hn, Hn, y, nullptr, Hn,
            bo + (size_t)l * Hn, x, Hn);
        layernorm<<<MR, 256>>>(y, g1 + (size_t)l * Hn, be1 + (size_t)l * Hn, x, xf);

        // FFN1 (relu)
        gemm1<128,128,4><<<dim3(Fn/128, MR/128), 512, SMEM_G1B>>>(
            xf, Hn, w116 + (size_t)l * Hn * Fn, Hn, nullptr, f16, Fn,
            b1 + (size_t)l * Fn, nullptr, Hn);

        // FFN2 + resid
        gemm1<64,128,3><<<dim3(Hn/128, MR/64), 512, SMEM_G1A>>>(
            f16, Fn, w216 + (size_t)l * Fn * Hn, Fn, y, nullptr, Hn,
            b2 + (size_t)l * Hn, x, Fn);
        layernorm<<<MR, 256>>>(y, g2 + (size_t)l * Hn, be2 + (size_t)l * Hn, x, xf);
    }

    cudaMemcpyAsync(out, x, (size_t)MR * Hn * sizeof(float), cudaMemcpyDeviceToDevice);
}

// round 8
// speedup vs baseline: 8.0023x; 1.0555x over previous
#include <cuda_runtime.h>
#include <cuda_bf16.h>
#include <cuda_fp16.h>

typedef unsigned int u32;
typedef unsigned long long u64;

#define Bn 4
#define Sn 512
#define Hn 768
#define NHn 12
#define Fn 3072
#define Ln 6
#define MR (Bn*Sn)          // 2048
#define QKVN 2304
#define BH (Bn*NHn)         // 48

// ---------------- scratch (device globals) ----------------
__device__ __half g_wqkv16[(size_t)Ln*QKVN*Hn];  // [l][n=2304][k=768]
__device__ __half g_wo16[(size_t)Ln*Hn*Hn];
__device__ __half g_w116[(size_t)Ln*Hn*Fn];
__device__ __half g_w216[(size_t)Ln*Fn*Hn];
__device__ float g_x[MR*Hn];
__device__ float g_y[MR*Hn];
__device__ float g_bqkv[Ln*QKVN];
__device__ __half g_xf[MR*Hn];
__device__ __half g_qkv16[(size_t)MR*QKVN];
__device__ __half g_ct16[MR*Hn];
__device__ __half g_f16[(size_t)MR*Fn];

// ---------------- helpers ----------------
__device__ __forceinline__ u32 s2u(const void* p) {
    u32 a;
    asm("{ .reg .u64 t; cvta.to.shared.u64 t, %1; cvt.u32.u64 %0, t; }" : "=r"(a) : "l"(p));
    return a;
}
__device__ __forceinline__ u32 swz(u32 o) { return o ^ ((o >> 3) & 0x70); }

__device__ __forceinline__ void cpasync16(u32 dst, const void* src) {
    asm volatile("cp.async.cg.shared.global [%0], [%1], 16;" :: "r"(dst), "l"(src) : "memory");
}
__device__ __forceinline__ void ldsm4(u32& r0, u32& r1, u32& r2, u32& r3, u32 a) {
    asm volatile("ldmatrix.sync.aligned.m8n8.x4.shared.b16 {%0,%1,%2,%3}, [%4];"
                 : "=r"(r0), "=r"(r1), "=r"(r2), "=r"(r3) : "r"(a));
}
__device__ __forceinline__ void ldsm4t(u32& r0, u32& r1, u32& r2, u32& r3, u32 a) {
    asm volatile("ldmatrix.sync.aligned.m8n8.x4.trans.shared.b16 {%0,%1,%2,%3}, [%4];"
                 : "=r"(r0), "=r"(r1), "=r"(r2), "=r"(r3) : "r"(a));
}
__device__ __forceinline__ void mma16816h(float* c, const u32* a, const u32* b) {
    asm volatile("mma.sync.aligned.m16n8k16.row.col.f32.f16.f16.f32 "
                 "{%0,%1,%2,%3}, {%4,%5,%6,%7}, {%8,%9}, {%0,%1,%2,%3};"
                 : "+f"(c[0]), "+f"(c[1]), "+f"(c[2]), "+f"(c[3])
                 : "r"(a[0]), "r"(a[1]), "r"(a[2]), "r"(a[3]), "r"(b[0]), "r"(b[1]));
}
__device__ __forceinline__ u32 packh2(float v0, float v1) {
    __half2 h = __floats2half2_rn(v0, v1);
    return *reinterpret_cast<u32*>(&h);
}

// ==================================================================
// fp16 single-pass GEMM. MT x NT, BK=64, 512 threads (16 warps 4x4).
// EPI: 0=bias->fp16  3=bias+resid->f32  4=bias+relu->fp16
// ==================================================================
template<int MT, int NT, int EPI>
__global__ void __launch_bounds__(512)
gemm1(const __half* __restrict__ A, int lda, const __half* __restrict__ B, int ldb,
      float* __restrict__ Cf, __half* __restrict__ Ch, int ldc,
      const float* __restrict__ bias, const float* __restrict__ resid, int K)
{
    constexpr int WM = MT / 4, WN = NT / 4;
    constexpr int MI = WM / 16, NI = WN / 8;
    constexpr u32 ASZ = (u32)MT * 128u, BSZ = (u32)NT * 128u;
    constexpr u32 STG = ASZ + BSZ;

    extern __shared__ char smem[];
    const u32 sb = s2u(smem);
    const int tid = threadIdx.x, wid = tid >> 5, lane = tid & 31;
    const int warp_m = wid >> 2, warp_n = wid & 3;
    const int m0 = blockIdx.y * MT, n0 = blockIdx.x * NT;
    const int nsl = K >> 6;

    float acc[MI][NI][4];
#pragma unroll
    for (int mi = 0; mi < MI; mi++)
#pragma unroll
        for (int ni = 0; ni < NI; ni++)
#pragma unroll
            for (int q = 0; q < 4; q++) acc[mi][ni][q] = 0.f;

    auto prefetch = [&](int sl) {
        const u32 base = sb + (u32)(sl % 3) * STG;
#pragma unroll
        for (int i = 0; i < MT * 8 / 512; i++) {
            int u = tid + i * 512;
            int r = u >> 3, c = u & 7;
            cpasync16(base + swz((u32)(r * 128 + c * 16)),
                      A + (size_t)(m0 + r) * lda + sl * 64 + c * 8);
        }
#pragma unroll
        for (int i = 0; i < NT * 8 / 512; i++) {
            int u = tid + i * 512;
            int r = u >> 3, c = u & 7;
            cpasync16(base + ASZ + swz((u32)(r * 128 + c * 16)),
                      B + (size_t)(n0 + r) * ldb + sl * 64 + c * 8);
        }
        asm volatile("cp.async.commit_group;" ::: "memory");
    };

    prefetch(0); prefetch(1);

    for (int it = 0; it < nsl; it++) {
        if (it < nsl - 1) asm volatile("cp.async.wait_group 1;" ::: "memory");
        else              asm volatile("cp.async.wait_group 0;" ::: "memory");
        __syncthreads();
        if (it + 2 < nsl) prefetch(it + 2);

        const u32 ab = sb + (u32)(it % 3) * STG;
        const u32 bb = ab + ASZ;

#pragma unroll
        for (int ks = 0; ks < 4; ks++) {
            u32 ar[MI][4];
#pragma unroll
            for (int mi = 0; mi < MI; mi++) {
                int row = warp_m * WM + mi * 16 + (lane & 15);
                u32 off = swz((u32)(row * 128 + (ks * 16 + (lane >> 4) * 8) * 2));
                ldsm4(ar[mi][0], ar[mi][1], ar[mi][2], ar[mi][3], ab + off);
            }
            u32 br[NI][2];
#pragma unroll
            for (int nj = 0; nj < NI / 2; nj++) {
                int nrow = warp_n * WN + nj * 16 + (lane & 7) + ((lane >> 4) << 3);
                u32 off = swz((u32)(nrow * 128 + (ks * 16 + ((lane >> 3) & 1) * 8) * 2));
                u32 r0, r1, r2, r3;
                ldsm4(r0, r1, r2, r3, bb + off);
                br[2 * nj][0] = r0; br[2 * nj][1] = r1;
                br[2 * nj + 1][0] = r2; br[2 * nj + 1][1] = r3;
            }
#pragma unroll
            for (int mi = 0; mi < MI; mi++)
#pragma unroll
                for (int ni = 0; ni < NI; ni++)
                    mma16816h(acc[mi][ni], ar[mi], br[ni]);
        }
    }

    const int tg = lane & 3, g = lane >> 2;
#pragma unroll
    for (int mi = 0; mi < MI; mi++)
#pragma unroll
        for (int half = 0; half < 2; half++) {
            const int mrow = m0 + warp_m * WM + mi * 16 + half * 8 + g;
#pragma unroll
            for (int ni = 0; ni < NI; ni++) {
                const int col = n0 + warp_n * WN + ni * 8 + tg * 2;
                float v0 = acc[mi][ni][half * 2]     + bias[col];
                float v1 = acc[mi][ni][half * 2 + 1] + bias[col + 1];
                size_t off = (size_t)mrow * ldc + col;
                if (EPI == 3) {
                    float2 rv = *(const float2*)(resid + off);
                    *(float2*)(Cf + off) = make_float2(v0 + rv.x, v1 + rv.y);
                } else if (EPI == 4) {
                    v0 = fmaxf(v0, 0.f); v1 = fmaxf(v1, 0.f);
                    *(u32*)(Ch + off) = packh2(v0, v1);
                } else {
                    *(u32*)(Ch + off) = packh2(v0, v1);
                }
            }
        }
}

// ==================================================================
// Fused attention (all fp16): scores + softmax + P@V. 64 q-rows/(b,h).
// smem: Q[0,8K)  K[8K,72K)->P  V[72K,136K)  red[136K..]
// ==================================================================
#define ATT_KP   8192u
#define ATT_V    73728u
#define ATT_RED  139264
#define SMEM_ATT (ATT_RED + 2048)

__global__ void __launch_bounds__(256)
attn_fused(const __half* __restrict__ qkv, const int* __restrict__ tok,
           float* __restrict__ attn, __half* __restrict__ ct)
{
    extern __shared__ char smem[];
    const u32 sb = s2u(smem);
    const int tid = threadIdx.x, wid = tid >> 5, lane = tid & 31;
    const int g = lane >> 2, tg = lane & 3;
    const int m0 = blockIdx.x * 64;
    const int zbh = blockIdx.y;
    const int b = zbh / NHn, h = zbh - b * NHn;

    const __half* Q_src = qkv + (size_t)(b * Sn + m0) * QKVN + h * 64;
    const __half* K_src = qkv + (size_t)(b * Sn) * QKVN + 768 + h * 64;
    const __half* V_src = qkv + (size_t)(b * Sn) * QKVN + 1536 + h * 64;

    for (int u = tid; u < 512; u += 256) {
        int r = u >> 3, c = u & 7;
        cpasync16(sb + swz((u32)(r * 128 + c * 16)), Q_src + (size_t)r * QKVN + c * 8);
    }
    for (int u = tid; u < 4096; u += 256) {
        int r = u >> 3, c = u & 7;
        cpasync16(sb + ATT_KP + swz((u32)(r * 128 + c * 16)), K_src + (size_t)r * QKVN + c * 8);
    }
    asm volatile("cp.async.commit_group;" ::: "memory");
    for (int u = tid; u < 4096; u += 256) {
        int r = u >> 3, c = u & 7;
        cpasync16(sb + ATT_V + swz((u32)(r * 128 + c * 16)), V_src + (size_t)r * QKVN + c * 8);
    }
    asm volatile("cp.async.commit_group;" ::: "memory");

    asm volatile("cp.async.wait_group 1;" ::: "memory");   // Q,K ready
    __syncthreads();

    // ---- scores = Q K^T ----
    float acc[4][8][4];
#pragma unroll
    for (int mi = 0; mi < 4; mi++)
#pragma unroll
        for (int ni = 0; ni < 8; ni++)
#pragma unroll
            for (int q = 0; q < 4; q++) acc[mi][ni][q] = 0.f;

#pragma unroll
    for (int ks = 0; ks < 4; ks++) {
        u32 arg[4][4];
#pragma unroll
        for (int mi = 0; mi < 4; mi++) {
            int row = mi * 16 + (lane & 15);
            u32 off = swz((u32)(row * 128 + (ks * 16 + (lane >> 4) * 8) * 2));
            ldsm4(arg[mi][0], arg[mi][1], arg[mi][2], arg[mi][3], sb + off);
        }
        u32 brg[8][2];
#pragma unroll
        for (int nj = 0; nj < 4; nj++) {
            int nrow = wid * 64 + nj * 16 + (lane & 7) + ((lane >> 4) << 3);
            u32 off = swz((u32)(nrow * 128 + (ks * 16 + ((lane >> 3) & 1) * 8) * 2));
            u32 r0, r1, r2, r3;
            ldsm4(r0, r1, r2, r3, sb + ATT_KP + off);
            brg[2 * nj][0] = r0; brg[2 * nj][1] = r1;
            brg[2 * nj + 1][0] = r2; brg[2 * nj + 1][1] = r3;
        }
#pragma unroll
        for (int mi = 0; mi < 4; mi++)
#pragma unroll
            for (int ni = 0; ni < 8; ni++)
                mma16816h(acc[mi][ni], arg[mi], brg[ni]);
    }
    __syncthreads();   // all warps done reading K (P will overwrite)

    // ---- scale + mask ----
    float mk[8][2];
#pragma unroll
    for (int ni = 0; ni < 8; ni++) {
        int c = wid * 64 + ni * 8 + tg * 2;
        mk[ni][0] = (tok[b * Sn + c]     == 0) ? -10000.f : 0.f;
        mk[ni][1] = (tok[b * Sn + c + 1] == 0) ? -10000.f : 0.f;
    }
#pragma unroll
    for (int mi = 0; mi < 4; mi++)
#pragma unroll
        for (int ni = 0; ni < 8; ni++)
#pragma unroll
            for (int q = 0; q < 4; q++)
                acc[mi][ni][q] = acc[mi][ni][q] * 0.125f + mk[ni][q & 1];

    float* red = (float*)(smem + ATT_RED);
    float rmax[8], rsum[8];

#pragma unroll
    for (int mi = 0; mi < 4; mi++)
#pragma unroll
        for (int half = 0; half < 2; half++) {
            float mx = -1e30f;
#pragma unroll
            for (int ni = 0; ni < 8; ni++)
                mx = fmaxf(mx, fmaxf(acc[mi][ni][half * 2], acc[mi][ni][half * 2 + 1]));
            mx = fmaxf(mx, __shfl_xor_sync(0xffffffffu, mx, 1));
            mx = fmaxf(mx, __shfl_xor_sync(0xffffffffu, mx, 2));
            int row = mi * 16 + half * 8 + g;
            if (tg == 0) red[row * 8 + wid] = mx;
        }
    __syncthreads();
#pragma unroll
    for (int mi = 0; mi < 4; mi++)
#pragma unroll
        for (int half = 0; half < 2; half++) {
            int row = mi * 16 + half * 8 + g;
            float m = -1e30f;
#pragma unroll
            for (int w = 0; w < 8; w++) m = fmaxf(m, red[row * 8 + w]);
            rmax[mi * 2 + half] = m;
        }
    __syncthreads();

#pragma unroll
    for (int mi = 0; mi < 4; mi++)
#pragma unroll
        for (int half = 0; half < 2; half++) {
            float s = 0.f;
#pragma unroll
            for (int ni = 0; ni < 8; ni++) {
                float e0 = __expf(acc[mi][ni][half * 2]     - rmax[mi * 2 + half]);
                float e1 = __expf(acc[mi][ni][half * 2 + 1] - rmax[mi * 2 + half]);
                acc[mi][ni][half * 2] = e0; acc[mi][ni][half * 2 + 1] = e1;
                s += e0 + e1;
            }
            s += __shfl_xor_sync(0xffffffffu, s, 1);
            s += __shfl_xor_sync(0xffffffffu, s, 2);
            int row = mi * 16 + half * 8 + g;
            if (tg == 0) red[row * 8 + wid] = s;
        }
    __syncthreads();
#pragma unroll
    for (int mi = 0; mi < 4; mi++)
#pragma unroll
        for (int half = 0; half < 2; half++) {
            int row = mi * 16 + half * 8 + g;
            float s = 0.f;
#pragma unroll
            for (int w = 0; w < 8; w++) s += red[row * 8 + w];
            rsum[mi * 2 + half] = 1.f / s;
        }

    // ---- write attn fp32 + P fp16 into smem (8 slabs 64x64 over K) ----
#pragma unroll
    for (int mi = 0; mi < 4; mi++)
#pragma unroll
        for (int half = 0; half < 2; half++) {
            int row = mi * 16 + half * 8 + g;
            size_t rbase = (size_t)zbh * Sn * Sn + (size_t)(m0 + row) * Sn;
            float inv = rsum[mi * 2 + half];
#pragma unroll
            for (int ni = 0; ni < 8; ni++) {
                int col = ni * 8 + tg * 2;
                float p0 = acc[mi][ni][half * 2]     * inv;
                float p1 = acc[mi][ni][half * 2 + 1] * inv;
                *(float2*)(attn + rbase + wid * 64 + col) = make_float2(p0, p1);
                u32 off = (u32)(wid * 8192) + swz((u32)(row * 128 + col * 2));
                *(u32*)(smem + ATT_KP + off) = packh2(p0, p1);
            }
        }

    asm volatile("cp.async.wait_group 0;" ::: "memory");   // V ready
    __syncthreads();                                        // P visible

    // ---- ctx = P @ V (V via trans-ldmatrix) ----
    const int wm = wid >> 2, wn = wid & 3;
    float acc2[2][2][4];
#pragma unroll
    for (int mi = 0; mi < 2; mi++)
#pragma unroll
        for (int ni = 0; ni < 2; ni++)
#pragma unroll
            for (int q = 0; q < 4; q++) acc2[mi][ni][q] = 0.f;

#pragma unroll 2
    for (int sl = 0; sl < 8; sl++) {
#pragma unroll
        for (int ks = 0; ks < 4; ks++) {
            u32 ar[2][4];
#pragma unroll
            for (int mi = 0; mi < 2; mi++) {
                int row = wm * 32 + mi * 16 + (lane & 15);
                u32 aoff = (u32)(sl * 8192) + swz((u32)(row * 128 + (ks * 16 + (lane >> 4) * 8) * 2));
                ldsm4(ar[mi][0], ar[mi][1], ar[mi][2], ar[mi][3], sb + ATT_KP + aoff);
            }
            int srow = sl * 64 + ks * 16 + (lane & 7) + ((lane >> 3) & 1) * 8;
            int dcol = wn * 16 + ((lane >> 4) << 3);
            u32 boff = swz((u32)(srow * 128 + dcol * 2));
            u32 br[2][2], r0, r1, r2, r3;
            ldsm4t(r0, r1, r2, r3, sb + ATT_V + boff);
            br[0][0] = r0; br[0][1] = r1; br[1][0] = r2; br[1][1] = r3;
#pragma unroll
            for (int mi = 0; mi < 2; mi++)
#pragma unroll
                for (int ni = 0; ni < 2; ni++)
                    mma16816h(acc2[mi][ni], ar[mi], br[ni]);
        }
    }

#pragma unroll
    for (int mi = 0; mi < 2; mi++)
#pragma unroll
        for (int half = 0; half < 2; half++) {
            int row = m0 + wm * 32 + mi * 16 + half * 8 + g;
#pragma unroll
            for (int ni = 0; ni < 2; ni++) {
                int col = wn * 16 + ni * 8 + tg * 2;
                size_t off = (size_t)(b * Sn + row) * Hn + h * 64 + col;
                *(u32*)(ct + off) = packh2(acc2[mi][ni][half * 2], acc2[mi][ni][half * 2 + 1]);
            }
        }
}

// ==================================================================
// weight convert+transpose: fp32 [K,N] -> fp16 [N,K], 32k x 128n tiles,
// float4 loads, half2 stores. dst/base resolved per family.
// ==================================================================
__global__ void __launch_bounds__(256)
wconv(const float* __restrict__ src0, __half* __restrict__ dst0,
      int K, int N, long in_l, long out_l)
{
    __shared__ float t[32][132];
    const float* src = src0 + (size_t)blockIdx.z * in_l;
    __half* dst = dst0 + (size_t)blockIdx.z * out_l;
    const int n0 = blockIdx.x * 128, k0 = blockIdx.y * 32;
    const int tid = threadIdx.x;

#pragma unroll
    for (int i = 0; i < 4; i++) {
        int idx = tid + i * 256;
        int r = idx >> 5, c = (idx & 31) << 2;
        float4 v = *(const float4*)(src + (size_t)(k0 + r) * N + n0 + c);
        t[r][c] = v.x; t[r][c + 1] = v.y; t[r][c + 2] = v.z; t[r][c + 3] = v.w;
    }
    __syncthreads();
#pragma unroll
    for (int i = 0; i < 4; i++) {
        int idx = tid + i * 256;
        int n = idx >> 3, ks = (idx & 7) << 2;
        u32 p0 = packh2(t[ks][n],     t[ks + 1][n]);
        u32 p1 = packh2(t[ks + 2][n], t[ks + 3][n]);
        size_t off = (size_t)(n0 + n) * K + k0 + ks;
        *(u32*)(dst + off)     = p0;
        *(u32*)(dst + off + 2) = p1;
    }
}

// merged variant for the 4 HxH weights (wq,wk,wv packed + wo)
__global__ void __launch_bounds__(256)
wconv4(const float* __restrict__ wq, const float* __restrict__ wk,
       const float* __restrict__ wv, const float* __restrict__ wo,
       __half* __restrict__ oqkv, __half* __restrict__ owo)
{
    __shared__ float t[32][132];
    int z = blockIdx.z, l = z >> 2, which = z & 3;
    const float* src = (which == 0 ? wq : which == 1 ? wk : which == 2 ? wv : wo)
                       + (size_t)l * Hn * Hn;
    __half* dst;
    size_t obase;
    if (which < 3) { dst = oqkv; obase = (size_t)l * QKVN * Hn + (size_t)which * 768 * Hn; }
    else           { dst = owo;  obase = (size_t)l * Hn * Hn; }
    const int n0 = blockIdx.x * 128, k0 = blockIdx.y * 32;
    const int tid = threadIdx.x;

#pragma unroll
    for (int i = 0; i < 4; i++) {
        int idx = tid + i * 256;
        int r = idx >> 5, c = (idx & 31) << 2;
        float4 v = *(const float4*)(src + (size_t)(k0 + r) * Hn + n0 + c);
        t[r][c] = v.x; t[r][c + 1] = v.y; t[r][c + 2] = v.z; t[r][c + 3] = v.w;
    }
    __syncthreads();
#pragma unroll
    for (int i = 0; i < 4; i++) {
        int idx = tid + i * 256;
        int n = idx >> 3, ks = (idx & 7) << 2;
        u32 p0 = packh2(t[ks][n],     t[ks + 1][n]);
        u32 p1 = packh2(t[ks + 2][n], t[ks + 3][n]);
        size_t off = obase + (size_t)(n0 + n) * Hn + k0 + ks;
        *(u32*)(dst + off)     = p0;
        *(u32*)(dst + off + 2) = p1;
    }
}

__global__ void biaspack(const float* __restrict__ bq, const float* __restrict__ bk,
                         const float* __restrict__ bv, float* __restrict__ o) {
    int i = blockIdx.x * 256 + threadIdx.x;
    if (i >= Ln * QKVN) return;
    int l = i / QKVN, n = i - l * QKVN;
    float v = (n < 768) ? bq[l * Hn + n] : (n < 1536) ? bk[l * Hn + n - 768] : bv[l * Hn + n - 1536];
    o[i] = v;
}

__global__ void embed_kernel(const int* __restrict__ tok, const float* __restrict__ emb,
                             const float* __restrict__ pos, float* __restrict__ x,
                             __half* __restrict__ xf) {
    int row = blockIdx.x;
    int t = tok[row];
    const float* e = emb + (size_t)t * Hn;
    const float* p = pos + (size_t)(row % Sn) * Hn;
    size_t base = (size_t)row * Hn;
    for (int c = threadIdx.x; c < Hn; c += blockDim.x) {
        float v = e[c] + p[c];
        x[base + c] = v;
        xf[base + c] = __float2half(v);
    }
}

// ==================================================================
// warp-per-row layernorm: 256 thr = 8 rows/CTA, no block syncs.
// ==================================================================
__global__ void __launch_bounds__(256)
layernorm_w(const float* __restrict__ in, const float* __restrict__ g,
            const float* __restrict__ be, float* __restrict__ out,
            __half* __restrict__ of) {
    const int row = blockIdx.x * 8 + (threadIdx.x >> 5);
    const int lane = threadIdx.x & 31;
    const float* p = in + (size_t)row * Hn;

    float4 v[6];
    float s = 0.f, sq = 0.f;
#pragma unroll
    for (int i = 0; i < 6; i++) {
        v[i] = *(const float4*)(p + i * 128 + lane * 4);
        s  += v[i].x + v[i].y + v[i].z + v[i].w;
        sq += v[i].x * v[i].x + v[i].y * v[i].y + v[i].z * v[i].z + v[i].w * v[i].w;
    }
#pragma unroll
    for (int o = 16; o; o >>= 1) {
        s  += __shfl_xor_sync(0xffffffffu, s, o);
        sq += __shfl_xor_sync(0xffffffffu, sq, o);
    }
    float m = s * (1.0f / Hn);
    float var = sq * (1.0f / Hn) - m * m;
    float inv = rsqrtf(var + 1e-12f);

    float* o32 = out + (size_t)row * Hn;
    __half* o16 = of + (size_t)row * Hn;
#pragma unroll
    for (int i = 0; i < 6; i++) {
        int idx = i * 128 + lane * 4;
        float4 gg = *(const float4*)(g + idx);
        float4 bb = *(const float4*)(be + idx);
        float4 r;
        r.x = (v[i].x - m) * inv * gg.x + bb.x;
        r.y = (v[i].y - m) * inv * gg.y + bb.y;
        r.z = (v[i].z - m) * inv * gg.z + bb.z;
        r.w = (v[i].w - m) * inv * gg.w + bb.w;
        *(float4*)(o32 + idx) = r;
        u32 h0 = packh2(r.x, r.y), h1 = packh2(r.z, r.w);
        *(u32*)(o16 + idx)     = h0;
        *(u32*)(o16 + idx + 2) = h1;
    }
}

// ==================================================================
#define SMEM_G1A (3 * (64*128 + 128*128))        // 73728  (MT=64,NT=128)
#define SMEM_G1B (3 * (128*128 + 128*128))       // 98304  (MT=128,NT=128)

extern "C" void kernel_launch(void* const* d_in, const int* in_sizes, int n_in,
                              void* d_out, int out_size) {
    const int*   tok = (const int*)d_in[0];
    const float* emb = (const float*)d_in[1];
    const float* pos = (const float*)d_in[2];
    const float* wq  = (const float*)d_in[3];
    const float* bq  = (const float*)d_in[4];
    const float* wk  = (const float*)d_in[5];
    const float* bk  = (const float*)d_in[6];
    const float* wv  = (const float*)d_in[7];
    const float* bv  = (const float*)d_in[8];
    const float* wo  = (const float*)d_in[9];
    const float* bo  = (const float*)d_in[10];
    const float* g1  = (const float*)d_in[11];
    const float* be1 = (const float*)d_in[12];
    const float* w1  = (const float*)d_in[13];
    const float* b1  = (const float*)d_in[14];
    const float* w2  = (const float*)d_in[15];
    const float* b2  = (const float*)d_in[16];
    const float* g2  = (const float*)d_in[17];
    const float* be2 = (const float*)d_in[18];

    float* out      = (float*)d_out;
    float* attn_out = out + (size_t)MR * Hn;

    float *x, *y, *bqkv;
    __half *wqkv16, *wo16, *w116, *w216, *xf, *qkv16, *ct, *f16;
    cudaGetSymbolAddress((void**)&x, g_x);      cudaGetSymbolAddress((void**)&y, g_y);
    cudaGetSymbolAddress((void**)&bqkv, g_bqkv);
    cudaGetSymbolAddress((void**)&wqkv16, g_wqkv16);
    cudaGetSymbolAddress((void**)&wo16, g_wo16);
    cudaGetSymbolAddress((void**)&w116, g_w116);
    cudaGetSymbolAddress((void**)&w216, g_w216);
    cudaGetSymbolAddress((void**)&xf, g_xf);
    cudaGetSymbolAddress((void**)&qkv16, g_qkv16);
    cudaGetSymbolAddress((void**)&ct, g_ct16);
    cudaGetSymbolAddress((void**)&f16, g_f16);

    cudaFuncSetAttribute(gemm1<128,128,0>, cudaFuncAttributeMaxDynamicSharedMemorySize, SMEM_G1B);
    cudaFuncSetAttribute(gemm1<64,128,3>,  cudaFuncAttributeMaxDynamicSharedMemorySize, SMEM_G1A);
    cudaFuncSetAttribute(gemm1<128,128,4>, cudaFuncAttributeMaxDynamicSharedMemorySize, SMEM_G1B);
    cudaFuncSetAttribute(attn_fused, cudaFuncAttributeMaxDynamicSharedMemorySize, SMEM_ATT);

    // prologue
    wconv4<<<dim3(Hn/128, Hn/32, 4*Ln), 256>>>(wq, wk, wv, wo, wqkv16, wo16);
    wconv<<<dim3(Fn/128, Hn/32, Ln), 256>>>(w1, w116, Hn, Fn, (long)Hn*Fn, (long)Hn*Fn);
    wconv<<<dim3(Hn/128, Fn/32, Ln), 256>>>(w2, w216, Fn, Hn, (long)Fn*Hn, (long)Fn*Hn);
    biaspack<<<(Ln*QKVN + 255)/256, 256>>>(bq, bk, bv, bqkv);
    embed_kernel<<<MR, 256>>>(tok, emb, pos, x, xf);

    for (int l = 0; l < Ln; l++) {
        float* attnL = attn_out + (size_t)l * BH * Sn * Sn;

        // fused QKV projection (fp16)
        gemm1<128,128,0><<<dim3(QKVN/128, MR/128), 512, SMEM_G1B>>>(
            xf, Hn, wqkv16 + (size_t)l * QKVN * Hn, Hn, nullptr, qkv16, QKVN,
            bqkv + (size_t)l * QKVN, nullptr, Hn);

        // scores + softmax + P@V (all fp16)
        attn_fused<<<dim3(Sn/64, BH), 256, SMEM_ATT>>>(qkv16, tok, attnL, ct);

        // Wo + resid
        gemm1<64,128,3><<<dim3(Hn/128, MR/64), 512, SMEM_G1A>>>(
            ct, Hn, wo16 + (size_t)l * Hn * Hn, Hn, y, nullptr, Hn,
            bo + (size_t)l * Hn, x, Hn);
        layernorm_w<<<MR/8, 256>>>(y, g1 + (size_t)l * Hn, be1 + (size_t)l * Hn, x, xf);

        // FFN1 (relu)
        gemm1<128,128,4><<<dim3(Fn/128, MR/128), 512, SMEM_G1B>>>(
            xf, Hn, w116 + (size_t)l * Hn * Fn, Hn, nullptr, f16, Fn,
            b1 + (size_t)l * Fn, nullptr, Hn);

        // FFN2 + resid
        gemm1<64,128,3><<<dim3(Hn/128, MR/64), 512, SMEM_G1A>>>(
            f16, Fn, w216 + (size_t)l * Fn * Hn, Fn, y, nullptr, Hn,
            b2 + (size_t)l * Hn, x, Fn);
        layernorm_w<<<MR/8, 256>>>(y, g2 + (size_t)l * Hn, be2 + (size_t)l * Hn, x, xf);
    }

    cudaMemcpyAsync(out, x, (size_t)MR * Hn * sizeof(float), cudaMemcpyDeviceToDevice);
}

// round 9
// speedup vs baseline: 8.0948x; 1.0116x over previous
#include <cuda_runtime.h>
#include <cuda_bf16.h>
#include <cuda_fp16.h>

typedef unsigned int u32;
typedef unsigned long long u64;

#define Bn 4
#define Sn 512
#define Hn 768
#define NHn 12
#define Fn 3072
#define Ln 6
#define MR (Bn*Sn)          // 2048
#define QKVN 2304
#define BH (Bn*NHn)         // 48

// ---------------- scratch (device globals) ----------------
__device__ __half g_wqkv16[(size_t)Ln*QKVN*Hn];  // [l][n=2304][k=768]
__device__ __half g_wo16[(size_t)Ln*Hn*Hn];
__device__ __half g_w116[(size_t)Ln*Hn*Fn];
__device__ __half g_w216[(size_t)Ln*Fn*Hn];
__device__ float g_x[MR*Hn];
__device__ float g_y[MR*Hn];
__device__ float g_bqkv[Ln*QKVN];
__device__ __half g_xf[MR*Hn];
__device__ __half g_qkv16[(size_t)MR*QKVN];
__device__ __half g_ct16[MR*Hn];
__device__ __half g_f16[(size_t)MR*Fn];

// ---------------- helpers ----------------
__device__ __forceinline__ u32 s2u(const void* p) {
    u32 a;
    asm("{ .reg .u64 t; cvta.to.shared.u64 t, %1; cvt.u32.u64 %0, t; }" : "=r"(a) : "l"(p));
    return a;
}
__device__ __forceinline__ u32 swz(u32 o) { return o ^ ((o >> 3) & 0x70); }

__device__ __forceinline__ void cpasync16(u32 dst, const void* src) {
    asm volatile("cp.async.cg.shared.global [%0], [%1], 16;" :: "r"(dst), "l"(src) : "memory");
}
__device__ __forceinline__ void ldsm4(u32& r0, u32& r1, u32& r2, u32& r3, u32 a) {
    asm volatile("ldmatrix.sync.aligned.m8n8.x4.shared.b16 {%0,%1,%2,%3}, [%4];"
                 : "=r"(r0), "=r"(r1), "=r"(r2), "=r"(r3) : "r"(a));
}
__device__ __forceinline__ void ldsm4t(u32& r0, u32& r1, u32& r2, u32& r3, u32 a) {
    asm volatile("ldmatrix.sync.aligned.m8n8.x4.trans.shared.b16 {%0,%1,%2,%3}, [%4];"
                 : "=r"(r0), "=r"(r1), "=r"(r2), "=r"(r3) : "r"(a));
}
__device__ __forceinline__ void mma16816h(float* c, const u32* a, const u32* b) {
    asm volatile("mma.sync.aligned.m16n8k16.row.col.f32.f16.f16.f32 "
                 "{%0,%1,%2,%3}, {%4,%5,%6,%7}, {%8,%9}, {%0,%1,%2,%3};"
                 : "+f"(c[0]), "+f"(c[1]), "+f"(c[2]), "+f"(c[3])
                 : "r"(a[0]), "r"(a[1]), "r"(a[2]), "r"(a[3]), "r"(b[0]), "r"(b[1]));
}
__device__ __forceinline__ u32 packh2(float v0, float v1) {
    __half2 h = __floats2half2_rn(v0, v1);
    return *reinterpret_cast<u32*>(&h);
}

// ==================================================================
// fp16 single-pass GEMM. MT x NT, BK=64, 512 threads (16 warps 4x4).
// EPI: 0=bias->fp16  3=bias+resid->f32  4=bias+relu->fp16
// ==================================================================
template<int MT, int NT, int EPI>
__global__ void __launch_bounds__(512)
gemm1(const __half* __restrict__ A, int lda, const __half* __restrict__ B, int ldb,
      float* __restrict__ Cf, __half* __restrict__ Ch, int ldc,
      const float* __restrict__ bias, const float* __restrict__ resid, int K)
{
    constexpr int WM = MT / 4, WN = NT / 4;
    constexpr int MI = WM / 16, NI = WN / 8;
    constexpr u32 ASZ = (u32)MT * 128u, BSZ = (u32)NT * 128u;
    constexpr u32 STG = ASZ + BSZ;

    extern __shared__ char smem[];
    const u32 sb = s2u(smem);
    const int tid = threadIdx.x, wid = tid >> 5, lane = tid & 31;
    const int warp_m = wid >> 2, warp_n = wid & 3;
    const int m0 = blockIdx.y * MT, n0 = blockIdx.x * NT;
    const int nsl = K >> 6;

    float acc[MI][NI][4];
#pragma unroll
    for (int mi = 0; mi < MI; mi++)
#pragma unroll
        for (int ni = 0; ni < NI; ni++)
#pragma unroll
            for (int q = 0; q < 4; q++) acc[mi][ni][q] = 0.f;

    auto prefetch = [&](int sl) {
        const u32 base = sb + (u32)(sl % 3) * STG;
#pragma unroll
        for (int i = 0; i < MT * 8 / 512; i++) {
            int u = tid + i * 512;
            int r = u >> 3, c = u & 7;
            cpasync16(base + swz((u32)(r * 128 + c * 16)),
                      A + (size_t)(m0 + r) * lda + sl * 64 + c * 8);
        }
#pragma unroll
        for (int i = 0; i < NT * 8 / 512; i++) {
            int u = tid + i * 512;
            int r = u >> 3, c = u & 7;
            cpasync16(base + ASZ + swz((u32)(r * 128 + c * 16)),
                      B + (size_t)(n0 + r) * ldb + sl * 64 + c * 8);
        }
        asm volatile("cp.async.commit_group;" ::: "memory");
    };

    prefetch(0); prefetch(1);

    for (int it = 0; it < nsl; it++) {
        if (it < nsl - 1) asm volatile("cp.async.wait_group 1;" ::: "memory");
        else              asm volatile("cp.async.wait_group 0;" ::: "memory");
        __syncthreads();
        if (it + 2 < nsl) prefetch(it + 2);

        const u32 ab = sb + (u32)(it % 3) * STG;
        const u32 bb = ab + ASZ;

#pragma unroll
        for (int ks = 0; ks < 4; ks++) {
            u32 ar[MI][4];
#pragma unroll
            for (int mi = 0; mi < MI; mi++) {
                int row = warp_m * WM + mi * 16 + (lane & 15);
                u32 off = swz((u32)(row * 128 + (ks * 16 + (lane >> 4) * 8) * 2));
                ldsm4(ar[mi][0], ar[mi][1], ar[mi][2], ar[mi][3], ab + off);
            }
            u32 br[NI][2];
#pragma unroll
            for (int nj = 0; nj < NI / 2; nj++) {
                int nrow = warp_n * WN + nj * 16 + (lane & 7) + ((lane >> 4) << 3);
                u32 off = swz((u32)(nrow * 128 + (ks * 16 + ((lane >> 3) & 1) * 8) * 2));
                u32 r0, r1, r2, r3;
                ldsm4(r0, r1, r2, r3, bb + off);
                br[2 * nj][0] = r0; br[2 * nj][1] = r1;
                br[2 * nj + 1][0] = r2; br[2 * nj + 1][1] = r3;
            }
#pragma unroll
            for (int mi = 0; mi < MI; mi++)
#pragma unroll
                for (int ni = 0; ni < NI; ni++)
                    mma16816h(acc[mi][ni], ar[mi], br[ni]);
        }
    }

    const int tg = lane & 3, g = lane >> 2;
#pragma unroll
    for (int mi = 0; mi < MI; mi++)
#pragma unroll
        for (int half = 0; half < 2; half++) {
            const int mrow = m0 + warp_m * WM + mi * 16 + half * 8 + g;
#pragma unroll
            for (int ni = 0; ni < NI; ni++) {
                const int col = n0 + warp_n * WN + ni * 8 + tg * 2;
                float v0 = acc[mi][ni][half * 2]     + bias[col];
                float v1 = acc[mi][ni][half * 2 + 1] + bias[col + 1];
                size_t off = (size_t)mrow * ldc + col;
                if (EPI == 3) {
                    float2 rv = *(const float2*)(resid + off);
                    *(float2*)(Cf + off) = make_float2(v0 + rv.x, v1 + rv.y);
                } else if (EPI == 4) {
                    v0 = fmaxf(v0, 0.f); v1 = fmaxf(v1, 0.f);
                    *(u32*)(Ch + off) = packh2(v0, v1);
                } else {
                    *(u32*)(Ch + off) = packh2(v0, v1);
                }
            }
        }
}

// ==================================================================
// Fused attention (all fp16): scores + softmax + P@V. 64 q-rows/(b,h).
// No max-subtraction in softmax (logits are small; masked underflow to 0).
// smem: Q[0,8K)  K[8K,72K)->P  V[72K,136K)  red[136K..]
// ==================================================================
#define ATT_KP   8192u
#define ATT_V    73728u
#define ATT_RED  139264
#define SMEM_ATT (ATT_RED + 2048)

__global__ void __launch_bounds__(256)
attn_fused(const __half* __restrict__ qkv, const int* __restrict__ tok,
           float* __restrict__ attn, __half* __restrict__ ct)
{
    extern __shared__ char smem[];
    const u32 sb = s2u(smem);
    const int tid = threadIdx.x, wid = tid >> 5, lane = tid & 31;
    const int g = lane >> 2, tg = lane & 3;
    const int m0 = blockIdx.x * 64;
    const int zbh = blockIdx.y;
    const int b = zbh / NHn, h = zbh - b * NHn;

    const __half* Q_src = qkv + (size_t)(b * Sn + m0) * QKVN + h * 64;
    const __half* K_src = qkv + (size_t)(b * Sn) * QKVN + 768 + h * 64;
    const __half* V_src = qkv + (size_t)(b * Sn) * QKVN + 1536 + h * 64;

    for (int u = tid; u < 512; u += 256) {
        int r = u >> 3, c = u & 7;
        cpasync16(sb + swz((u32)(r * 128 + c * 16)), Q_src + (size_t)r * QKVN + c * 8);
    }
    for (int u = tid; u < 4096; u += 256) {
        int r = u >> 3, c = u & 7;
        cpasync16(sb + ATT_KP + swz((u32)(r * 128 + c * 16)), K_src + (size_t)r * QKVN + c * 8);
    }
    asm volatile("cp.async.commit_group;" ::: "memory");
    for (int u = tid; u < 4096; u += 256) {
        int r = u >> 3, c = u & 7;
        cpasync16(sb + ATT_V + swz((u32)(r * 128 + c * 16)), V_src + (size_t)r * QKVN + c * 8);
    }
    asm volatile("cp.async.commit_group;" ::: "memory");

    asm volatile("cp.async.wait_group 1;" ::: "memory");   // Q,K ready
    __syncthreads();

    // ---- scores = Q K^T ----
    float acc[4][8][4];
#pragma unroll
    for (int mi = 0; mi < 4; mi++)
#pragma unroll
        for (int ni = 0; ni < 8; ni++)
#pragma unroll
            for (int q = 0; q < 4; q++) acc[mi][ni][q] = 0.f;

#pragma unroll
    for (int ks = 0; ks < 4; ks++) {
        u32 arg[4][4];
#pragma unroll
        for (int mi = 0; mi < 4; mi++) {
            int row = mi * 16 + (lane & 15);
            u32 off = swz((u32)(row * 128 + (ks * 16 + (lane >> 4) * 8) * 2));
            ldsm4(arg[mi][0], arg[mi][1], arg[mi][2], arg[mi][3], sb + off);
        }
        u32 brg[8][2];
#pragma unroll
        for (int nj = 0; nj < 4; nj++) {
            int nrow = wid * 64 + nj * 16 + (lane & 7) + ((lane >> 4) << 3);
            u32 off = swz((u32)(nrow * 128 + (ks * 16 + ((lane >> 3) & 1) * 8) * 2));
            u32 r0, r1, r2, r3;
            ldsm4(r0, r1, r2, r3, sb + ATT_KP + off);
            brg[2 * nj][0] = r0; brg[2 * nj][1] = r1;
            brg[2 * nj + 1][0] = r2; brg[2 * nj + 1][1] = r3;
        }
#pragma unroll
        for (int mi = 0; mi < 4; mi++)
#pragma unroll
            for (int ni = 0; ni < 8; ni++)
                mma16816h(acc[mi][ni], arg[mi], brg[ni]);
    }
    __syncthreads();   // all warps done reading K (P will overwrite)

    // ---- scale + mask + exp (no max-sub; logits tiny, mask underflows) ----
    float mk[8][2];
#pragma unroll
    for (int ni = 0; ni < 8; ni++) {
        int c = wid * 64 + ni * 8 + tg * 2;
        mk[ni][0] = (tok[b * Sn + c]     == 0) ? -10000.f : 0.f;
        mk[ni][1] = (tok[b * Sn + c + 1] == 0) ? -10000.f : 0.f;
    }

    float* red = (float*)(smem + ATT_RED);
    float rsum[8];

#pragma unroll
    for (int mi = 0; mi < 4; mi++)
#pragma unroll
        for (int half = 0; half < 2; half++) {
            float s = 0.f;
#pragma unroll
            for (int ni = 0; ni < 8; ni++) {
                float e0 = __expf(acc[mi][ni][half * 2]     * 0.125f + mk[ni][0]);
                float e1 = __expf(acc[mi][ni][half * 2 + 1] * 0.125f + mk[ni][1]);
                acc[mi][ni][half * 2] = e0; acc[mi][ni][half * 2 + 1] = e1;
                s += e0 + e1;
            }
            s += __shfl_xor_sync(0xffffffffu, s, 1);
            s += __shfl_xor_sync(0xffffffffu, s, 2);
            int row = mi * 16 + half * 8 + g;
            if (tg == 0) red[row * 8 + wid] = s;
        }
    __syncthreads();
#pragma unroll
    for (int mi = 0; mi < 4; mi++)
#pragma unroll
        for (int half = 0; half < 2; half++) {
            int row = mi * 16 + half * 8 + g;
            float s = 0.f;
#pragma unroll
            for (int w = 0; w < 8; w++) s += red[row * 8 + w];
            rsum[mi * 2 + half] = 1.f / s;
        }

    // ---- write attn fp32 + P fp16 into smem (8 slabs 64x64 over K) ----
#pragma unroll
    for (int mi = 0; mi < 4; mi++)
#pragma unroll
        for (int half = 0; half < 2; half++) {
            int row = mi * 16 + half * 8 + g;
            size_t rbase = (size_t)zbh * Sn * Sn + (size_t)(m0 + row) * Sn;
            float inv = rsum[mi * 2 + half];
#pragma unroll
            for (int ni = 0; ni < 8; ni++) {
                int col = ni * 8 + tg * 2;
                float p0 = acc[mi][ni][half * 2]     * inv;
                float p1 = acc[mi][ni][half * 2 + 1] * inv;
                *(float2*)(attn + rbase + wid * 64 + col) = make_float2(p0, p1);
                u32 off = (u32)(wid * 8192) + swz((u32)(row * 128 + col * 2));
                *(u32*)(smem + ATT_KP + off) = packh2(p0, p1);
            }
        }

    asm volatile("cp.async.wait_group 0;" ::: "memory");   // V ready
    __syncthreads();                                        // P visible

    // ---- ctx = P @ V (V via trans-ldmatrix) ----
    const int wm = wid >> 2, wn = wid & 3;
    float acc2[2][2][4];
#pragma unroll
    for (int mi = 0; mi < 2; mi++)
#pragma unroll
        for (int ni = 0; ni < 2; ni++)
#pragma unroll
            for (int q = 0; q < 4; q++) acc2[mi][ni][q] = 0.f;

#pragma unroll 2
    for (int sl = 0; sl < 8; sl++) {
#pragma unroll
        for (int ks = 0; ks < 4; ks++) {
            u32 ar[2][4];
#pragma unroll
            for (int mi = 0; mi < 2; mi++) {
                int row = wm * 32 + mi * 16 + (lane & 15);
                u32 aoff = (u32)(sl * 8192) + swz((u32)(row * 128 + (ks * 16 + (lane >> 4) * 8) * 2));
                ldsm4(ar[mi][0], ar[mi][1], ar[mi][2], ar[mi][3], sb + ATT_KP + aoff);
            }
            int srow = sl * 64 + ks * 16 + (lane & 7) + ((lane >> 3) & 1) * 8;
            int dcol = wn * 16 + ((lane >> 4) << 3);
            u32 boff = swz((u32)(srow * 128 + dcol * 2));
            u32 br[2][2], r0, r1, r2, r3;
            ldsm4t(r0, r1, r2, r3, sb + ATT_V + boff);
            br[0][0] = r0; br[0][1] = r1; br[1][0] = r2; br[1][1] = r3;
#pragma unroll
            for (int mi = 0; mi < 2; mi++)
#pragma unroll
                for (int ni = 0; ni < 2; ni++)
                    mma16816h(acc2[mi][ni], ar[mi], br[ni]);
        }
    }

#pragma unroll
    for (int mi = 0; mi < 2; mi++)
#pragma unroll
        for (int half = 0; half < 2; half++) {
            int row = m0 + wm * 32 + mi * 16 + half * 8 + g;
#pragma unroll
            for (int ni = 0; ni < 2; ni++) {
                int col = wn * 16 + ni * 8 + tg * 2;
                size_t off = (size_t)(b * Sn + row) * Hn + h * 64 + col;
                *(u32*)(ct + off) = packh2(acc2[mi][ni][half * 2], acc2[mi][ni][half * 2 + 1]);
            }
        }
}

// ==================================================================
// weight convert+transpose: fp32 [K,N] -> fp16 [N,K], 32k x 128n tiles
// ==================================================================
__global__ void __launch_bounds__(256)
wconv(const float* __restrict__ src0, __half* __restrict__ dst0,
      int K, int N, long in_l, long out_l)
{
    __shared__ float t[32][132];
    const float* src = src0 + (size_t)blockIdx.z * in_l;
    __half* dst = dst0 + (size_t)blockIdx.z * out_l;
    const int n0 = blockIdx.x * 128, k0 = blockIdx.y * 32;
    const int tid = threadIdx.x;

#pragma unroll
    for (int i = 0; i < 4; i++) {
        int idx = tid + i * 256;
        int r = idx >> 5, c = (idx & 31) << 2;
        float4 v = *(const float4*)(src + (size_t)(k0 + r) * N + n0 + c);
        t[r][c] = v.x; t[r][c + 1] = v.y; t[r][c + 2] = v.z; t[r][c + 3] = v.w;
    }
    __syncthreads();
#pragma unroll
    for (int i = 0; i < 4; i++) {
        int idx = tid + i * 256;
        int n = idx >> 3, ks = (idx & 7) << 2;
        u32 p0 = packh2(t[ks][n],     t[ks + 1][n]);
        u32 p1 = packh2(t[ks + 2][n], t[ks + 3][n]);
        size_t off = (size_t)(n0 + n) * K + k0 + ks;
        *(u32*)(dst + off)     = p0;
        *(u32*)(dst + off + 2) = p1;
    }
}

// merged variant for the 4 HxH weights (wq,wk,wv packed + wo)
__global__ void __launch_bounds__(256)
wconv4(const float* __restrict__ wq, const float* __restrict__ wk,
       const float* __restrict__ wv, const float* __restrict__ wo,
       __half* __restrict__ oqkv, __half* __restrict__ owo)
{
    __shared__ float t[32][132];
    int z = blockIdx.z, l = z >> 2, which = z & 3;
    const float* src = (which == 0 ? wq : which == 1 ? wk : which == 2 ? wv : wo)
                       + (size_t)l * Hn * Hn;
    __half* dst;
    size_t obase;
    if (which < 3) { dst = oqkv; obase = (size_t)l * QKVN * Hn + (size_t)which * 768 * Hn; }
    else           { dst = owo;  obase = (size_t)l * Hn * Hn; }
    const int n0 = blockIdx.x * 128, k0 = blockIdx.y * 32;
    const int tid = threadIdx.x;

#pragma unroll
    for (int i = 0; i < 4; i++) {
        int idx = tid + i * 256;
        int r = idx >> 5, c = (idx & 31) << 2;
        float4 v = *(const float4*)(src + (size_t)(k0 + r) * Hn + n0 + c);
        t[r][c] = v.x; t[r][c + 1] = v.y; t[r][c + 2] = v.z; t[r][c + 3] = v.w;
    }
    __syncthreads();
#pragma unroll
    for (int i = 0; i < 4; i++) {
        int idx = tid + i * 256;
        int n = idx >> 3, ks = (idx & 7) << 2;
        u32 p0 = packh2(t[ks][n],     t[ks + 1][n]);
        u32 p1 = packh2(t[ks + 2][n], t[ks + 3][n]);
        size_t off = obase + (size_t)(n0 + n) * Hn + k0 + ks;
        *(u32*)(dst + off)     = p0;
        *(u32*)(dst + off + 2) = p1;
    }
}

// embed (blocks 0..MR-1) + biaspack (blocks MR..) merged
__global__ void embed_bias(const int* __restrict__ tok, const float* __restrict__ emb,
                           const float* __restrict__ pos, float* __restrict__ x,
                           __half* __restrict__ xf,
                           const float* __restrict__ bq, const float* __restrict__ bk,
                           const float* __restrict__ bv, float* __restrict__ obias) {
    if (blockIdx.x < MR) {
        int row = blockIdx.x;
        int t = tok[row];
        const float* e = emb + (size_t)t * Hn;
        const float* p = pos + (size_t)(row % Sn) * Hn;
        size_t base = (size_t)row * Hn;
        for (int c = threadIdx.x; c < Hn; c += blockDim.x) {
            float v = e[c] + p[c];
            x[base + c] = v;
            xf[base + c] = __float2half(v);
        }
    } else {
        int i = (blockIdx.x - MR) * 256 + threadIdx.x;
        if (i < Ln * QKVN) {
            int l = i / QKVN, n = i - l * QKVN;
            float v = (n < 768) ? bq[l * Hn + n]
                    : (n < 1536) ? bk[l * Hn + n - 768] : bv[l * Hn + n - 1536];
            obias[i] = v;
        }
    }
}

// ==================================================================
// warp-per-row layernorm: 256 thr = 8 rows/CTA, no block syncs.
// ==================================================================
__global__ void __launch_bounds__(256)
layernorm_w(const float* __restrict__ in, const float* __restrict__ g,
            const float* __restrict__ be, float* __restrict__ out,
            __half* __restrict__ of) {
    const int row = blockIdx.x * 8 + (threadIdx.x >> 5);
    const int lane = threadIdx.x & 31;
    const float* p = in + (size_t)row * Hn;

    float4 v[6];
    float s = 0.f, sq = 0.f;
#pragma unroll
    for (int i = 0; i < 6; i++) {
        v[i] = *(const float4*)(p + i * 128 + lane * 4);
        s  += v[i].x + v[i].y + v[i].z + v[i].w;
        sq += v[i].x * v[i].x + v[i].y * v[i].y + v[i].z * v[i].z + v[i].w * v[i].w;
    }
#pragma unroll
    for (int o = 16; o; o >>= 1) {
        s  += __shfl_xor_sync(0xffffffffu, s, o);
        sq += __shfl_xor_sync(0xffffffffu, sq, o);
    }
    float m = s * (1.0f / Hn);
    float var = sq * (1.0f / Hn) - m * m;
    float inv = rsqrtf(var + 1e-12f);

    float* o32 = out + (size_t)row * Hn;
    __half* o16 = of + (size_t)row * Hn;
#pragma unroll
    for (int i = 0; i < 6; i++) {
        int idx = i * 128 + lane * 4;
        float4 gg = *(const float4*)(g + idx);
        float4 bb = *(const float4*)(be + idx);
        float4 r;
        r.x = (v[i].x - m) * inv * gg.x + bb.x;
        r.y = (v[i].y - m) * inv * gg.y + bb.y;
        r.z = (v[i].z - m) * inv * gg.z + bb.z;
        r.w = (v[i].w - m) * inv * gg.w + bb.w;
        *(float4*)(o32 + idx) = r;
        u32 h0 = packh2(r.x, r.y), h1 = packh2(r.z, r.w);
        *(u32*)(o16 + idx)     = h0;
        *(u32*)(o16 + idx + 2) = h1;
    }
}

// ==================================================================
#define SMEM_G1B (3 * (128*128 + 128*128))       // 98304  (MT=128,NT=128)
#define SMEM_G1C (3 * (64*128  + 64*128))        // 49152  (MT=64, NT=64)

extern "C" void kernel_launch(void* const* d_in, const int* in_sizes, int n_in,
                              void* d_out, int out_size) {
    const int*   tok = (const int*)d_in[0];
    const float* emb = (const float*)d_in[1];
    const float* pos = (const float*)d_in[2];
    const float* wq  = (const float*)d_in[3];
    const float* bq  = (const float*)d_in[4];
    const float* wk  = (const float*)d_in[5];
    const float* bk  = (const float*)d_in[6];
    const float* wv  = (const float*)d_in[7];
    const float* bv  = (const float*)d_in[8];
    const float* wo  = (const float*)d_in[9];
    const float* bo  = (const float*)d_in[10];
    const float* g1  = (const float*)d_in[11];
    const float* be1 = (const float*)d_in[12];
    const float* w1  = (const float*)d_in[13];
    const float* b1  = (const float*)d_in[14];
    const float* w2  = (const float*)d_in[15];
    const float* b2  = (const float*)d_in[16];
    const float* g2  = (const float*)d_in[17];
    const float* be2 = (const float*)d_in[18];

    float* out      = (float*)d_out;
    float* attn_out = out + (size_t)MR * Hn;

    float *x, *y, *bqkv;
    __half *wqkv16, *wo16, *w116, *w216, *xf, *qkv16, *ct, *f16;
    cudaGetSymbolAddress((void**)&x, g_x);      cudaGetSymbolAddress((void**)&y, g_y);
    cudaGetSymbolAddress((void**)&bqkv, g_bqkv);
    cudaGetSymbolAddress((void**)&wqkv16, g_wqkv16);
    cudaGetSymbolAddress((void**)&wo16, g_wo16);
    cudaGetSymbolAddress((void**)&w116, g_w116);
    cudaGetSymbolAddress((void**)&w216, g_w216);
    cudaGetSymbolAddress((void**)&xf, g_xf);
    cudaGetSymbolAddress((void**)&qkv16, g_qkv16);
    cudaGetSymbolAddress((void**)&ct, g_ct16);
    cudaGetSymbolAddress((void**)&f16, g_f16);

    cudaFuncSetAttribute(gemm1<128,128,0>, cudaFuncAttributeMaxDynamicSharedMemorySize, SMEM_G1B);
    cudaFuncSetAttribute(gemm1<64,64,3>,   cudaFuncAttributeMaxDynamicSharedMemorySize, SMEM_G1C);
    cudaFuncSetAttribute(gemm1<128,128,4>, cudaFuncAttributeMaxDynamicSharedMemorySize, SMEM_G1B);
    cudaFuncSetAttribute(attn_fused, cudaFuncAttributeMaxDynamicSharedMemorySize, SMEM_ATT);

    // prologue
    wconv4<<<dim3(Hn/128, Hn/32, 4*Ln), 256>>>(wq, wk, wv, wo, wqkv16, wo16);
    wconv<<<dim3(Fn/128, Hn/32, Ln), 256>>>(w1, w116, Hn, Fn, (long)Hn*Fn, (long)Hn*Fn);
    wconv<<<dim3(Hn/128, Fn/32, Ln), 256>>>(w2, w216, Fn, Hn, (long)Fn*Hn, (long)Fn*Hn);
    embed_bias<<<MR + (Ln*QKVN + 255)/256, 256>>>(tok, emb, pos, x, xf, bq, bk, bv, bqkv);

    for (int l = 0; l < Ln; l++) {
        float* attnL = attn_out + (size_t)l * BH * Sn * Sn;

        // fused QKV projection (fp16)
        gemm1<128,128,0><<<dim3(QKVN/128, MR/128), 512, SMEM_G1B>>>(
            xf, Hn, wqkv16 + (size_t)l * QKVN * Hn, Hn, nullptr, qkv16, QKVN,
            bqkv + (size_t)l * QKVN, nullptr, Hn);

        // scores + softmax + P@V (all fp16)
        attn_fused<<<dim3(Sn/64, BH), 256, SMEM_ATT>>>(qkv16, tok, attnL, ct);

        // Wo + resid (64x64 tiles: 384 CTAs, 86% wave utilization)
        gemm1<64,64,3><<<dim3(Hn/64, MR/64), 512, SMEM_G1C>>>(
            ct, Hn, wo16 + (size_t)l * Hn * Hn, Hn, y, nullptr, Hn,
            bo + (size_t)l * Hn, x, Hn);
        layernorm_w<<<MR/8, 256>>>(y, g1 + (size_t)l * Hn, be1 + (size_t)l * Hn, x, xf);

        // FFN1 (relu)
        gemm1<128,128,4><<<dim3(Fn/128, MR/128), 512, SMEM_G1B>>>(
            xf, Hn, w116 + (size_t)l * Hn * Fn, Hn, nullptr, f16, Fn,
            b1 + (size_t)l * Fn, nullptr, Hn);

        // FFN2 + resid (64x64 tiles)
        gemm1<64,64,3><<<dim3(Hn/64, MR/64), 512, SMEM_G1C>>>(
            f16, Fn, w216 + (size_t)l * Fn * Hn, Fn, y, nullptr, Hn,
            b2 + (size_t)l * Hn, x, Fn);
        layernorm_w<<<MR/8, 256>>>(y, g2 + (size_t)l * Hn, be2 + (size_t)l * Hn, x, xf);
    }

    cudaMemcpyAsync(out, x, (size_t)MR * Hn * sizeof(float), cudaMemcpyDeviceToDevice);
}

// round 10
// speedup vs baseline: 8.6674x; 1.0707x over previous
#include <cuda_runtime.h>
#include <cuda_bf16.h>
#include <cuda_fp16.h>

typedef unsigned int u32;
typedef unsigned long long u64;

#define Bn 4
#define Sn 512
#define Hn 768
#define NHn 12
#define Fn 3072
#define Ln 6
#define MR (Bn*Sn)          // 2048
#define QKVN 2304
#define BH (Bn*NHn)         // 48

// ---------------- scratch (device globals) ----------------
__device__ __half g_wqkv16[(size_t)Ln*QKVN*Hn];
__device__ __half g_wo16[(size_t)Ln*Hn*Hn];
__device__ __half g_w116[(size_t)Ln*Hn*Fn];
__device__ __half g_w216[(size_t)Ln*Fn*Hn];
__device__ float g_x[MR*Hn];
__device__ float g_y[2*MR*Hn];                 // split-K partials
__device__ float g_bqkv[Ln*QKVN];
__device__ __half g_xf[MR*Hn];
__device__ __half g_qkv16[(size_t)MR*QKVN];
__device__ __half g_ct16[MR*Hn];
__device__ __half g_f16[(size_t)MR*Fn];

// ---------------- helpers ----------------
__device__ __forceinline__ u32 s2u(const void* p) {
    u32 a;
    asm("{ .reg .u64 t; cvta.to.shared.u64 t, %1; cvt.u32.u64 %0, t; }" : "=r"(a) : "l"(p));
    return a;
}
__device__ __forceinline__ u32 swz(u32 o) { return o ^ ((o >> 3) & 0x70); }

__device__ __forceinline__ void cpasync16(u32 dst, const void* src) {
    asm volatile("cp.async.cg.shared.global [%0], [%1], 16;" :: "r"(dst), "l"(src) : "memory");
}
__device__ __forceinline__ void ldsm4(u32& r0, u32& r1, u32& r2, u32& r3, u32 a) {
    asm volatile("ldmatrix.sync.aligned.m8n8.x4.shared.b16 {%0,%1,%2,%3}, [%4];"
                 : "=r"(r0), "=r"(r1), "=r"(r2), "=r"(r3) : "r"(a));
}
__device__ __forceinline__ void ldsm4t(u32& r0, u32& r1, u32& r2, u32& r3, u32 a) {
    asm volatile("ldmatrix.sync.aligned.m8n8.x4.trans.shared.b16 {%0,%1,%2,%3}, [%4];"
                 : "=r"(r0), "=r"(r1), "=r"(r2), "=r"(r3) : "r"(a));
}
__device__ __forceinline__ void mma16816h(float* c, const u32* a, const u32* b) {
    asm volatile("mma.sync.aligned.m16n8k16.row.col.f32.f16.f16.f32 "
                 "{%0,%1,%2,%3}, {%4,%5,%6,%7}, {%8,%9}, {%0,%1,%2,%3};"
                 : "+f"(c[0]), "+f"(c[1]), "+f"(c[2]), "+f"(c[3])
                 : "r"(a[0]), "r"(a[1]), "r"(a[2]), "r"(a[3]), "r"(b[0]), "r"(b[1]));
}
__device__ __forceinline__ u32 packh2(float v0, float v1) {
    __half2 h = __floats2half2_rn(v0, v1);
    return *reinterpret_cast<u32*>(&h);
}

// ==================================================================
// fp16 single-pass GEMM. MT x NT, BK=64, 512 threads (16 warps 4x4).
// EPI: 0=bias->fp16  4=bias+relu->fp16  5=split-K raw partial -> f32
// ==================================================================
template<int MT, int NT, int EPI>
__global__ void __launch_bounds__(512)
gemm1(const __half* __restrict__ A, int lda, const __half* __restrict__ B, int ldb,
      float* __restrict__ Cf, __half* __restrict__ Ch, int ldc,
      const float* __restrict__ bias, int K)
{
    constexpr int WM = MT / 4, WN = NT / 4;
    constexpr int MI = WM / 16, NI = WN / 8;
    constexpr u32 ASZ = (u32)MT * 128u, BSZ = (u32)NT * 128u;
    constexpr u32 STG = ASZ + BSZ;

    if (EPI == 5) {            // split-K: this CTA handles half the K range
        A += (size_t)blockIdx.z * (u32)(K >> 1);
        B += (size_t)blockIdx.z * (u32)(K >> 1);
        K >>= 1;
    }

    extern __shared__ char smem[];
    const u32 sb = s2u(smem);
    const int tid = threadIdx.x, wid = tid >> 5, lane = tid & 31;
    const int warp_m = wid >> 2, warp_n = wid & 3;
    const int m0 = blockIdx.y * MT, n0 = blockIdx.x * NT;
    const int nsl = K >> 6;

    float acc[MI][NI][4];
#pragma unroll
    for (int mi = 0; mi < MI; mi++)
#pragma unroll
        for (int ni = 0; ni < NI; ni++)
#pragma unroll
            for (int q = 0; q < 4; q++) acc[mi][ni][q] = 0.f;

    auto prefetch = [&](int sl) {
        const u32 base = sb + (u32)(sl % 3) * STG;
#pragma unroll
        for (int i = 0; i < MT * 8 / 512; i++) {
            int u = tid + i * 512;
            int r = u >> 3, c = u & 7;
            cpasync16(base + swz((u32)(r * 128 + c * 16)),
                      A + (size_t)(m0 + r) * lda + sl * 64 + c * 8);
        }
#pragma unroll
        for (int i = 0; i < NT * 8 / 512; i++) {
            int u = tid + i * 512;
            int r = u >> 3, c = u & 7;
            cpasync16(base + ASZ + swz((u32)(r * 128 + c * 16)),
                      B + (size_t)(n0 + r) * ldb + sl * 64 + c * 8);
        }
        asm volatile("cp.async.commit_group;" ::: "memory");
    };

    prefetch(0); prefetch(1);

    for (int it = 0; it < nsl; it++) {
        if (it < nsl - 1) asm volatile("cp.async.wait_group 1;" ::: "memory");
        else              asm volatile("cp.async.wait_group 0;" ::: "memory");
        __syncthreads();
        if (it + 2 < nsl) prefetch(it + 2);

        const u32 ab = sb + (u32)(it % 3) * STG;
        const u32 bb = ab + ASZ;

#pragma unroll
        for (int ks = 0; ks < 4; ks++) {
            u32 ar[MI][4];
#pragma unroll
            for (int mi = 0; mi < MI; mi++) {
                int row = warp_m * WM + mi * 16 + (lane & 15);
                u32 off = swz((u32)(row * 128 + (ks * 16 + (lane >> 4) * 8) * 2));
                ldsm4(ar[mi][0], ar[mi][1], ar[mi][2], ar[mi][3], ab + off);
            }
            u32 br[NI][2];
#pragma unroll
            for (int nj = 0; nj < NI / 2; nj++) {
                int nrow = warp_n * WN + nj * 16 + (lane & 7) + ((lane >> 4) << 3);
                u32 off = swz((u32)(nrow * 128 + (ks * 16 + ((lane >> 3) & 1) * 8) * 2));
                u32 r0, r1, r2, r3;
                ldsm4(r0, r1, r2, r3, bb + off);
                br[2 * nj][0] = r0; br[2 * nj][1] = r1;
                br[2 * nj + 1][0] = r2; br[2 * nj + 1][1] = r3;
            }
#pragma unroll
            for (int mi = 0; mi < MI; mi++)
#pragma unroll
                for (int ni = 0; ni < NI; ni++)
                    mma16816h(acc[mi][ni], ar[mi], br[ni]);
        }
    }

    const int tg = lane & 3, g = lane >> 2;
    const size_t zoff = (EPI == 5) ? (size_t)blockIdx.z * MR * ldc : 0;
#pragma unroll
    for (int mi = 0; mi < MI; mi++)
#pragma unroll
        for (int half = 0; half < 2; half++) {
            const int mrow = m0 + warp_m * WM + mi * 16 + half * 8 + g;
#pragma unroll
            for (int ni = 0; ni < NI; ni++) {
                const int col = n0 + warp_n * WN + ni * 8 + tg * 2;
                float v0 = acc[mi][ni][half * 2];
                float v1 = acc[mi][ni][half * 2 + 1];
                size_t off = (size_t)mrow * ldc + col;
                if (EPI == 5) {
                    *(float2*)(Cf + zoff + off) = make_float2(v0, v1);
                } else {
                    v0 += bias[col]; v1 += bias[col + 1];
                    if (EPI == 4) { v0 = fmaxf(v0, 0.f); v1 = fmaxf(v1, 0.f); }
                    *(u32*)(Ch + off) = packh2(v0, v1);
                }
            }
        }
}

// ==================================================================
// Fused attention (all fp16): scores + softmax + P@V. 64 q-rows/(b,h).
// smem: Q[0,8K)  K[8K,72K)->P  V[72K,136K)  red[136K..]
// ==================================================================
#define ATT_KP   8192u
#define ATT_V    73728u
#define ATT_RED  139264
#define SMEM_ATT (ATT_RED + 2048)

__global__ void __launch_bounds__(256)
attn_fused(const __half* __restrict__ qkv, const int* __restrict__ tok,
           float* __restrict__ attn, __half* __restrict__ ct)
{
    extern __shared__ char smem[];
    const u32 sb = s2u(smem);
    const int tid = threadIdx.x, wid = tid >> 5, lane = tid & 31;
    const int g = lane >> 2, tg = lane & 3;
    const int m0 = blockIdx.x * 64;
    const int zbh = blockIdx.y;
    const int b = zbh / NHn, h = zbh - b * NHn;

    const __half* Q_src = qkv + (size_t)(b * Sn + m0) * QKVN + h * 64;
    const __half* K_src = qkv + (size_t)(b * Sn) * QKVN + 768 + h * 64;
    const __half* V_src = qkv + (size_t)(b * Sn) * QKVN + 1536 + h * 64;

    for (int u = tid; u < 512; u += 256) {
        int r = u >> 3, c = u & 7;
        cpasync16(sb + swz((u32)(r * 128 + c * 16)), Q_src + (size_t)r * QKVN + c * 8);
    }
    for (int u = tid; u < 4096; u += 256) {
        int r = u >> 3, c = u & 7;
        cpasync16(sb + ATT_KP + swz((u32)(r * 128 + c * 16)), K_src + (size_t)r * QKVN + c * 8);
    }
    asm volatile("cp.async.commit_group;" ::: "memory");
    for (int u = tid; u < 4096; u += 256) {
        int r = u >> 3, c = u & 7;
        cpasync16(sb + ATT_V + swz((u32)(r * 128 + c * 16)), V_src + (size_t)r * QKVN + c * 8);
    }
    asm volatile("cp.async.commit_group;" ::: "memory");

    asm volatile("cp.async.wait_group 1;" ::: "memory");
    __syncthreads();

    // ---- scores = Q K^T ----
    float acc[4][8][4];
#pragma unroll
    for (int mi = 0; mi < 4; mi++)
#pragma unroll
        for (int ni = 0; ni < 8; ni++)
#pragma unroll
            for (int q = 0; q < 4; q++) acc[mi][ni][q] = 0.f;

#pragma unroll
    for (int ks = 0; ks < 4; ks++) {
        u32 arg[4][4];
#pragma unroll
        for (int mi = 0; mi < 4; mi++) {
            int row = mi * 16 + (lane & 15);
            u32 off = swz((u32)(row * 128 + (ks * 16 + (lane >> 4) * 8) * 2));
            ldsm4(arg[mi][0], arg[mi][1], arg[mi][2], arg[mi][3], sb + off);
        }
        u32 brg[8][2];
#pragma unroll
        for (int nj = 0; nj < 4; nj++) {
            int nrow = wid * 64 + nj * 16 + (lane & 7) + ((lane >> 4) << 3);
            u32 off = swz((u32)(nrow * 128 + (ks * 16 + ((lane >> 3) & 1) * 8) * 2));
            u32 r0, r1, r2, r3;
            ldsm4(r0, r1, r2, r3, sb + ATT_KP + off);
            brg[2 * nj][0] = r0; brg[2 * nj][1] = r1;
            brg[2 * nj + 1][0] = r2; brg[2 * nj + 1][1] = r3;
        }
#pragma unroll
        for (int mi = 0; mi < 4; mi++)
#pragma unroll
            for (int ni = 0; ni < 8; ni++)
                mma16816h(acc[mi][ni], arg[mi], brg[ni]);
    }
    __syncthreads();

    // ---- scale + mask + exp (no max-sub; logits small, mask underflows) ----
    float mk[8][2];
#pragma unroll
    for (int ni = 0; ni < 8; ni++) {
        int c = wid * 64 + ni * 8 + tg * 2;
        mk[ni][0] = (tok[b * Sn + c]     == 0) ? -10000.f : 0.f;
        mk[ni][1] = (tok[b * Sn + c + 1] == 0) ? -10000.f : 0.f;
    }

    float* red = (float*)(smem + ATT_RED);
    float rsum[8];

#pragma unroll
    for (int mi = 0; mi < 4; mi++)
#pragma unroll
        for (int half = 0; half < 2; half++) {
            float s = 0.f;
#pragma unroll
            for (int ni = 0; ni < 8; ni++) {
                float e0 = __expf(acc[mi][ni][half * 2]     * 0.125f + mk[ni][0]);
                float e1 = __expf(acc[mi][ni][half * 2 + 1] * 0.125f + mk[ni][1]);
                acc[mi][ni][half * 2] = e0; acc[mi][ni][half * 2 + 1] = e1;
                s += e0 + e1;
            }
            s += __shfl_xor_sync(0xffffffffu, s, 1);
            s += __shfl_xor_sync(0xffffffffu, s, 2);
            int row = mi * 16 + half * 8 + g;
            if (tg == 0) red[row * 8 + wid] = s;
        }
    __syncthreads();
#pragma unroll
    for (int mi = 0; mi < 4; mi++)
#pragma unroll
        for (int half = 0; half < 2; half++) {
            int row = mi * 16 + half * 8 + g;
            float s = 0.f;
#pragma unroll
            for (int w = 0; w < 8; w++) s += red[row * 8 + w];
            rsum[mi * 2 + half] = 1.f / s;
        }

    // ---- write attn fp32 + P fp16 into smem ----
#pragma unroll
    for (int mi = 0; mi < 4; mi++)
#pragma unroll
        for (int half = 0; half < 2; half++) {
            int row = mi * 16 + half * 8 + g;
            size_t rbase = (size_t)zbh * Sn * Sn + (size_t)(m0 + row) * Sn;
            float inv = rsum[mi * 2 + half];
#pragma unroll
            for (int ni = 0; ni < 8; ni++) {
                int col = ni * 8 + tg * 2;
                float p0 = acc[mi][ni][half * 2]     * inv;
                float p1 = acc[mi][ni][half * 2 + 1] * inv;
                *(float2*)(attn + rbase + wid * 64 + col) = make_float2(p0, p1);
                u32 off = (u32)(wid * 8192) + swz((u32)(row * 128 + col * 2));
                *(u32*)(smem + ATT_KP + off) = packh2(p0, p1);
            }
        }

    asm volatile("cp.async.wait_group 0;" ::: "memory");
    __syncthreads();

    // ---- ctx = P @ V (V via trans-ldmatrix) ----
    const int wm = wid >> 2, wn = wid & 3;
    float acc2[2][2][4];
#pragma unroll
    for (int mi = 0; mi < 2; mi++)
#pragma unroll
        for (int ni = 0; ni < 2; ni++)
#pragma unroll
            for (int q = 0; q < 4; q++) acc2[mi][ni][q] = 0.f;

#pragma unroll 2
    for (int sl = 0; sl < 8; sl++) {
#pragma unroll
        for (int ks = 0; ks < 4; ks++) {
            u32 ar[2][4];
#pragma unroll
            for (int mi = 0; mi < 2; mi++) {
                int row = wm * 32 + mi * 16 + (lane & 15);
                u32 aoff = (u32)(sl * 8192) + swz((u32)(row * 128 + (ks * 16 + (lane >> 4) * 8) * 2));
                ldsm4(ar[mi][0], ar[mi][1], ar[mi][2], ar[mi][3], sb + ATT_KP + aoff);
            }
            int srow = sl * 64 + ks * 16 + (lane & 7) + ((lane >> 3) & 1) * 8;
            int dcol = wn * 16 + ((lane >> 4) << 3);
            u32 boff = swz((u32)(srow * 128 + dcol * 2));
            u32 br[2][2], r0, r1, r2, r3;
            ldsm4t(r0, r1, r2, r3, sb + ATT_V + boff);
            br[0][0] = r0; br[0][1] = r1; br[1][0] = r2; br[1][1] = r3;
#pragma unroll
            for (int mi = 0; mi < 2; mi++)
#pragma unroll
                for (int ni = 0; ni < 2; ni++)
                    mma16816h(acc2[mi][ni], ar[mi], br[ni]);
        }
    }

#pragma unroll
    for (int mi = 0; mi < 2; mi++)
#pragma unroll
        for (int half = 0; half < 2; half++) {
            int row = m0 + wm * 32 + mi * 16 + half * 8 + g;
#pragma unroll
            for (int ni = 0; ni < 2; ni++) {
                int col = wn * 16 + ni * 8 + tg * 2;
                size_t off = (size_t)(b * Sn + row) * Hn + h * 64 + col;
                *(u32*)(ct + off) = packh2(acc2[mi][ni][half * 2], acc2[mi][ni][half * 2 + 1]);
            }
        }
}

// ==================================================================
// weight convert+transpose: fp32 [K,N] -> fp16 [N,K]
// ==================================================================
__global__ void __launch_bounds__(256)
wconv(const float* __restrict__ src0, __half* __restrict__ dst0,
      int K, int N, long in_l, long out_l)
{
    __shared__ float t[32][132];
    const float* src = src0 + (size_t)blockIdx.z * in_l;
    __half* dst = dst0 + (size_t)blockIdx.z * out_l;
    const int n0 = blockIdx.x * 128, k0 = blockIdx.y * 32;
    const int tid = threadIdx.x;

#pragma unroll
    for (int i = 0; i < 4; i++) {
        int idx = tid + i * 256;
        int r = idx >> 5, c = (idx & 31) << 2;
        float4 v = *(const float4*)(src + (size_t)(k0 + r) * N + n0 + c);
        t[r][c] = v.x; t[r][c + 1] = v.y; t[r][c + 2] = v.z; t[r][c + 3] = v.w;
    }
    __syncthreads();
#pragma unroll
    for (int i = 0; i < 4; i++) {
        int idx = tid + i * 256;
        int n = idx >> 3, ks = (idx & 7) << 2;
        u32 p0 = packh2(t[ks][n],     t[ks + 1][n]);
        u32 p1 = packh2(t[ks + 2][n], t[ks + 3][n]);
        size_t off = (size_t)(n0 + n) * K + k0 + ks;
        *(u32*)(dst + off)     = p0;
        *(u32*)(dst + off + 2) = p1;
    }
}

// merged variant for the 4 HxH weights; zoff selects layer range
__global__ void __launch_bounds__(256)
wconv4(const float* __restrict__ wq, const float* __restrict__ wk,
       const float* __restrict__ wv, const float* __restrict__ wo,
       __half* __restrict__ oqkv, __half* __restrict__ owo, int zoff)
{
    __shared__ float t[32][132];
    int z = blockIdx.z + zoff, l = z >> 2, which = z & 3;
    const float* src = (which == 0 ? wq : which == 1 ? wk : which == 2 ? wv : wo)
                       + (size_t)l * Hn * Hn;
    __half* dst;
    size_t obase;
    if (which < 3) { dst = oqkv; obase = (size_t)l * QKVN * Hn + (size_t)which * 768 * Hn; }
    else           { dst = owo;  obase = (size_t)l * Hn * Hn; }
    const int n0 = blockIdx.x * 128, k0 = blockIdx.y * 32;
    const int tid = threadIdx.x;

#pragma unroll
    for (int i = 0; i < 4; i++) {
        int idx = tid + i * 256;
        int r = idx >> 5, c = (idx & 31) << 2;
        float4 v = *(const float4*)(src + (size_t)(k0 + r) * Hn + n0 + c);
        t[r][c] = v.x; t[r][c + 1] = v.y; t[r][c + 2] = v.z; t[r][c + 3] = v.w;
    }
    __syncthreads();
#pragma unroll
    for (int i = 0; i < 4; i++) {
        int idx = tid + i * 256;
        int n = idx >> 3, ks = (idx & 7) << 2;
        u32 p0 = packh2(t[ks][n],     t[ks + 1][n]);
        u32 p1 = packh2(t[ks + 2][n], t[ks + 3][n]);
        size_t off = obase + (size_t)(n0 + n) * Hn + k0 + ks;
        *(u32*)(dst + off)     = p0;
        *(u32*)(dst + off + 2) = p1;
    }
}

// embed + biaspack merged
__global__ void embed_bias(const int* __restrict__ tok, const float* __restrict__ emb,
                           const float* __restrict__ pos, float* __restrict__ x,
                           __half* __restrict__ xf,
                           const float* __restrict__ bq, const float* __restrict__ bk,
                           const float* __restrict__ bv, float* __restrict__ obias) {
    if (blockIdx.x < MR) {
        int row = blockIdx.x;
        int t = tok[row];
        const float* e = emb + (size_t)t * Hn;
        const float* p = pos + (size_t)(row % Sn) * Hn;
        size_t base = (size_t)row * Hn;
        for (int c = threadIdx.x; c < Hn; c += blockDim.x) {
            float v = e[c] + p[c];
            x[base + c] = v;
            xf[base + c] = __float2half(v);
        }
    } else {
        int i = (blockIdx.x - MR) * 256 + threadIdx.x;
        if (i < Ln * QKVN) {
            int l = i / QKVN, n = i - l * QKVN;
            float v = (n < 768) ? bq[l * Hn + n]
                    : (n < 1536) ? bk[l * Hn + n - 768] : bv[l * Hn + n - 1536];
            obias[i] = v;
        }
    }
}

// ==================================================================
// warp-per-row layernorm over (y0 + y1 + bias + resid)
// ==================================================================
__global__ void __launch_bounds__(256)
layernorm_sum(const float* __restrict__ y0, const float* __restrict__ y1,
              const float* __restrict__ bias, const float* __restrict__ resid,
              const float* __restrict__ g, const float* __restrict__ be,
              float* __restrict__ out, __half* __restrict__ of) {
    const int row = blockIdx.x * 8 + (threadIdx.x >> 5);
    const int lane = threadIdx.x & 31;
    const size_t rb = (size_t)row * Hn;

    float4 v[6];
    float s = 0.f, sq = 0.f;
#pragma unroll
    for (int i = 0; i < 6; i++) {
        int idx = i * 128 + lane * 4;
        float4 a0 = *(const float4*)(y0 + rb + idx);
        float4 a1 = *(const float4*)(y1 + rb + idx);
        float4 bv = *(const float4*)(bias + idx);
        float4 rv = *(const float4*)(resid + rb + idx);
        v[i].x = a0.x + a1.x + bv.x + rv.x;
        v[i].y = a0.y + a1.y + bv.y + rv.y;
        v[i].z = a0.z + a1.z + bv.z + rv.z;
        v[i].w = a0.w + a1.w + bv.w + rv.w;
        s  += v[i].x + v[i].y + v[i].z + v[i].w;
        sq += v[i].x * v[i].x + v[i].y * v[i].y + v[i].z * v[i].z + v[i].w * v[i].w;
    }
#pragma unroll
    for (int o = 16; o; o >>= 1) {
        s  += __shfl_xor_sync(0xffffffffu, s, o);
        sq += __shfl_xor_sync(0xffffffffu, sq, o);
    }
    float m = s * (1.0f / Hn);
    float var = sq * (1.0f / Hn) - m * m;
    float inv = rsqrtf(var + 1e-12f);

#pragma unroll
    for (int i = 0; i < 6; i++) {
        int idx = i * 128 + lane * 4;
        float4 gg = *(const float4*)(g + idx);
        float4 bb = *(const float4*)(be + idx);
        float4 r;
        r.x = (v[i].x - m) * inv * gg.x + bb.x;
        r.y = (v[i].y - m) * inv * gg.y + bb.y;
        r.z = (v[i].z - m) * inv * gg.z + bb.z;
        r.w = (v[i].w - m) * inv * gg.w + bb.w;
        *(float4*)(out + rb + idx) = r;
        u32 h0 = packh2(r.x, r.y), h1 = packh2(r.z, r.w);
        *(u32*)(of + rb + idx)     = h0;
        *(u32*)(of + rb + idx + 2) = h1;
    }
}

// ==================================================================
#define SMEM_G1B (3 * (128*128 + 128*128))       // 98304 (128x128)
#define SMEM_G1A (3 * (64*128  + 128*128))       // 73728 (64x128)

extern "C" void kernel_launch(void* const* d_in, const int* in_sizes, int n_in,
                              void* d_out, int out_size) {
    const int*   tok = (const int*)d_in[0];
    const float* emb = (const float*)d_in[1];
    const float* pos = (const float*)d_in[2];
    const float* wq  = (const float*)d_in[3];
    const float* bq  = (const float*)d_in[4];
    const float* wk  = (const float*)d_in[5];
    const float* bk  = (const float*)d_in[6];
    const float* wv  = (const float*)d_in[7];
    const float* bv  = (const float*)d_in[8];
    const float* wo  = (const float*)d_in[9];
    const float* bo  = (const float*)d_in[10];
    const float* g1  = (const float*)d_in[11];
    const float* be1 = (const float*)d_in[12];
    const float* w1  = (const float*)d_in[13];
    const float* b1  = (const float*)d_in[14];
    const float* w2  = (const float*)d_in[15];
    const float* b2  = (const float*)d_in[16];
    const float* g2  = (const float*)d_in[17];
    const float* be2 = (const float*)d_in[18];

    float* out      = (float*)d_out;
    float* attn_out = out + (size_t)MR * Hn;

    float *x, *y, *bqkv;
    __half *wqkv16, *wo16, *w116, *w216, *xf, *qkv16, *ct, *f16;
    cudaGetSymbolAddress((void**)&x, g_x);      cudaGetSymbolAddress((void**)&y, g_y);
    cudaGetSymbolAddress((void**)&bqkv, g_bqkv);
    cudaGetSymbolAddress((void**)&wqkv16, g_wqkv16);
    cudaGetSymbolAddress((void**)&wo16, g_wo16);
    cudaGetSymbolAddress((void**)&w116, g_w116);
    cudaGetSymbolAddress((void**)&w216, g_w216);
    cudaGetSymbolAddress((void**)&xf, g_xf);
    cudaGetSymbolAddress((void**)&qkv16, g_qkv16);
    cudaGetSymbolAddress((void**)&ct, g_ct16);
    cudaGetSymbolAddress((void**)&f16, g_f16);

    cudaFuncSetAttribute(gemm1<128,128,0>, cudaFuncAttributeMaxDynamicSharedMemorySize, SMEM_G1B);
    cudaFuncSetAttribute(gemm1<64,128,5>,  cudaFuncAttributeMaxDynamicSharedMemorySize, SMEM_G1A);
    cudaFuncSetAttribute(gemm1<128,128,4>, cudaFuncAttributeMaxDynamicSharedMemorySize, SMEM_G1B);
    cudaFuncSetAttribute(attn_fused, cudaFuncAttributeMaxDynamicSharedMemorySize, SMEM_ATT);

    // side stream + events (created once; reused every call)
    static cudaStream_t s2 = nullptr;
    static cudaEvent_t ev1 = nullptr, ev2 = nullptr;
    if (!s2) {
        cudaStreamCreateWithFlags(&s2, cudaStreamNonBlocking);
        cudaEventCreateWithFlags(&ev1, cudaEventDisableTiming);
        cudaEventCreateWithFlags(&ev2, cudaEventDisableTiming);
    }

    // ---- prologue: layer-0 weights on main stream ----
    wconv4<<<dim3(Hn/128, Hn/32, 4), 256>>>(wq, wk, wv, wo, wqkv16, wo16, 0);
    wconv<<<dim3(Fn/128, Hn/32, 1), 256>>>(w1, w116, Hn, Fn, (long)Hn*Fn, (long)Hn*Fn);
    wconv<<<dim3(Hn/128, Fn/32, 1), 256>>>(w2, w216, Fn, Hn, (long)Fn*Hn, (long)Fn*Hn);
    embed_bias<<<MR + (Ln*QKVN + 255)/256, 256>>>(tok, emb, pos, x, xf, bq, bk, bv, bqkv);

    // ---- layers 1..5 weight conversion on side stream ----
    cudaEventRecord(ev1, 0);
    cudaStreamWaitEvent(s2, ev1, 0);
    wconv4<<<dim3(Hn/128, Hn/32, 4*(Ln-1)), 256, 0, s2>>>(wq, wk, wv, wo, wqkv16, wo16, 4);
    wconv<<<dim3(Fn/128, Hn/32, Ln-1), 256, 0, s2>>>(
        w1 + (size_t)Hn*Fn, w116 + (size_t)Hn*Fn, Hn, Fn, (long)Hn*Fn, (long)Hn*Fn);
    wconv<<<dim3(Hn/128, Fn/32, Ln-1), 256, 0, s2>>>(
        w2 + (size_t)Fn*Hn, w216 + (size_t)Fn*Hn, Fn, Hn, (long)Fn*Hn, (long)Fn*Hn);
    cudaEventRecord(ev2, s2);

    for (int l = 0; l < Ln; l++) {
        if (l == 1) cudaStreamWaitEvent(0, ev2, 0);   // layers 1..5 weights ready
        float* attnL = attn_out + (size_t)l * BH * Sn * Sn;
        bool last = (l == Ln - 1);
        float* lnout = last ? out : x;

        // fused QKV projection (fp16)
        gemm1<128,128,0><<<dim3(QKVN/128, MR/128), 512, SMEM_G1B>>>(
            xf, Hn, wqkv16 + (size_t)l * QKVN * Hn, Hn, nullptr, qkv16, QKVN,
            bqkv + (size_t)l * QKVN, Hn);

        // scores + softmax + P@V
        attn_fused<<<dim3(Sn/64, BH), 256, SMEM_ATT>>>(qkv16, tok, attnL, ct);

        // Wo split-K=2 -> partials y0/y1
        gemm1<64,128,5><<<dim3(Hn/128, MR/64, 2), 512, SMEM_G1A>>>(
            ct, Hn, wo16 + (size_t)l * Hn * Hn, Hn, y, nullptr, Hn,
            nullptr, Hn);
        layernorm_sum<<<MR/8, 256>>>(y, y + (size_t)MR*Hn, bo + (size_t)l * Hn, x,
                                     g1 + (size_t)l * Hn, be1 + (size_t)l * Hn, x, xf);

        // FFN1 (relu)
        gemm1<128,128,4><<<dim3(Fn/128, MR/128), 512, SMEM_G1B>>>(
            xf, Hn, w116 + (size_t)l * Hn * Fn, Hn, nullptr, f16, Fn,
            b1 + (size_t)l * Fn, Hn);

        // FFN2 split-K=2 -> partials
        gemm1<64,128,5><<<dim3(Hn/128, MR/64, 2), 512, SMEM_G1A>>>(
            f16, Fn, w216 + (size_t)l * Fn * Hn, Fn, y, nullptr, Hn,
            nullptr, Fn);
        layernorm_sum<<<MR/8, 256>>>(y, y + (size_t)MR*Hn, b2 + (size_t)l * Hn, x,
                                     g2 + (size_t)l * Hn, be2 + (size_t)l * Hn, lnout, xf);
    }
}